// round 9
// baseline (speedup 1.0000x reference)
#include <cuda_runtime.h>
#include <cstdint>
#include <cstdio>

#define EPS_LN 1e-5f
#define MAX_N 50048
#define MAX_E 1600064

__device__ float g_aggf[(size_t)50000 * 128];
__device__ int g_deg[MAX_N];
__device__ int g_cur[MAX_N];
__device__ int g_off[MAX_N + 1];
__device__ int g_csr[MAX_E];
__device__ int g_is64;

// edge-MLP weights in constant memory (uniform-port access)
__constant__ __align__(16) float W1c[47 * 64];
__constant__ __align__(16) float W2c[64 * 128];
__constant__ __align__(16) float b1c[64];
__constant__ __align__(16) float g1c[64];
__constant__ __align__(16) float be1c[64];
__constant__ __align__(16) float b2c[128];
__constant__ __align__(16) float g2c[128];
__constant__ __align__(16) float be2c[128];

// ---------------------------------------------------------------------------
// packed f32x2 helpers (FFMA2)
// ---------------------------------------------------------------------------
__device__ __forceinline__ void ffma2(unsigned long long& d,
                                      unsigned long long a,
                                      unsigned long long b) {
    asm("fma.rn.f32x2 %0, %1, %2, %0;" : "+l"(d) : "l"(a), "l"(b));
}
__device__ __forceinline__ unsigned long long packf2(float lo, float hi) {
    return ((unsigned long long)__float_as_uint(hi) << 32) |
           (unsigned long long)__float_as_uint(lo);
}
__device__ __forceinline__ float lof(unsigned long long v) {
    return __uint_as_float((unsigned)v);
}
__device__ __forceinline__ float hif(unsigned long long v) {
    return __uint_as_float((unsigned)(v >> 32));
}

__device__ __forceinline__ void sc_angle(float ax, float ay, float az,
                                         float bx, float by, float bz,
                                         float& s, float& c) {
    float cx = ay * bz - az * by;
    float cy = az * bx - ax * bz;
    float cz = ax * by - ay * bx;
    float cn2 = cx * cx + cy * cy + cz * cz;
    float d = ax * bx + ay * by + az * bz;
    float den = cn2 + d * d;
    if (den > 0.0f) {
        float r = rsqrtf(den);
        s = sqrtf(cn2) * r;
        c = d * r;
    } else {
        s = 0.0f;
        c = 1.0f;
    }
}

// ---------------------------------------------------------------------------
// Kernel 1: zero degree counters + detect edge_index dtype (int64 vs int32)
// ---------------------------------------------------------------------------
__global__ void init_kernel(const int* __restrict__ ei32, int nNodes) {
    int tid = blockIdx.x * blockDim.x + threadIdx.x;
    int stride = gridDim.x * blockDim.x;
    for (int i = tid; i < nNodes; i += stride) g_deg[i] = 0;
    if (blockIdx.x == 0 && threadIdx.x == 0) {
        int all0 = 1;
        for (int i = 0; i < 256; i++) all0 &= (ei32[2 * i + 1] == 0);
        g_is64 = all0;
    }
}

// ---------------------------------------------------------------------------
// Kernel 2: histogram of dst
// ---------------------------------------------------------------------------
__global__ void hist_kernel(const void* __restrict__ eiPtr, int E) {
    const bool is64 = (g_is64 != 0);
    const long long* ei64 = (const long long*)eiPtr;
    const int* ei32 = (const int*)eiPtr;
    int tid = blockIdx.x * blockDim.x + threadIdx.x;
    int stride = gridDim.x * blockDim.x;
    for (int e = tid; e < E; e += stride) {
        int dst = is64 ? (int)ei64[(long long)E + e] : ei32[(long long)E + e];
        atomicAdd(&g_deg[dst], 1);
    }
}

// ---------------------------------------------------------------------------
// Kernel 3: single-block exclusive scan -> g_off, copy to g_cur
// ---------------------------------------------------------------------------
__global__ void scan_kernel(int nNodes) {
    __shared__ int part[1024];
    int t = threadIdx.x;
    int CH = (nNodes + 1023) / 1024;
    int base = t * CH;
    int s = 0;
    for (int k = 0; k < CH; k++) {
        int idx = base + k;
        if (idx < nNodes) s += g_deg[idx];
    }
    part[t] = s;
    __syncthreads();
    for (int off = 1; off < 1024; off <<= 1) {
        int v = (t >= off) ? part[t - off] : 0;
        __syncthreads();
        part[t] += v;
        __syncthreads();
    }
    int run = part[t] - s;  // exclusive prefix for this chunk
    for (int k = 0; k < CH; k++) {
        int idx = base + k;
        if (idx < nNodes) {
            g_off[idx] = run;
            g_cur[idx] = run;
            run += g_deg[idx];
        }
    }
    if (t == 1023) g_off[nNodes] = run;
}

// ---------------------------------------------------------------------------
// Kernel 4: fill CSR with edge ids
// ---------------------------------------------------------------------------
__global__ void fill_kernel(const void* __restrict__ eiPtr, int E) {
    const bool is64 = (g_is64 != 0);
    const long long* ei64 = (const long long*)eiPtr;
    const int* ei32 = (const int*)eiPtr;
    int tid = blockIdx.x * blockDim.x + threadIdx.x;
    int stride = gridDim.x * blockDim.x;
    for (int e = tid; e < E; e += stride) {
        int dst = is64 ? (int)ei64[(long long)E + e] : ei32[(long long)E + e];
        int p = atomicAdd(&g_cur[dst], 1);
        g_csr[p] = e;
    }
}

// ---------------------------------------------------------------------------
// Kernel 5: node-centric edge MLP, EDGE-PER-LANE layout.
// Warp per node; each lane computes one full edge message in registers;
// weights stream from __constant__ (uniform port); no shared memory at all.
// Segment max via one shfl butterfly per feature per 32-edge batch.
// ---------------------------------------------------------------------------
__global__ __launch_bounds__(128)
void compute_kernel(const float* __restrict__ x, const float* __restrict__ pos,
                    const float* __restrict__ normal, const float* __restrict__ ea,
                    const void* __restrict__ eiPtr, int E, int nNodes) {
    const int lane = threadIdx.x & 31;
    const int w = threadIdx.x >> 5;
    const int warpGlobal = (blockIdx.x << 2) + w;
    const int warpsTotal = gridDim.x << 2;
    const bool is64 = (g_is64 != 0);
    const long long* ei64 = (const long long*)eiPtr;
    const int* ei32 = (const int*)eiPtr;

    const unsigned long long* cW1 = (const unsigned long long*)W1c;
    const unsigned long long* cW2 = (const unsigned long long*)W2c;
    const unsigned long long* cb1 = (const unsigned long long*)b1c;
    const unsigned long long* cb2 = (const unsigned long long*)b2c;

    const float NEG_INF = -__int_as_float(0x7f800000);

    for (int node = warpGlobal; node < nNodes; node += warpsTotal) {
        int rowStart = g_off[node];
        int deg = g_off[node + 1] - rowStart;

        float out4[4];
        #pragma unroll
        for (int j = 0; j < 4; j++) out4[j] = NEG_INF;

        // node-invariant geometry (warp-uniform loads)
        float pix = pos[node * 3 + 0], piy = pos[node * 3 + 1], piz = pos[node * 3 + 2];
        float nix = normal[node * 3 + 0], niy = normal[node * 3 + 1], niz = normal[node * 3 + 2];

        for (int it = 0; it < deg; it += 32) {
            // each lane owns one edge; tail lanes clamp to a duplicate real
            // edge (harmless under max)
            int idx = it + lane;
            int cl = (idx < deg) ? idx : (deg - 1);
            int eid = g_csr[rowStart + cl];
            int src = is64 ? (int)ei64[eid] : ei32[eid];

            // ---- build 47-dim input in registers ----
            float in[47];
            {
                const float4* xp = (const float4*)(x + (size_t)src * 32);
                #pragma unroll
                for (int q = 0; q < 8; q++) {
                    float4 v = xp[q];
                    in[4 * q + 0] = v.x; in[4 * q + 1] = v.y;
                    in[4 * q + 2] = v.z; in[4 * q + 3] = v.w;
                }
                float pjx = pos[src * 3 + 0], pjy = pos[src * 3 + 1], pjz = pos[src * 3 + 2];
                float px = pjx - pix, py = pjy - piy, pz = pjz - piz;
                float njx = normal[src * 3 + 0], njy = normal[src * 3 + 1], njz = normal[src * 3 + 2];
                in[32] = sqrtf(px * px + py * py + pz * pz) * 0.125f;
                float s, c;
                sc_angle(nix, niy, niz, px, py, pz, s, c);    in[33] = s; in[34] = c;
                sc_angle(njx, njy, njz, px, py, pz, s, c);    in[35] = s; in[36] = c;
                sc_angle(nix, niy, niz, njx, njy, njz, s, c); in[37] = s; in[38] = c;
                const float4* ep = (const float4*)(ea + (size_t)eid * 8);
                float4 e0 = ep[0], e1 = ep[1];
                in[39] = e0.x; in[40] = e0.y; in[41] = e0.z; in[42] = e0.w;
                in[43] = e1.x; in[44] = e1.y; in[45] = e1.z; in[46] = e1.w;
            }

            // ---- GEMV1: 47 -> 64, N-packed col pairs, weights uniform ----
            unsigned long long acc1[32];
            #pragma unroll
            for (int kk = 0; kk < 32; kk++) acc1[kk] = cb1[kk];
            #pragma unroll
            for (int i = 0; i < 47; i++) {
                unsigned long long ap = packf2(in[i], in[i]);
                #pragma unroll
                for (int kk = 0; kk < 32; kk++)
                    ffma2(acc1[kk], ap, cW1[i * 32 + kk]);
            }

            // ---- ReLU + LayerNorm(64), fully in-lane ----
            float sum1 = 0.0f, sq1 = 0.0f;
            #pragma unroll
            for (int kk = 0; kk < 32; kk++) {
                float lo = fmaxf(lof(acc1[kk]), 0.0f);
                float hi = fmaxf(hif(acc1[kk]), 0.0f);
                sum1 += lo + hi;
                sq1 += lo * lo + hi * hi;
            }
            float mu1 = sum1 * (1.0f / 64.0f);
            float var1 = sq1 * (1.0f / 64.0f) - mu1 * mu1;
            float rs1 = rsqrtf(var1 + EPS_LN);
            float h[64];
            #pragma unroll
            for (int kk = 0; kk < 32; kk++) {
                float lo = fmaxf(lof(acc1[kk]), 0.0f);
                float hi = fmaxf(hif(acc1[kk]), 0.0f);
                h[2 * kk]     = (lo - mu1) * rs1 * g1c[2 * kk]     + be1c[2 * kk];
                h[2 * kk + 1] = (hi - mu1) * rs1 * g1c[2 * kk + 1] + be1c[2 * kk + 1];
            }

            // ---- GEMV2: 64 -> 128, N-packed col pairs ----
            unsigned long long acc2[64];
            #pragma unroll
            for (int kk = 0; kk < 64; kk++) acc2[kk] = cb2[kk];
            #pragma unroll
            for (int i = 0; i < 64; i++) {
                unsigned long long hp = packf2(h[i], h[i]);
                #pragma unroll
                for (int kk = 0; kk < 64; kk++)
                    ffma2(acc2[kk], hp, cW2[i * 64 + kk]);
            }

            // ---- ReLU + LayerNorm(128) stats ----
            float sum2 = 0.0f, sq2 = 0.0f;
            #pragma unroll
            for (int kk = 0; kk < 64; kk++) {
                float lo = fmaxf(lof(acc2[kk]), 0.0f);
                float hi = fmaxf(hif(acc2[kk]), 0.0f);
                sum2 += lo + hi;
                sq2 += lo * lo + hi * hi;
            }
            float mu2 = sum2 * (1.0f / 128.0f);
            float var2 = sq2 * (1.0f / 128.0f) - mu2 * mu2;
            float rs2 = rsqrtf(var2 + EPS_LN);

            // ---- per-feature msg + cross-lane max butterfly ----
            #pragma unroll
            for (int f = 0; f < 128; f++) {
                float z = (f & 1) ? hif(acc2[f >> 1]) : lof(acc2[f >> 1]);
                float v = (fmaxf(z, 0.0f) - mu2) * rs2 * g2c[f] + be2c[f];
                #pragma unroll
                for (int off = 16; off > 0; off >>= 1)
                    v = fmaxf(v, __shfl_xor_sync(0xffffffffu, v, off));
                if (lane == (f & 31))
                    out4[f >> 5] = fmaxf(out4[f >> 5], v);
            }
        }

        // lane L owns features L, L+32, L+64, L+96
        #pragma unroll
        for (int j = 0; j < 4; j++)
            g_aggf[(size_t)node * 128 + 32 * j + lane] =
                (deg > 0) ? out4[j] : 0.0f;
    }
}

// ---------------------------------------------------------------------------
// Kernel 6: node MLP 128->256 (ReLU+LN), one warp x 4 nodes
// ---------------------------------------------------------------------------
__global__ __launch_bounds__(512)
void node_kernel(const float* __restrict__ Wg, const float* __restrict__ bg,
                 const float* __restrict__ gg, const float* __restrict__ beg,
                 float* __restrict__ out, int nNodes) {
    extern __shared__ float sm[];
    float* sWgT = sm;            // [256 rows][132 floats]
    float* sbg  = sm + 33792;
    float* sgg  = sm + 34048;
    float* sbeg = sm + 34304;
    float* sH   = sm + 34560;    // 16 warps * 4 nodes * 128

    int tid = threadIdx.x;
    for (int t = tid; t < 128 * 256; t += 512) {
        int i = t >> 8, k = t & 255;
        sWgT[k * 132 + i] = Wg[t];
    }
    for (int t = tid; t < 256; t += 512) { sbg[t] = bg[t]; sgg[t] = gg[t]; sbeg[t] = beg[t]; }
    __syncthreads();

    int lane = tid & 31, w = tid >> 5;
    int warpGlobal = blockIdx.x * 16 + w;
    int warpsTotal = gridDim.x * 16;
    float* myH = sH + w * 512;

    float bj[8], gj[8], bej[8];
    #pragma unroll
    for (int j = 0; j < 8; j++) {
        int k = lane + 32 * j;
        bj[j] = sbg[k]; gj[j] = sgg[k]; bej[j] = sbeg[k];
    }

    for (int base = warpGlobal * 4; base < nNodes; base += warpsTotal * 4) {
        #pragma unroll
        for (int m = 0; m < 4; m++) {
            int node = base + m;
            int nc = (node < nNodes) ? node : base;
            float4 f = ((const float4*)g_aggf)[(size_t)nc * 32 + lane];
            ((float4*)(myH + m * 128))[lane] = f;
        }
        __syncwarp();

        float acc[8][4];  // [j][m]
        #pragma unroll
        for (int j = 0; j < 8; j++)
            #pragma unroll
            for (int m = 0; m < 4; m++) acc[j][m] = bj[j];

        #pragma unroll 4
        for (int i4 = 0; i4 < 32; i4++) {
            float4 wv[8];
            #pragma unroll
            for (int j = 0; j < 8; j++)
                wv[j] = *(const float4*)(sWgT + (lane + 32 * j) * 132 + i4 * 4);
            #pragma unroll
            for (int m = 0; m < 4; m++) {
                float4 xm = ((const float4*)(myH + m * 128))[i4];
                #pragma unroll
                for (int j = 0; j < 8; j++) {
                    acc[j][m] += xm.x * wv[j].x; acc[j][m] += xm.y * wv[j].y;
                    acc[j][m] += xm.z * wv[j].z; acc[j][m] += xm.w * wv[j].w;
                }
            }
        }

        float sum[4], sq[4];
        #pragma unroll
        for (int m = 0; m < 4; m++) {
            sum[m] = 0.0f; sq[m] = 0.0f;
            #pragma unroll
            for (int j = 0; j < 8; j++) {
                float v = fmaxf(acc[j][m], 0.0f);
                acc[j][m] = v;
                sum[m] += v;
                sq[m] += v * v;
            }
        }
        #pragma unroll
        for (int off = 16; off > 0; off >>= 1) {
            #pragma unroll
            for (int m = 0; m < 4; m++) {
                sum[m] += __shfl_xor_sync(0xffffffffu, sum[m], off);
                sq[m]  += __shfl_xor_sync(0xffffffffu, sq[m], off);
            }
        }
        #pragma unroll
        for (int m = 0; m < 4; m++) {
            int node = base + m;
            if (node < nNodes) {
                float mu = sum[m] * (1.0f / 256.0f);
                float var = sq[m] * (1.0f / 256.0f) - mu * mu;
                float rs = rsqrtf(var + EPS_LN);
                #pragma unroll
                for (int j = 0; j < 8; j++)
                    out[(size_t)node * 256 + lane + 32 * j] =
                        (acc[j][m] - mu) * rs * gj[j] + bej[j];
            }
        }
        __syncwarp();
    }
}

// ---------------------------------------------------------------------------
extern "C" void kernel_launch(void* const* d_in, const int* in_sizes, int n_in,
                              void* d_out, int out_size) {
    const float* x      = (const float*)d_in[0];
    const float* pos    = (const float*)d_in[1];
    const float* normal = (const float*)d_in[2];
    const float* ea     = (const float*)d_in[3];
    const void*  ei     = d_in[4];
    const float* W1  = (const float*)d_in[5];
    const float* b1  = (const float*)d_in[6];
    const float* g1  = (const float*)d_in[7];
    const float* be1 = (const float*)d_in[8];
    const float* W2  = (const float*)d_in[9];
    const float* b2  = (const float*)d_in[10];
    const float* g2  = (const float*)d_in[11];
    const float* be2 = (const float*)d_in[12];
    const float* Wg  = (const float*)d_in[13];
    const float* bg  = (const float*)d_in[14];
    const float* gg  = (const float*)d_in[15];
    const float* beg = (const float*)d_in[16];
    float* out = (float*)d_out;

    int E = in_sizes[4] / 2;
    int N = in_sizes[1] / 3;

    // stage edge-MLP weights into __constant__ (D2D memcpy nodes, capturable)
    cudaMemcpyToSymbolAsync(W1c, W1, 47 * 64 * sizeof(float), 0,
                            cudaMemcpyDeviceToDevice, 0);
    cudaMemcpyToSymbolAsync(W2c, W2, 64 * 128 * sizeof(float), 0,
                            cudaMemcpyDeviceToDevice, 0);
    cudaMemcpyToSymbolAsync(b1c,  b1,  64 * sizeof(float), 0,
                            cudaMemcpyDeviceToDevice, 0);
    cudaMemcpyToSymbolAsync(g1c,  g1,  64 * sizeof(float), 0,
                            cudaMemcpyDeviceToDevice, 0);
    cudaMemcpyToSymbolAsync(be1c, be1, 64 * sizeof(float), 0,
                            cudaMemcpyDeviceToDevice, 0);
    cudaMemcpyToSymbolAsync(b2c,  b2,  128 * sizeof(float), 0,
                            cudaMemcpyDeviceToDevice, 0);
    cudaMemcpyToSymbolAsync(g2c,  g2,  128 * sizeof(float), 0,
                            cudaMemcpyDeviceToDevice, 0);
    cudaMemcpyToSymbolAsync(be2c, be2, 128 * sizeof(float), 0,
                            cudaMemcpyDeviceToDevice, 0);

    static const size_t nodeSmem = 42752 * sizeof(float);   // 171008 B
    cudaFuncSetAttribute(node_kernel, cudaFuncAttributeMaxDynamicSharedMemorySize,
                         (int)nodeSmem);

    init_kernel<<<64, 256>>>((const int*)ei, N);
    hist_kernel<<<512, 256>>>(ei, E);
    scan_kernel<<<1, 1024>>>(N);
    fill_kernel<<<512, 256>>>(ei, E);
    compute_kernel<<<1184, 128>>>(x, pos, normal, ea, ei, E, N);
    node_kernel<<<148, 512, nodeSmem>>>(Wg, bg, gg, beg, out, N);
}

// round 10
// speedup vs baseline: 4.7261x; 4.7261x over previous
#include <cuda_runtime.h>
#include <cstdint>

#define EPS_LN 1e-5f
#define MAX_N 50048
#define MAX_E 1600064

__device__ float g_aggf[(size_t)50000 * 128];
__device__ float g_xr[(size_t)50000 * 32];     // tf32-rounded x
__device__ float g_ear[(size_t)MAX_E * 8];     // tf32-rounded edge_attr
__device__ int g_deg[MAX_N];
__device__ int g_cur[MAX_N];
__device__ int g_off[MAX_N + 1];
__device__ int g_csr[MAX_E];
__device__ int g_is64;

// ---------------------------------------------------------------------------
// tf32 helpers
// ---------------------------------------------------------------------------
__device__ __forceinline__ float tf32r(float v) {
    float o;
    asm("cvt.rna.tf32.f32 %0, %1;" : "=f"(o) : "f"(v));
    return o;
}
__device__ __forceinline__ void mma8(float* c,
                                     unsigned a0, unsigned a1, unsigned a2, unsigned a3,
                                     unsigned b0, unsigned b1) {
    asm volatile(
        "mma.sync.aligned.m16n8k8.row.col.f32.tf32.tf32.f32 "
        "{%0,%1,%2,%3}, {%4,%5,%6,%7}, {%8,%9}, {%0,%1,%2,%3};"
        : "+f"(c[0]), "+f"(c[1]), "+f"(c[2]), "+f"(c[3])
        : "r"(a0), "r"(a1), "r"(a2), "r"(a3), "r"(b0), "r"(b1));
}

__device__ __forceinline__ void sc_angle(float ax, float ay, float az,
                                         float bx, float by, float bz,
                                         float& s, float& c) {
    float cx = ay * bz - az * by;
    float cy = az * bx - ax * bz;
    float cz = ax * by - ay * bx;
    float cn2 = cx * cx + cy * cy + cz * cz;
    float d = ax * bx + ay * by + az * bz;
    float den = cn2 + d * d;
    if (den > 0.0f) {
        float r = rsqrtf(den);
        s = sqrtf(cn2) * r;
        c = d * r;
    } else {
        s = 0.0f;
        c = 1.0f;
    }
}

// ---------------------------------------------------------------------------
// Kernel 1: zero degree counters + detect edge_index dtype
// ---------------------------------------------------------------------------
__global__ void init_kernel(const int* __restrict__ ei32, int nNodes) {
    int tid = blockIdx.x * blockDim.x + threadIdx.x;
    int stride = gridDim.x * blockDim.x;
    for (int i = tid; i < nNodes; i += stride) g_deg[i] = 0;
    if (blockIdx.x == 0 && threadIdx.x == 0) {
        int all0 = 1;
        for (int i = 0; i < 256; i++) all0 &= (ei32[2 * i + 1] == 0);
        g_is64 = all0;
    }
}

// ---------------------------------------------------------------------------
// Kernel 1b: pre-round x and edge_attr to tf32 (rna)
// ---------------------------------------------------------------------------
__global__ void pre_kernel(const float* __restrict__ x,
                           const float* __restrict__ ea, int nx, int nea) {
    int tid = blockIdx.x * blockDim.x + threadIdx.x;
    int stride = gridDim.x * blockDim.x;
    for (int i = tid; i < nx; i += stride) g_xr[i] = tf32r(x[i]);
    for (int i = tid; i < nea; i += stride) g_ear[i] = tf32r(ea[i]);
}

// ---------------------------------------------------------------------------
// Kernel 2: histogram of dst
// ---------------------------------------------------------------------------
__global__ void hist_kernel(const void* __restrict__ eiPtr, int E) {
    const bool is64 = (g_is64 != 0);
    const long long* ei64 = (const long long*)eiPtr;
    const int* ei32 = (const int*)eiPtr;
    int tid = blockIdx.x * blockDim.x + threadIdx.x;
    int stride = gridDim.x * blockDim.x;
    for (int e = tid; e < E; e += stride) {
        int dst = is64 ? (int)ei64[(long long)E + e] : ei32[(long long)E + e];
        atomicAdd(&g_deg[dst], 1);
    }
}

// ---------------------------------------------------------------------------
// Kernel 3: single-block exclusive scan
// ---------------------------------------------------------------------------
__global__ void scan_kernel(int nNodes) {
    __shared__ int part[1024];
    int t = threadIdx.x;
    int CH = (nNodes + 1023) / 1024;
    int base = t * CH;
    int s = 0;
    for (int k = 0; k < CH; k++) {
        int idx = base + k;
        if (idx < nNodes) s += g_deg[idx];
    }
    part[t] = s;
    __syncthreads();
    for (int off = 1; off < 1024; off <<= 1) {
        int v = (t >= off) ? part[t - off] : 0;
        __syncthreads();
        part[t] += v;
        __syncthreads();
    }
    int run = part[t] - s;
    for (int k = 0; k < CH; k++) {
        int idx = base + k;
        if (idx < nNodes) {
            g_off[idx] = run;
            g_cur[idx] = run;
            run += g_deg[idx];
        }
    }
    if (t == 1023) g_off[nNodes] = run;
}

// ---------------------------------------------------------------------------
// Kernel 4: fill CSR
// ---------------------------------------------------------------------------
__global__ void fill_kernel(const void* __restrict__ eiPtr, int E) {
    const bool is64 = (g_is64 != 0);
    const long long* ei64 = (const long long*)eiPtr;
    const int* ei32 = (const int*)eiPtr;
    int tid = blockIdx.x * blockDim.x + threadIdx.x;
    int stride = gridDim.x * blockDim.x;
    for (int e = tid; e < E; e += stride) {
        int dst = is64 ? (int)ei64[(long long)E + e] : ei32[(long long)E + e];
        int p = atomicAdd(&g_cur[dst], 1);
        g_csr[p] = e;
    }
}

// ---------------------------------------------------------------------------
// Kernel 5: tf32 mma.sync fused edge MLP + segment max.
// Warp per node, 16 edges per batch.
// GEMM1: [16x48]x[48x64], GEMM2: [16x64]x[64x128], LN in fragments.
// ---------------------------------------------------------------------------
// smem float offsets
#define OFF_W1  0            // 48*72 = 3456
#define OFF_W2  3456         // 64*136 = 8704
#define OFF_B1  12160
#define OFF_G1  12224
#define OFF_BE1 12288
#define OFF_B2  12352
#define OFF_G2  12480
#define OFF_BE2 12608
#define OFF_A1  12736        // 4 warps * 16*52 = 3328
#define OFF_A2  16064        // 4 warps * 16*68 = 4352
#define SMEM_FLOATS 20416    // 81664 bytes

__global__ __launch_bounds__(128)
void compute_kernel(const float* __restrict__ pos,
                    const float* __restrict__ normal,
                    const void* __restrict__ eiPtr,
                    const float* __restrict__ W1, const float* __restrict__ b1,
                    const float* __restrict__ g1, const float* __restrict__ be1,
                    const float* __restrict__ W2, const float* __restrict__ b2,
                    const float* __restrict__ g2, const float* __restrict__ be2,
                    int E, int nNodes) {
    extern __shared__ float sm[];
    int tid = threadIdx.x;

    // zero W tiles (covers pad rows), then fill rna-rounded
    for (int i = tid; i < 48 * 72; i += 128) sm[OFF_W1 + i] = 0.0f;
    for (int i = tid; i < 64 * 136; i += 128) sm[OFF_W2 + i] = 0.0f;
    __syncthreads();
    for (int i = tid; i < 47 * 64; i += 128) {
        int k = i >> 6, n = i & 63;
        sm[OFF_W1 + k * 72 + n] = tf32r(W1[i]);
    }
    for (int i = tid; i < 64 * 128; i += 128) {
        int k = i >> 7, n = i & 127;
        sm[OFF_W2 + k * 136 + n] = tf32r(W2[i]);
    }
    for (int i = tid; i < 64; i += 128) {
        sm[OFF_B1 + i] = b1[i]; sm[OFF_G1 + i] = g1[i]; sm[OFF_BE1 + i] = be1[i];
    }
    for (int i = tid; i < 128; i += 128) {
        sm[OFF_B2 + i] = b2[i]; sm[OFF_G2 + i] = g2[i]; sm[OFF_BE2 + i] = be2[i];
    }
    __syncthreads();

    const int lane = tid & 31;
    const int w = tid >> 5;
    const int g = lane >> 2;      // row group 0..7
    const int t = lane & 3;       // thread in group 0..3
    const int warpGlobal = (blockIdx.x << 2) + w;
    const int warpsTotal = gridDim.x << 2;
    const bool is64 = (g_is64 != 0);
    const long long* ei64 = (const long long*)eiPtr;
    const int* ei32 = (const int*)eiPtr;

    float* A1 = sm + OFF_A1 + w * 832;    // [16][52]
    float* A2 = sm + OFF_A2 + w * 1088;   // [16][68]

    const float NEG_INF = -__int_as_float(0x7f800000);

    for (int node = warpGlobal; node < nNodes; node += warpsTotal) {
        int rowStart = g_off[node];
        int deg = g_off[node + 1] - rowStart;

        float mx[32];
        #pragma unroll
        for (int i = 0; i < 32; i++) mx[i] = NEG_INF;

        float pix = pos[node * 3 + 0], piy = pos[node * 3 + 1], piz = pos[node * 3 + 2];
        float nix = normal[node * 3 + 0], niy = normal[node * 3 + 1], niz = normal[node * 3 + 2];

        for (int it = 0; it < deg; it += 16) {
            int eid = 0, src = 0;
            if (lane < 16) {
                int idx = it + lane;
                int cl = (idx < deg) ? idx : (deg - 1);
                eid = g_csr[rowStart + cl];
                src = is64 ? (int)ei64[eid] : ei32[eid];
            }
            // stage x rows (pre-rounded)
            #pragma unroll
            for (int m = 0; m < 16; m++) {
                int srcm = __shfl_sync(0xffffffffu, src, m);
                A1[m * 52 + lane] = g_xr[(size_t)srcm * 32 + lane];
            }
            // stage ea + ppf, lane m handles edge m
            if (lane < 16) {
                float* q = A1 + lane * 52;
                const float4* ep = (const float4*)(g_ear + (size_t)eid * 8);
                float4 e0 = ep[0], e1 = ep[1];
                q[39] = e0.x; q[40] = e0.y; q[41] = e0.z; q[42] = e0.w;
                q[43] = e1.x; q[44] = e1.y; q[45] = e1.z; q[46] = e1.w;
                q[47] = 0.0f;
                float pjx = pos[src * 3 + 0], pjy = pos[src * 3 + 1], pjz = pos[src * 3 + 2];
                float px = pjx - pix, py = pjy - piy, pz = pjz - piz;
                float njx = normal[src * 3 + 0], njy = normal[src * 3 + 1], njz = normal[src * 3 + 2];
                q[32] = tf32r(sqrtf(px * px + py * py + pz * pz) * 0.125f);
                float s, c;
                sc_angle(nix, niy, niz, px, py, pz, s, c);
                q[33] = tf32r(s); q[34] = tf32r(c);
                sc_angle(njx, njy, njz, px, py, pz, s, c);
                q[35] = tf32r(s); q[36] = tf32r(c);
                sc_angle(nix, niy, niz, njx, njy, njz, s, c);
                q[37] = tf32r(s); q[38] = tf32r(c);
            }
            __syncwarp();

            // ---- GEMM1: [16x48] x [48x64] ----
            float c1[8][4];
            #pragma unroll
            for (int nt = 0; nt < 8; nt++) {
                float bl = sm[OFF_B1 + 8 * nt + 2 * t];
                float bh = sm[OFF_B1 + 8 * nt + 2 * t + 1];
                c1[nt][0] = bl; c1[nt][1] = bh; c1[nt][2] = bl; c1[nt][3] = bh;
            }
            #pragma unroll
            for (int ks = 0; ks < 6; ks++) {
                unsigned a0 = __float_as_uint(A1[g * 52 + 8 * ks + t]);
                unsigned a1v = __float_as_uint(A1[(g + 8) * 52 + 8 * ks + t]);
                unsigned a2 = __float_as_uint(A1[g * 52 + 8 * ks + t + 4]);
                unsigned a3 = __float_as_uint(A1[(g + 8) * 52 + 8 * ks + t + 4]);
                #pragma unroll
                for (int nt = 0; nt < 8; nt++) {
                    unsigned b0 = __float_as_uint(sm[OFF_W1 + (8 * ks + t) * 72 + 8 * nt + g]);
                    unsigned b1v = __float_as_uint(sm[OFF_W1 + (8 * ks + t + 4) * 72 + 8 * nt + g]);
                    mma8(c1[nt], a0, a1v, a2, a3, b0, b1v);
                }
            }
            // ---- ReLU + LN(64) in fragments; edges g and g+8 per lane ----
            float s0 = 0.0f, q0 = 0.0f, s1 = 0.0f, q1 = 0.0f;
            #pragma unroll
            for (int nt = 0; nt < 8; nt++) {
                float r0 = fmaxf(c1[nt][0], 0.0f), r1 = fmaxf(c1[nt][1], 0.0f);
                float r2 = fmaxf(c1[nt][2], 0.0f), r3 = fmaxf(c1[nt][3], 0.0f);
                c1[nt][0] = r0; c1[nt][1] = r1; c1[nt][2] = r2; c1[nt][3] = r3;
                s0 += r0 + r1; q0 += r0 * r0 + r1 * r1;
                s1 += r2 + r3; q1 += r2 * r2 + r3 * r3;
            }
            s0 += __shfl_xor_sync(0xffffffffu, s0, 1); s0 += __shfl_xor_sync(0xffffffffu, s0, 2);
            q0 += __shfl_xor_sync(0xffffffffu, q0, 1); q0 += __shfl_xor_sync(0xffffffffu, q0, 2);
            s1 += __shfl_xor_sync(0xffffffffu, s1, 1); s1 += __shfl_xor_sync(0xffffffffu, s1, 2);
            q1 += __shfl_xor_sync(0xffffffffu, q1, 1); q1 += __shfl_xor_sync(0xffffffffu, q1, 2);
            float mu0 = s0 * (1.0f / 64.0f);
            float rs0 = rsqrtf(q0 * (1.0f / 64.0f) - mu0 * mu0 + EPS_LN);
            float mu1 = s1 * (1.0f / 64.0f);
            float rs1 = rsqrtf(q1 * (1.0f / 64.0f) - mu1 * mu1 + EPS_LN);
            #pragma unroll
            for (int nt = 0; nt < 8; nt++) {
                int f0 = 8 * nt + 2 * t, f1 = f0 + 1;
                float gl0 = sm[OFF_G1 + f0], bl0 = sm[OFF_BE1 + f0];
                float gl1 = sm[OFF_G1 + f1], bl1 = sm[OFF_BE1 + f1];
                A2[g * 68 + f0]       = tf32r((c1[nt][0] - mu0) * rs0 * gl0 + bl0);
                A2[g * 68 + f1]       = tf32r((c1[nt][1] - mu0) * rs0 * gl1 + bl1);
                A2[(g + 8) * 68 + f0] = tf32r((c1[nt][2] - mu1) * rs1 * gl0 + bl0);
                A2[(g + 8) * 68 + f1] = tf32r((c1[nt][3] - mu1) * rs1 * gl1 + bl1);
            }
            __syncwarp();

            // ---- GEMM2: [16x64] x [64x128] ----
            float c2[16][4];
            #pragma unroll
            for (int nt = 0; nt < 16; nt++) {
                float bl = sm[OFF_B2 + 8 * nt + 2 * t];
                float bh = sm[OFF_B2 + 8 * nt + 2 * t + 1];
                c2[nt][0] = bl; c2[nt][1] = bh; c2[nt][2] = bl; c2[nt][3] = bh;
            }
            #pragma unroll
            for (int ks = 0; ks < 8; ks++) {
                unsigned a0 = __float_as_uint(A2[g * 68 + 8 * ks + t]);
                unsigned a1v = __float_as_uint(A2[(g + 8) * 68 + 8 * ks + t]);
                unsigned a2 = __float_as_uint(A2[g * 68 + 8 * ks + t + 4]);
                unsigned a3 = __float_as_uint(A2[(g + 8) * 68 + 8 * ks + t + 4]);
                #pragma unroll
                for (int nt = 0; nt < 16; nt++) {
                    unsigned b0 = __float_as_uint(sm[OFF_W2 + (8 * ks + t) * 136 + 8 * nt + g]);
                    unsigned b1v = __float_as_uint(sm[OFF_W2 + (8 * ks + t + 4) * 136 + 8 * nt + g]);
                    mma8(c2[nt], a0, a1v, a2, a3, b0, b1v);
                }
            }
            // ---- ReLU + LN(128) + cross-edge max ----
            s0 = 0.0f; q0 = 0.0f; s1 = 0.0f; q1 = 0.0f;
            #pragma unroll
            for (int nt = 0; nt < 16; nt++) {
                float r0 = fmaxf(c2[nt][0], 0.0f), r1 = fmaxf(c2[nt][1], 0.0f);
                float r2 = fmaxf(c2[nt][2], 0.0f), r3 = fmaxf(c2[nt][3], 0.0f);
                c2[nt][0] = r0; c2[nt][1] = r1; c2[nt][2] = r2; c2[nt][3] = r3;
                s0 += r0 + r1; q0 += r0 * r0 + r1 * r1;
                s1 += r2 + r3; q1 += r2 * r2 + r3 * r3;
            }
            s0 += __shfl_xor_sync(0xffffffffu, s0, 1); s0 += __shfl_xor_sync(0xffffffffu, s0, 2);
            q0 += __shfl_xor_sync(0xffffffffu, q0, 1); q0 += __shfl_xor_sync(0xffffffffu, q0, 2);
            s1 += __shfl_xor_sync(0xffffffffu, s1, 1); s1 += __shfl_xor_sync(0xffffffffu, s1, 2);
            q1 += __shfl_xor_sync(0xffffffffu, q1, 1); q1 += __shfl_xor_sync(0xffffffffu, q1, 2);
            mu0 = s0 * (1.0f / 128.0f);
            rs0 = rsqrtf(q0 * (1.0f / 128.0f) - mu0 * mu0 + EPS_LN);
            mu1 = s1 * (1.0f / 128.0f);
            rs1 = rsqrtf(q1 * (1.0f / 128.0f) - mu1 * mu1 + EPS_LN);
            #pragma unroll
            for (int nt = 0; nt < 16; nt++) {
                int f0 = 8 * nt + 2 * t, f1 = f0 + 1;
                float g20 = sm[OFF_G2 + f0], b20 = sm[OFF_BE2 + f0];
                float g21 = sm[OFF_G2 + f1], b21 = sm[OFF_BE2 + f1];
                float v0 = fmaxf((c2[nt][0] - mu0) * rs0 * g20 + b20,
                                 (c2[nt][2] - mu1) * rs1 * g20 + b20);
                float v1 = fmaxf((c2[nt][1] - mu0) * rs0 * g21 + b21,
                                 (c2[nt][3] - mu1) * rs1 * g21 + b21);
                v0 = fmaxf(v0, __shfl_xor_sync(0xffffffffu, v0, 4));
                v0 = fmaxf(v0, __shfl_xor_sync(0xffffffffu, v0, 8));
                v0 = fmaxf(v0, __shfl_xor_sync(0xffffffffu, v0, 16));
                v1 = fmaxf(v1, __shfl_xor_sync(0xffffffffu, v1, 4));
                v1 = fmaxf(v1, __shfl_xor_sync(0xffffffffu, v1, 8));
                v1 = fmaxf(v1, __shfl_xor_sync(0xffffffffu, v1, 16));
                mx[2 * nt]     = fmaxf(mx[2 * nt], v0);
                mx[2 * nt + 1] = fmaxf(mx[2 * nt + 1], v1);
            }
            __syncwarp();
        }

        // lanes 0..3 (g==0, t=lane) hold all 128 features: f = 8*nt + 2*t + p
        if (lane < 4) {
            #pragma unroll
            for (int nt = 0; nt < 16; nt++) {
                g_aggf[(size_t)node * 128 + 8 * nt + 2 * lane] =
                    (deg > 0) ? mx[2 * nt] : 0.0f;
                g_aggf[(size_t)node * 128 + 8 * nt + 2 * lane + 1] =
                    (deg > 0) ? mx[2 * nt + 1] : 0.0f;
            }
        }
    }
}

// ---------------------------------------------------------------------------
// Kernel 6: node MLP 128->256 (ReLU+LN), fp32, one warp x 4 nodes
// ---------------------------------------------------------------------------
__global__ __launch_bounds__(512)
void node_kernel(const float* __restrict__ Wg, const float* __restrict__ bg,
                 const float* __restrict__ gg, const float* __restrict__ beg,
                 float* __restrict__ out, int nNodes) {
    extern __shared__ float sm[];
    float* sWgT = sm;            // [256 rows][132 floats]
    float* sbg  = sm + 33792;
    float* sgg  = sm + 34048;
    float* sbeg = sm + 34304;
    float* sH   = sm + 34560;    // 16 warps * 4 nodes * 128

    int tid = threadIdx.x;
    for (int t = tid; t < 128 * 256; t += 512) {
        int i = t >> 8, k = t & 255;
        sWgT[k * 132 + i] = Wg[t];
    }
    for (int t = tid; t < 256; t += 512) { sbg[t] = bg[t]; sgg[t] = gg[t]; sbeg[t] = beg[t]; }
    __syncthreads();

    int lane = tid & 31, w = tid >> 5;
    int warpGlobal = blockIdx.x * 16 + w;
    int warpsTotal = gridDim.x * 16;
    float* myH = sH + w * 512;

    float bj[8], gj[8], bej[8];
    #pragma unroll
    for (int j = 0; j < 8; j++) {
        int k = lane + 32 * j;
        bj[j] = sbg[k]; gj[j] = sgg[k]; bej[j] = sbeg[k];
    }

    for (int base = warpGlobal * 4; base < nNodes; base += warpsTotal * 4) {
        #pragma unroll
        for (int m = 0; m < 4; m++) {
            int node = base + m;
            int nc = (node < nNodes) ? node : base;
            float4 f = ((const float4*)g_aggf)[(size_t)nc * 32 + lane];
            ((float4*)(myH + m * 128))[lane] = f;
        }
        __syncwarp();

        float acc[8][4];
        #pragma unroll
        for (int j = 0; j < 8; j++)
            #pragma unroll
            for (int m = 0; m < 4; m++) acc[j][m] = bj[j];

        #pragma unroll 4
        for (int i4 = 0; i4 < 32; i4++) {
            float4 wv[8];
            #pragma unroll
            for (int j = 0; j < 8; j++)
                wv[j] = *(const float4*)(sWgT + (lane + 32 * j) * 132 + i4 * 4);
            #pragma unroll
            for (int m = 0; m < 4; m++) {
                float4 xm = ((const float4*)(myH + m * 128))[i4];
                #pragma unroll
                for (int j = 0; j < 8; j++) {
                    acc[j][m] += xm.x * wv[j].x; acc[j][m] += xm.y * wv[j].y;
                    acc[j][m] += xm.z * wv[j].z; acc[j][m] += xm.w * wv[j].w;
                }
            }
        }

        float sum[4], sq[4];
        #pragma unroll
        for (int m = 0; m < 4; m++) {
            sum[m] = 0.0f; sq[m] = 0.0f;
            #pragma unroll
            for (int j = 0; j < 8; j++) {
                float v = fmaxf(acc[j][m], 0.0f);
                acc[j][m] = v;
                sum[m] += v;
                sq[m] += v * v;
            }
        }
        #pragma unroll
        for (int off = 16; off > 0; off >>= 1) {
            #pragma unroll
            for (int m = 0; m < 4; m++) {
                sum[m] += __shfl_xor_sync(0xffffffffu, sum[m], off);
                sq[m]  += __shfl_xor_sync(0xffffffffu, sq[m], off);
            }
        }
        #pragma unroll
        for (int m = 0; m < 4; m++) {
            int node = base + m;
            if (node < nNodes) {
                float mu = sum[m] * (1.0f / 256.0f);
                float var = sq[m] * (1.0f / 256.0f) - mu * mu;
                float rs = rsqrtf(var + EPS_LN);
                #pragma unroll
                for (int j = 0; j < 8; j++)
                    out[(size_t)node * 256 + lane + 32 * j] =
                        (acc[j][m] - mu) * rs * gj[j] + bej[j];
            }
        }
        __syncwarp();
    }
}

// ---------------------------------------------------------------------------
extern "C" void kernel_launch(void* const* d_in, const int* in_sizes, int n_in,
                              void* d_out, int out_size) {
    const float* x      = (const float*)d_in[0];
    const float* pos    = (const float*)d_in[1];
    const float* normal = (const float*)d_in[2];
    const float* ea     = (const float*)d_in[3];
    const void*  ei     = d_in[4];
    const float* W1  = (const float*)d_in[5];
    const float* b1  = (const float*)d_in[6];
    const float* g1  = (const float*)d_in[7];
    const float* be1 = (const float*)d_in[8];
    const float* W2  = (const float*)d_in[9];
    const float* b2  = (const float*)d_in[10];
    const float* g2  = (const float*)d_in[11];
    const float* be2 = (const float*)d_in[12];
    const float* Wg  = (const float*)d_in[13];
    const float* bg  = (const float*)d_in[14];
    const float* gg  = (const float*)d_in[15];
    const float* beg = (const float*)d_in[16];
    float* out = (float*)d_out;

    int E = in_sizes[4] / 2;
    int N = in_sizes[1] / 3;

    static const size_t cmpSmem = SMEM_FLOATS * sizeof(float);  // 81664 B
    static const size_t nodeSmem = 42752 * sizeof(float);       // 171008 B
    cudaFuncSetAttribute(compute_kernel, cudaFuncAttributeMaxDynamicSharedMemorySize,
                         (int)cmpSmem);
    cudaFuncSetAttribute(node_kernel, cudaFuncAttributeMaxDynamicSharedMemorySize,
                         (int)nodeSmem);

    init_kernel<<<64, 256>>>((const int*)ei, N);
    pre_kernel<<<512, 256>>>(x, ea, N * 32, E * 8);
    hist_kernel<<<512, 256>>>(ei, E);
    scan_kernel<<<1, 1024>>>(N);
    fill_kernel<<<512, 256>>>(ei, E);
    compute_kernel<<<592, 128, cmpSmem>>>(pos, normal, ei,
                                          W1, b1, g1, be1, W2, b2, g2, be2, E, N);
    node_kernel<<<148, 512, nodeSmem>>>(Wg, bg, gg, beg, out, N);
}

// round 12
// speedup vs baseline: 7.1178x; 1.5060x over previous
#include <cuda_runtime.h>
#include <cstdint>

#define EPS_LN 1e-5f
#define MAX_N 50048
#define MAX_E 1600064

__device__ float g_aggf[(size_t)50000 * 128];
__device__ float g_xr[(size_t)50000 * 32];     // tf32-rounded x
__device__ float g_ear[(size_t)MAX_E * 8];     // tf32-rounded edge_attr
__device__ int g_deg[MAX_N];
__device__ int g_cur[MAX_N];
__device__ int g_off[MAX_N + 1];
__device__ int g_csr[MAX_E];
__device__ int g_bsum[64];
__device__ int g_is64;

// ---------------------------------------------------------------------------
// tf32 helpers
// ---------------------------------------------------------------------------
__device__ __forceinline__ float tf32r(float v) {
    float o;
    asm("cvt.rna.tf32.f32 %0, %1;" : "=f"(o) : "f"(v));
    return o;
}
__device__ __forceinline__ void mma8(float* c,
                                     unsigned a0, unsigned a1, unsigned a2, unsigned a3,
                                     unsigned b0, unsigned b1) {
    asm volatile(
        "mma.sync.aligned.m16n8k8.row.col.f32.tf32.tf32.f32 "
        "{%0,%1,%2,%3}, {%4,%5,%6,%7}, {%8,%9}, {%0,%1,%2,%3};"
        : "+f"(c[0]), "+f"(c[1]), "+f"(c[2]), "+f"(c[3])
        : "r"(a0), "r"(a1), "r"(a2), "r"(a3), "r"(b0), "r"(b1));
}

__device__ __forceinline__ void sc_angle(float ax, float ay, float az,
                                         float bx, float by, float bz,
                                         float& s, float& c) {
    float cx = ay * bz - az * by;
    float cy = az * bx - ax * bz;
    float cz = ax * by - ay * bx;
    float cn2 = cx * cx + cy * cy + cz * cz;
    float d = ax * bx + ay * by + az * bz;
    float den = cn2 + d * d;
    if (den > 0.0f) {
        float r = rsqrtf(den);
        s = sqrtf(cn2) * r;
        c = d * r;
    } else {
        s = 0.0f;
        c = 1.0f;
    }
}

// ---------------------------------------------------------------------------
// Kernel 1: zero degree counters + detect edge_index dtype
// ---------------------------------------------------------------------------
__global__ void init_kernel(const int* __restrict__ ei32, int nNodes) {
    int tid = blockIdx.x * blockDim.x + threadIdx.x;
    int stride = gridDim.x * blockDim.x;
    for (int i = tid; i < nNodes; i += stride) g_deg[i] = 0;
    if (blockIdx.x == 0 && threadIdx.x == 0) {
        int all0 = 1;
        for (int i = 0; i < 256; i++) all0 &= (ei32[2 * i + 1] == 0);
        g_is64 = all0;
    }
}

// ---------------------------------------------------------------------------
// Kernel 1b: pre-round x and edge_attr to tf32 (rna)
// ---------------------------------------------------------------------------
__global__ void pre_kernel(const float* __restrict__ x,
                           const float* __restrict__ ea, int nx, int nea) {
    int tid = blockIdx.x * blockDim.x + threadIdx.x;
    int stride = gridDim.x * blockDim.x;
    for (int i = tid; i < nx; i += stride) g_xr[i] = tf32r(x[i]);
    for (int i = tid; i < nea; i += stride) g_ear[i] = tf32r(ea[i]);
}

// ---------------------------------------------------------------------------
// Kernel 2: histogram of dst
// ---------------------------------------------------------------------------
__global__ void hist_kernel(const void* __restrict__ eiPtr, int E) {
    const bool is64 = (g_is64 != 0);
    const long long* ei64 = (const long long*)eiPtr;
    const int* ei32 = (const int*)eiPtr;
    int tid = blockIdx.x * blockDim.x + threadIdx.x;
    int stride = gridDim.x * blockDim.x;
    for (int e = tid; e < E; e += stride) {
        int dst = is64 ? (int)ei64[(long long)E + e] : ei32[(long long)E + e];
        atomicAdd(&g_deg[dst], 1);
    }
}

// ---------------------------------------------------------------------------
// Kernels 3a/3b/3c: parallel 3-phase exclusive scan of g_deg -> g_off, g_cur
// ---------------------------------------------------------------------------
__global__ void scanA_kernel(int nNodes) {
    int idx = blockIdx.x * 1024 + threadIdx.x;
    int lane = threadIdx.x & 31, wid = threadIdx.x >> 5;
    int v = (idx < nNodes) ? g_deg[idx] : 0;
    #pragma unroll
    for (int o = 16; o > 0; o >>= 1) v += __shfl_xor_sync(0xffffffffu, v, o);
    __shared__ int ws[32];
    if (lane == 0) ws[wid] = v;
    __syncthreads();
    if (threadIdx.x < 32) {
        int s = ws[threadIdx.x];
        #pragma unroll
        for (int o = 16; o > 0; o >>= 1) s += __shfl_xor_sync(0xffffffffu, s, o);
        if (threadIdx.x == 0) g_bsum[blockIdx.x] = s;
    }
}

__global__ void scanB_kernel(int nb) {
    __shared__ int sv[64];
    int t = threadIdx.x;
    sv[t] = (t < nb) ? g_bsum[t] : 0;
    __syncthreads();
    if (t == 0) {
        int run = 0;
        for (int i = 0; i < nb; i++) { int v = sv[i]; sv[i] = run; run += v; }
    }
    __syncthreads();
    if (t < nb) g_bsum[t] = sv[t];
}

__global__ void scanC_kernel(int nNodes) {
    int idx = blockIdx.x * 1024 + threadIdx.x;
    int lane = threadIdx.x & 31, wid = threadIdx.x >> 5;
    int v = (idx < nNodes) ? g_deg[idx] : 0;
    int s = v;
    #pragma unroll
    for (int o = 1; o < 32; o <<= 1) {
        int u = __shfl_up_sync(0xffffffffu, s, o);
        if (lane >= o) s += u;
    }
    __shared__ int ws[32];
    if (lane == 31) ws[wid] = s;
    __syncthreads();
    if (wid == 0) {
        int u = ws[lane];
        int ss = u;
        #pragma unroll
        for (int o = 1; o < 32; o <<= 1) {
            int p = __shfl_up_sync(0xffffffffu, ss, o);
            if (lane >= o) ss += p;
        }
        ws[lane] = ss - u;  // exclusive
    }
    __syncthreads();
    int off = g_bsum[blockIdx.x] + ws[wid] + s - v;
    if (idx < nNodes) {
        g_off[idx] = off;
        g_cur[idx] = off;
        if (idx == nNodes - 1) g_off[nNodes] = off + v;
    }
}

// ---------------------------------------------------------------------------
// Kernel 4: fill CSR
// ---------------------------------------------------------------------------
__global__ void fill_kernel(const void* __restrict__ eiPtr, int E) {
    const bool is64 = (g_is64 != 0);
    const long long* ei64 = (const long long*)eiPtr;
    const int* ei32 = (const int*)eiPtr;
    int tid = blockIdx.x * blockDim.x + threadIdx.x;
    int stride = gridDim.x * blockDim.x;
    for (int e = tid; e < E; e += stride) {
        int dst = is64 ? (int)ei64[(long long)E + e] : ei32[(long long)E + e];
        int p = atomicAdd(&g_cur[dst], 1);
        g_csr[p] = e;
    }
}

// ---------------------------------------------------------------------------
// Kernel 5: tf32 mma.sync fused edge MLP + segment max.
// 256-thread CTA (8 warps share staged weights), warp per node, 16 edges/batch.
// ---------------------------------------------------------------------------
// smem float offsets
#define OFF_W1  0            // 48*72 = 3456
#define OFF_W2  3456         // 64*136 = 8704
#define OFF_B1  12160
#define OFF_G1  12224
#define OFF_BE1 12288
#define OFF_B2  12352
#define OFF_G2  12480
#define OFF_BE2 12608
#define OFF_A1  12736        // 8 warps * 16*52 = 6656
#define OFF_A2  19392        // 8 warps * 16*68 = 8704
#define SMEM_FLOATS 28096    // 112384 bytes

__global__ __launch_bounds__(256, 2)
void compute_kernel(const float* __restrict__ pos,
                    const float* __restrict__ normal,
                    const void* __restrict__ eiPtr,
                    const float* __restrict__ W1, const float* __restrict__ b1,
                    const float* __restrict__ g1, const float* __restrict__ be1,
                    const float* __restrict__ W2, const float* __restrict__ b2,
                    const float* __restrict__ g2, const float* __restrict__ be2,
                    int E, int nNodes) {
    extern __shared__ float sm[];
    int tid = threadIdx.x;

    for (int i = tid; i < 48 * 72; i += 256) sm[OFF_W1 + i] = 0.0f;
    for (int i = tid; i < 64 * 136; i += 256) sm[OFF_W2 + i] = 0.0f;
    __syncthreads();
    for (int i = tid; i < 47 * 64; i += 256) {
        int k = i >> 6, n = i & 63;
        sm[OFF_W1 + k * 72 + n] = tf32r(W1[i]);
    }
    for (int i = tid; i < 64 * 128; i += 256) {
        int k = i >> 7, n = i & 127;
        sm[OFF_W2 + k * 136 + n] = tf32r(W2[i]);
    }
    for (int i = tid; i < 64; i += 256) {
        sm[OFF_B1 + i] = b1[i]; sm[OFF_G1 + i] = g1[i]; sm[OFF_BE1 + i] = be1[i];
    }
    for (int i = tid; i < 128; i += 256) {
        sm[OFF_B2 + i] = b2[i]; sm[OFF_G2 + i] = g2[i]; sm[OFF_BE2 + i] = be2[i];
    }
    __syncthreads();

    const int lane = tid & 31;
    const int w = tid >> 5;
    const int g = lane >> 2;      // row group 0..7
    const int t = lane & 3;       // thread in group 0..3
    const int warpGlobal = (blockIdx.x << 3) + w;
    const int warpsTotal = gridDim.x << 3;
    const bool is64 = (g_is64 != 0);
    const long long* ei64 = (const long long*)eiPtr;
    const int* ei32 = (const int*)eiPtr;

    float* A1 = sm + OFF_A1 + w * 832;    // [16][52]
    float* A2 = sm + OFF_A2 + w * 1088;   // [16][68]

    const float NEG_INF = -__int_as_float(0x7f800000);

    for (int node = warpGlobal; node < nNodes; node += warpsTotal) {
        int rowStart = g_off[node];
        int deg = g_off[node + 1] - rowStart;

        // lane (g,t) owns features of nt in {2g, 2g+1}: 4 running maxima
        float mx4[4];
        #pragma unroll
        for (int i = 0; i < 4; i++) mx4[i] = NEG_INF;

        float pix = pos[node * 3 + 0], piy = pos[node * 3 + 1], piz = pos[node * 3 + 2];
        float nix = normal[node * 3 + 0], niy = normal[node * 3 + 1], niz = normal[node * 3 + 2];

        for (int it = 0; it < deg; it += 16) {
            int eid = 0, src = 0;
            if (lane < 16) {
                int idx = it + lane;
                int cl = (idx < deg) ? idx : (deg - 1);
                eid = g_csr[rowStart + cl];
                src = is64 ? (int)ei64[eid] : ei32[eid];
            }
            // stage x rows (pre-rounded)
            #pragma unroll
            for (int m = 0; m < 16; m++) {
                int srcm = __shfl_sync(0xffffffffu, src, m);
                A1[m * 52 + lane] = g_xr[(size_t)srcm * 32 + lane];
            }
            // stage ea + ppf, lane m handles edge m
            if (lane < 16) {
                float* q = A1 + lane * 52;
                const float4* ep = (const float4*)(g_ear + (size_t)eid * 8);
                float4 e0 = ep[0], e1 = ep[1];
                q[39] = e0.x; q[40] = e0.y; q[41] = e0.z; q[42] = e0.w;
                q[43] = e1.x; q[44] = e1.y; q[45] = e1.z; q[46] = e1.w;
                q[47] = 0.0f;
                float pjx = pos[src * 3 + 0], pjy = pos[src * 3 + 1], pjz = pos[src * 3 + 2];
                float px = pjx - pix, py = pjy - piy, pz = pjz - piz;
                float njx = normal[src * 3 + 0], njy = normal[src * 3 + 1], njz = normal[src * 3 + 2];
                q[32] = tf32r(sqrtf(px * px + py * py + pz * pz) * 0.125f);
                float s, c;
                sc_angle(nix, niy, niz, px, py, pz, s, c);
                q[33] = tf32r(s); q[34] = tf32r(c);
                sc_angle(njx, njy, njz, px, py, pz, s, c);
                q[35] = tf32r(s); q[36] = tf32r(c);
                sc_angle(nix, niy, niz, njx, njy, njz, s, c);
                q[37] = tf32r(s); q[38] = tf32r(c);
            }
            __syncwarp();

            // ---- GEMM1: [16x48] x [48x64] ----
            float c1[8][4];
            #pragma unroll
            for (int nt = 0; nt < 8; nt++) {
                float bl = sm[OFF_B1 + 8 * nt + 2 * t];
                float bh = sm[OFF_B1 + 8 * nt + 2 * t + 1];
                c1[nt][0] = bl; c1[nt][1] = bh; c1[nt][2] = bl; c1[nt][3] = bh;
            }
            #pragma unroll
            for (int ks = 0; ks < 6; ks++) {
                unsigned a0 = __float_as_uint(A1[g * 52 + 8 * ks + t]);
                unsigned a1v = __float_as_uint(A1[(g + 8) * 52 + 8 * ks + t]);
                unsigned a2 = __float_as_uint(A1[g * 52 + 8 * ks + t + 4]);
                unsigned a3 = __float_as_uint(A1[(g + 8) * 52 + 8 * ks + t + 4]);
                #pragma unroll
                for (int nt = 0; nt < 8; nt++) {
                    unsigned b0 = __float_as_uint(sm[OFF_W1 + (8 * ks + t) * 72 + 8 * nt + g]);
                    unsigned b1v = __float_as_uint(sm[OFF_W1 + (8 * ks + t + 4) * 72 + 8 * nt + g]);
                    mma8(c1[nt], a0, a1v, a2, a3, b0, b1v);
                }
            }
            // ---- ReLU + LN(64) in fragments ----
            float s0 = 0.0f, q0 = 0.0f, s1 = 0.0f, q1 = 0.0f;
            #pragma unroll
            for (int nt = 0; nt < 8; nt++) {
                float r0 = fmaxf(c1[nt][0], 0.0f), r1 = fmaxf(c1[nt][1], 0.0f);
                float r2 = fmaxf(c1[nt][2], 0.0f), r3 = fmaxf(c1[nt][3], 0.0f);
                c1[nt][0] = r0; c1[nt][1] = r1; c1[nt][2] = r2; c1[nt][3] = r3;
                s0 += r0 + r1; q0 += r0 * r0 + r1 * r1;
                s1 += r2 + r3; q1 += r2 * r2 + r3 * r3;
            }
            s0 += __shfl_xor_sync(0xffffffffu, s0, 1); s0 += __shfl_xor_sync(0xffffffffu, s0, 2);
            q0 += __shfl_xor_sync(0xffffffffu, q0, 1); q0 += __shfl_xor_sync(0xffffffffu, q0, 2);
            s1 += __shfl_xor_sync(0xffffffffu, s1, 1); s1 += __shfl_xor_sync(0xffffffffu, s1, 2);
            q1 += __shfl_xor_sync(0xffffffffu, q1, 1); q1 += __shfl_xor_sync(0xffffffffu, q1, 2);
            float mu0 = s0 * (1.0f / 64.0f);
            float rs0 = rsqrtf(q0 * (1.0f / 64.0f) - mu0 * mu0 + EPS_LN);
            float mu1 = s1 * (1.0f / 64.0f);
            float rs1 = rsqrtf(q1 * (1.0f / 64.0f) - mu1 * mu1 + EPS_LN);
            #pragma unroll
            for (int nt = 0; nt < 8; nt++) {
                int f0 = 8 * nt + 2 * t, f1 = f0 + 1;
                float gl0 = sm[OFF_G1 + f0], bl0 = sm[OFF_BE1 + f0];
                float gl1 = sm[OFF_G1 + f1], bl1 = sm[OFF_BE1 + f1];
                A2[g * 68 + f0]       = tf32r((c1[nt][0] - mu0) * rs0 * gl0 + bl0);
                A2[g * 68 + f1]       = tf32r((c1[nt][1] - mu0) * rs0 * gl1 + bl1);
                A2[(g + 8) * 68 + f0] = tf32r((c1[nt][2] - mu1) * rs1 * gl0 + bl0);
                A2[(g + 8) * 68 + f1] = tf32r((c1[nt][3] - mu1) * rs1 * gl1 + bl1);
            }
            __syncwarp();

            // ---- GEMM2: [16x64] x [64x128] ----
            float c2[16][4];
            #pragma unroll
            for (int nt = 0; nt < 16; nt++) {
                float bl = sm[OFF_B2 + 8 * nt + 2 * t];
                float bh = sm[OFF_B2 + 8 * nt + 2 * t + 1];
                c2[nt][0] = bl; c2[nt][1] = bh; c2[nt][2] = bl; c2[nt][3] = bh;
            }
            #pragma unroll
            for (int ks = 0; ks < 8; ks++) {
                unsigned a0 = __float_as_uint(A2[g * 68 + 8 * ks + t]);
                unsigned a1v = __float_as_uint(A2[(g + 8) * 68 + 8 * ks + t]);
                unsigned a2 = __float_as_uint(A2[g * 68 + 8 * ks + t + 4]);
                unsigned a3 = __float_as_uint(A2[(g + 8) * 68 + 8 * ks + t + 4]);
                #pragma unroll
                for (int nt = 0; nt < 16; nt++) {
                    unsigned b0 = __float_as_uint(sm[OFF_W2 + (8 * ks + t) * 136 + 8 * nt + g]);
                    unsigned b1v = __float_as_uint(sm[OFF_W2 + (8 * ks + t + 4) * 136 + 8 * nt + g]);
                    mma8(c2[nt], a0, a1v, a2, a3, b0, b1v);
                }
            }
            // ---- ReLU + LN(128) + cross-edge max ----
            s0 = 0.0f; q0 = 0.0f; s1 = 0.0f; q1 = 0.0f;
            #pragma unroll
            for (int nt = 0; nt < 16; nt++) {
                float r0 = fmaxf(c2[nt][0], 0.0f), r1 = fmaxf(c2[nt][1], 0.0f);
                float r2 = fmaxf(c2[nt][2], 0.0f), r3 = fmaxf(c2[nt][3], 0.0f);
                c2[nt][0] = r0; c2[nt][1] = r1; c2[nt][2] = r2; c2[nt][3] = r3;
                s0 += r0 + r1; q0 += r0 * r0 + r1 * r1;
                s1 += r2 + r3; q1 += r2 * r2 + r3 * r3;
            }
            s0 += __shfl_xor_sync(0xffffffffu, s0, 1); s0 += __shfl_xor_sync(0xffffffffu, s0, 2);
            q0 += __shfl_xor_sync(0xffffffffu, q0, 1); q0 += __shfl_xor_sync(0xffffffffu, q0, 2);
            s1 += __shfl_xor_sync(0xffffffffu, s1, 1); s1 += __shfl_xor_sync(0xffffffffu, s1, 2);
            q1 += __shfl_xor_sync(0xffffffffu, q1, 1); q1 += __shfl_xor_sync(0xffffffffu, q1, 2);
            mu0 = s0 * (1.0f / 128.0f);
            rs0 = rsqrtf(q0 * (1.0f / 128.0f) - mu0 * mu0 + EPS_LN);
            mu1 = s1 * (1.0f / 128.0f);
            rs1 = rsqrtf(q1 * (1.0f / 128.0f) - mu1 * mu1 + EPS_LN);
            #pragma unroll
            for (int nt = 0; nt < 16; nt++) {
                int f0 = 8 * nt + 2 * t, f1 = f0 + 1;
                float g20 = sm[OFF_G2 + f0], b20 = sm[OFF_BE2 + f0];
                float g21 = sm[OFF_G2 + f1], b21 = sm[OFF_BE2 + f1];
                float v0 = fmaxf((c2[nt][0] - mu0) * rs0 * g20 + b20,
                                 (c2[nt][2] - mu1) * rs1 * g20 + b20);
                float v1 = fmaxf((c2[nt][1] - mu0) * rs0 * g21 + b21,
                                 (c2[nt][3] - mu1) * rs1 * g21 + b21);
                v0 = fmaxf(v0, __shfl_xor_sync(0xffffffffu, v0, 4));
                v0 = fmaxf(v0, __shfl_xor_sync(0xffffffffu, v0, 8));
                v0 = fmaxf(v0, __shfl_xor_sync(0xffffffffu, v0, 16));
                v1 = fmaxf(v1, __shfl_xor_sync(0xffffffffu, v1, 4));
                v1 = fmaxf(v1, __shfl_xor_sync(0xffffffffu, v1, 8));
                v1 = fmaxf(v1, __shfl_xor_sync(0xffffffffu, v1, 16));
                if (g == (nt >> 1)) {
                    int b = nt & 1;
                    mx4[2 * b]     = fmaxf(mx4[2 * b], v0);
                    mx4[2 * b + 1] = fmaxf(mx4[2 * b + 1], v1);
                }
            }
            __syncwarp();
        }

        // lane (g,t) writes features 8*(2g+b) + 2t + p for b,p in {0,1}
        #pragma unroll
        for (int b = 0; b < 2; b++) {
            int nt = 2 * g + b;
            g_aggf[(size_t)node * 128 + 8 * nt + 2 * t] =
                (deg > 0) ? mx4[2 * b] : 0.0f;
            g_aggf[(size_t)node * 128 + 8 * nt + 2 * t + 1] =
                (deg > 0) ? mx4[2 * b + 1] : 0.0f;
        }
    }
}

// ---------------------------------------------------------------------------
// Kernel 6: node MLP 128->256 (ReLU+LN), fp32, one warp x 4 nodes
// ---------------------------------------------------------------------------
__global__ __launch_bounds__(512)
void node_kernel(const float* __restrict__ Wg, const float* __restrict__ bg,
                 const float* __restrict__ gg, const float* __restrict__ beg,
                 float* __restrict__ out, int nNodes) {
    extern __shared__ float sm[];
    float* sWgT = sm;            // [256 rows][132 floats]
    float* sbg  = sm + 33792;
    float* sgg  = sm + 34048;
    float* sbeg = sm + 34304;
    float* sH   = sm + 34560;    // 16 warps * 4 nodes * 128

    int tid = threadIdx.x;
    for (int t = tid; t < 128 * 256; t += 512) {
        int i = t >> 8, k = t & 255;
        sWgT[k * 132 + i] = Wg[t];
    }
    for (int t = tid; t < 256; t += 512) { sbg[t] = bg[t]; sgg[t] = gg[t]; sbeg[t] = beg[t]; }
    __syncthreads();

    int lane = tid & 31, w = tid >> 5;
    int warpGlobal = blockIdx.x * 16 + w;
    int warpsTotal = gridDim.x * 16;
    float* myH = sH + w * 512;

    float bj[8], gj[8], bej[8];
    #pragma unroll
    for (int j = 0; j < 8; j++) {
        int k = lane + 32 * j;
        bj[j] = sbg[k]; gj[j] = sgg[k]; bej[j] = sbeg[k];
    }

    for (int base = warpGlobal * 4; base < nNodes; base += warpsTotal * 4) {
        #pragma unroll
        for (int m = 0; m < 4; m++) {
            int node = base + m;
            int nc = (node < nNodes) ? node : base;
            float4 f = ((const float4*)g_aggf)[(size_t)nc * 32 + lane];
            ((float4*)(myH + m * 128))[lane] = f;
        }
        __syncwarp();

        float acc[8][4];
        #pragma unroll
        for (int j = 0; j < 8; j++)
            #pragma unroll
            for (int m = 0; m < 4; m++) acc[j][m] = bj[j];

        #pragma unroll 4
        for (int i4 = 0; i4 < 32; i4++) {
            float4 wv[8];
            #pragma unroll
            for (int j = 0; j < 8; j++)
                wv[j] = *(const float4*)(sWgT + (lane + 32 * j) * 132 + i4 * 4);
            #pragma unroll
            for (int m = 0; m < 4; m++) {
                float4 xm = ((const float4*)(myH + m * 128))[i4];
                #pragma unroll
                for (int j = 0; j < 8; j++) {
                    acc[j][m] += xm.x * wv[j].x; acc[j][m] += xm.y * wv[j].y;
                    acc[j][m] += xm.z * wv[j].z; acc[j][m] += xm.w * wv[j].w;
                }
            }
        }

        float sum[4], sq[4];
        #pragma unroll
        for (int m = 0; m < 4; m++) {
            sum[m] = 0.0f; sq[m] = 0.0f;
            #pragma unroll
            for (int j = 0; j < 8; j++) {
                float v = fmaxf(acc[j][m], 0.0f);
                acc[j][m] = v;
                sum[m] += v;
                sq[m] += v * v;
            }
        }
        #pragma unroll
        for (int off = 16; off > 0; off >>= 1) {
            #pragma unroll
            for (int m = 0; m < 4; m++) {
                sum[m] += __shfl_xor_sync(0xffffffffu, sum[m], off);
                sq[m]  += __shfl_xor_sync(0xffffffffu, sq[m], off);
            }
        }
        #pragma unroll
        for (int m = 0; m < 4; m++) {
            int node = base + m;
            if (node < nNodes) {
                float mu = sum[m] * (1.0f / 256.0f);
                float var = sq[m] * (1.0f / 256.0f) - mu * mu;
                float rs = rsqrtf(var + EPS_LN);
                #pragma unroll
                for (int j = 0; j < 8; j++)
                    out[(size_t)node * 256 + lane + 32 * j] =
                        (acc[j][m] - mu) * rs * gj[j] + bej[j];
            }
        }
        __syncwarp();
    }
}

// ---------------------------------------------------------------------------
extern "C" void kernel_launch(void* const* d_in, const int* in_sizes, int n_in,
                              void* d_out, int out_size) {
    const float* x      = (const float*)d_in[0];
    const float* pos    = (const float*)d_in[1];
    const float* normal = (const float*)d_in[2];
    const float* ea     = (const float*)d_in[3];
    const void*  ei     = d_in[4];
    const float* W1  = (const float*)d_in[5];
    const float* b1  = (const float*)d_in[6];
    const float* g1  = (const float*)d_in[7];
    const float* be1 = (const float*)d_in[8];
    const float* W2  = (const float*)d_in[9];
    const float* b2  = (const float*)d_in[10];
    const float* g2  = (const float*)d_in[11];
    const float* be2 = (const float*)d_in[12];
    const float* Wg  = (const float*)d_in[13];
    const float* bg  = (const float*)d_in[14];
    const float* gg  = (const float*)d_in[15];
    const float* beg = (const float*)d_in[16];
    float* out = (float*)d_out;

    int E = in_sizes[4] / 2;
    int N = in_sizes[1] / 3;
    int nb = (N + 1023) / 1024;

    static const size_t cmpSmem = SMEM_FLOATS * sizeof(float);  // 112384 B
    static const size_t nodeSmem = 42752 * sizeof(float);       // 171008 B
    cudaFuncSetAttribute(compute_kernel, cudaFuncAttributeMaxDynamicSharedMemorySize,
                         (int)cmpSmem);
    cudaFuncSetAttribute(node_kernel, cudaFuncAttributeMaxDynamicSharedMemorySize,
                         (int)nodeSmem);

    init_kernel<<<64, 256>>>((const int*)ei, N);
    pre_kernel<<<512, 256>>>(x, ea, N * 32, E * 8);
    hist_kernel<<<512, 256>>>(ei, E);
    scanA_kernel<<<nb, 1024>>>(N);
    scanB_kernel<<<1, 64>>>(nb);
    scanC_kernel<<<nb, 1024>>>(N);
    fill_kernel<<<512, 256>>>(ei, E);
    compute_kernel<<<296, 256, cmpSmem>>>(pos, normal, ei,
                                          W1, b1, g1, be1, W2, b2, g2, be2, E, N);
    node_kernel<<<148, 512, nodeSmem>>>(Wg, bg, gg, beg, out, N);
}

// round 14
// speedup vs baseline: 7.4190x; 1.0423x over previous
#include <cuda_runtime.h>
#include <cstdint>

#define EPS_LN 1e-5f
#define MAX_N 50048
#define MAX_E 1600064

__device__ float g_aggf[(size_t)50000 * 128];
__device__ int g_deg[MAX_N];
__device__ int g_cur[MAX_N];
__device__ int g_off[MAX_N + 1];
__device__ int g_csr[MAX_E];
__device__ int g_bsum[64];
__device__ int g_is64;

// ---------------------------------------------------------------------------
// tf32 helpers
// ---------------------------------------------------------------------------
__device__ __forceinline__ float tf32r(float v) {
    float o;
    asm("cvt.rna.tf32.f32 %0, %1;" : "=f"(o) : "f"(v));
    return o;
}
__device__ __forceinline__ void mma8(float* c,
                                     unsigned a0, unsigned a1, unsigned a2, unsigned a3,
                                     unsigned b0, unsigned b1) {
    asm volatile(
        "mma.sync.aligned.m16n8k8.row.col.f32.tf32.tf32.f32 "
        "{%0,%1,%2,%3}, {%4,%5,%6,%7}, {%8,%9}, {%0,%1,%2,%3};"
        : "+f"(c[0]), "+f"(c[1]), "+f"(c[2]), "+f"(c[3])
        : "r"(a0), "r"(a1), "r"(a2), "r"(a3), "r"(b0), "r"(b1));
}

__device__ __forceinline__ void sc_angle(float ax, float ay, float az,
                                         float bx, float by, float bz,
                                         float& s, float& c) {
    float cx = ay * bz - az * by;
    float cy = az * bx - ax * bz;
    float cz = ax * by - ay * bx;
    float cn2 = cx * cx + cy * cy + cz * cz;
    float d = ax * bx + ay * by + az * bz;
    float den = cn2 + d * d;
    if (den > 0.0f) {
        float r = rsqrtf(den);
        s = sqrtf(cn2) * r;
        c = d * r;
    } else {
        s = 0.0f;
        c = 1.0f;
    }
}

// ---------------------------------------------------------------------------
// Kernel 1: zero degree counters + detect edge_index dtype
// ---------------------------------------------------------------------------
__global__ void init_kernel(const int* __restrict__ ei32, int nNodes) {
    int tid = blockIdx.x * blockDim.x + threadIdx.x;
    int stride = gridDim.x * blockDim.x;
    for (int i = tid; i < nNodes; i += stride) g_deg[i] = 0;
    if (blockIdx.x == 0 && threadIdx.x == 0) {
        int all0 = 1;
        for (int i = 0; i < 256; i++) all0 &= (ei32[2 * i + 1] == 0);
        g_is64 = all0;
    }
}

// ---------------------------------------------------------------------------
// Kernel 2: histogram of dst
// ---------------------------------------------------------------------------
__global__ void hist_kernel(const void* __restrict__ eiPtr, int E) {
    const bool is64 = (g_is64 != 0);
    const long long* ei64 = (const long long*)eiPtr;
    const int* ei32 = (const int*)eiPtr;
    int tid = blockIdx.x * blockDim.x + threadIdx.x;
    int stride = gridDim.x * blockDim.x;
    for (int e = tid; e < E; e += stride) {
        int dst = is64 ? (int)ei64[(long long)E + e] : ei32[(long long)E + e];
        atomicAdd(&g_deg[dst], 1);
    }
}

// ---------------------------------------------------------------------------
// Kernels 3a/3b/3c: parallel 3-phase exclusive scan of g_deg -> g_off, g_cur
// ---------------------------------------------------------------------------
__global__ void scanA_kernel(int nNodes) {
    int idx = blockIdx.x * 1024 + threadIdx.x;
    int lane = threadIdx.x & 31, wid = threadIdx.x >> 5;
    int v = (idx < nNodes) ? g_deg[idx] : 0;
    #pragma unroll
    for (int o = 16; o > 0; o >>= 1) v += __shfl_xor_sync(0xffffffffu, v, o);
    __shared__ int ws[32];
    if (lane == 0) ws[wid] = v;
    __syncthreads();
    if (threadIdx.x < 32) {
        int s = ws[threadIdx.x];
        #pragma unroll
        for (int o = 16; o > 0; o >>= 1) s += __shfl_xor_sync(0xffffffffu, s, o);
        if (threadIdx.x == 0) g_bsum[blockIdx.x] = s;
    }
}

__global__ void scanB_kernel(int nb) {
    __shared__ int sv[64];
    int t = threadIdx.x;
    sv[t] = (t < nb) ? g_bsum[t] : 0;
    __syncthreads();
    if (t == 0) {
        int run = 0;
        for (int i = 0; i < nb; i++) { int v = sv[i]; sv[i] = run; run += v; }
    }
    __syncthreads();
    if (t < nb) g_bsum[t] = sv[t];
}

__global__ void scanC_kernel(int nNodes) {
    int idx = blockIdx.x * 1024 + threadIdx.x;
    int lane = threadIdx.x & 31, wid = threadIdx.x >> 5;
    int v = (idx < nNodes) ? g_deg[idx] : 0;
    int s = v;
    #pragma unroll
    for (int o = 1; o < 32; o <<= 1) {
        int u = __shfl_up_sync(0xffffffffu, s, o);
        if (lane >= o) s += u;
    }
    __shared__ int ws[32];
    if (lane == 31) ws[wid] = s;
    __syncthreads();
    if (wid == 0) {
        int u = ws[lane];
        int ss = u;
        #pragma unroll
        for (int o = 1; o < 32; o <<= 1) {
            int p = __shfl_up_sync(0xffffffffu, ss, o);
            if (lane >= o) ss += p;
        }
        ws[lane] = ss - u;  // exclusive
    }
    __syncthreads();
    int off = g_bsum[blockIdx.x] + ws[wid] + s - v;
    if (idx < nNodes) {
        g_off[idx] = off;
        g_cur[idx] = off;
        if (idx == nNodes - 1) g_off[nNodes] = off + v;
    }
}

// ---------------------------------------------------------------------------
// Kernel 4: fill CSR
// ---------------------------------------------------------------------------
__global__ void fill_kernel(const void* __restrict__ eiPtr, int E) {
    const bool is64 = (g_is64 != 0);
    const long long* ei64 = (const long long*)eiPtr;
    const int* ei32 = (const int*)eiPtr;
    int tid = blockIdx.x * blockDim.x + threadIdx.x;
    int stride = gridDim.x * blockDim.x;
    for (int e = tid; e < E; e += stride) {
        int dst = is64 ? (int)ei64[(long long)E + e] : ei32[(long long)E + e];
        int p = atomicAdd(&g_cur[dst], 1);
        g_csr[p] = e;
    }
}

// ---------------------------------------------------------------------------
// Kernel 5: tf32 mma.sync fused edge MLP + segment max.
// 256-thread CTA (8 warps share staged weights), warp per node, 16 edges/batch.
// Weights in mma-FRAGMENT order (per-lane 16-float chunks, stride 20 ->
// conflict-free LDS.128). A1/A2 aliased into one [16][68] buffer per warp.
// tf32 rounding of x/ea inlined at staging (no pre-pass).
// ---------------------------------------------------------------------------
// smem float offsets
#define OFF_W1F  0            // 6*32*20  = 3840
#define OFF_W2FA 3840         // 8*32*20  = 5120
#define OFF_W2FB 8960         // 8*32*20  = 5120
#define OFF_B1   14080
#define OFF_G1   14144
#define OFF_BE1  14208
#define OFF_B2   14272
#define OFF_G2   14400
#define OFF_BE2  14528
#define OFF_AB   14656        // 8 warps * 16*68 = 8704
#define SMEM_FLOATS 23360     // 93440 bytes

__global__ __launch_bounds__(256, 2)
void compute_kernel(const float* __restrict__ x,
                    const float* __restrict__ pos,
                    const float* __restrict__ normal,
                    const float* __restrict__ ea,
                    const void* __restrict__ eiPtr,
                    const float* __restrict__ W1, const float* __restrict__ b1,
                    const float* __restrict__ g1, const float* __restrict__ be1,
                    const float* __restrict__ W2, const float* __restrict__ b2,
                    const float* __restrict__ g2, const float* __restrict__ be2,
                    int E, int nNodes) {
    extern __shared__ float sm[];
    int tid = threadIdx.x;

    // ---- stage W1 in fragment order: chunk (ks,lane) holds 16 floats:
    // j in 0..7  -> b0 for nt=j   : W1[k=8ks+t      ][n=8j+g]
    // j in 8..15 -> b1 for nt=j-8 : W1[k=8ks+t+4    ][n=8(j-8)+g]
    for (int i = tid; i < 6 * 32 * 16; i += 256) {
        int ks = i >> 9;
        int r = i & 511;
        int ln = r >> 4;
        int j = r & 15;
        int gg = ln >> 2, tt = ln & 3;
        int k = 8 * ks + tt + ((j & 8) ? 4 : 0);
        int n = ((j & 7) << 3) + gg;
        sm[OFF_W1F + (ks * 32 + ln) * 20 + j] =
            (k < 47) ? tf32r(W1[k * 64 + n]) : 0.0f;
    }
    // ---- stage W2: FA = b0 (k=8ks+t), FB = b1 (k=8ks+t+4); j = nt 0..15
    for (int i = tid; i < 8 * 32 * 16; i += 256) {
        int ks = i >> 9;
        int r = i & 511;
        int ln = r >> 4;
        int j = r & 15;
        int gg = ln >> 2, tt = ln & 3;
        int n = (j << 3) + gg;
        sm[OFF_W2FA + (ks * 32 + ln) * 20 + j] = tf32r(W2[(8 * ks + tt) * 128 + n]);
        sm[OFF_W2FB + (ks * 32 + ln) * 20 + j] = tf32r(W2[(8 * ks + tt + 4) * 128 + n]);
    }
    for (int i = tid; i < 64; i += 256) {
        sm[OFF_B1 + i] = b1[i]; sm[OFF_G1 + i] = g1[i]; sm[OFF_BE1 + i] = be1[i];
    }
    for (int i = tid; i < 128; i += 256) {
        sm[OFF_B2 + i] = b2[i]; sm[OFF_G2 + i] = g2[i]; sm[OFF_BE2 + i] = be2[i];
    }
    __syncthreads();

    const int lane = tid & 31;
    const int w = tid >> 5;
    const int g = lane >> 2;      // row group 0..7
    const int t = lane & 3;       // thread in group 0..3
    const int warpGlobal = (blockIdx.x << 3) + w;
    const int warpsTotal = gridDim.x << 3;
    const bool is64 = (g_is64 != 0);
    const long long* ei64 = (const long long*)eiPtr;
    const int* ei32 = (const int*)eiPtr;

    float* AB = sm + OFF_AB + w * 1088;   // [16][68]; A1 cols 0..47, A2 cols 0..63

    const float NEG_INF = -__int_as_float(0x7f800000);

    for (int node = warpGlobal; node < nNodes; node += warpsTotal) {
        int rowStart = g_off[node];
        int deg = g_off[node + 1] - rowStart;

        // lane (g,t) owns features of nt in {2g, 2g+1}: 4 running maxima
        float mx4[4];
        #pragma unroll
        for (int i = 0; i < 4; i++) mx4[i] = NEG_INF;

        float pix = pos[node * 3 + 0], piy = pos[node * 3 + 1], piz = pos[node * 3 + 2];
        float nix = normal[node * 3 + 0], niy = normal[node * 3 + 1], niz = normal[node * 3 + 2];

        for (int it = 0; it < deg; it += 16) {
            int eid = 0, src = 0;
            if (lane < 16) {
                int idx = it + lane;
                int cl = (idx < deg) ? idx : (deg - 1);
                eid = g_csr[rowStart + cl];
                src = is64 ? (int)ei64[eid] : ei32[eid];
            }
            // stage x rows with inline tf32 rounding
            #pragma unroll
            for (int m = 0; m < 16; m++) {
                int srcm = __shfl_sync(0xffffffffu, src, m);
                AB[m * 68 + lane] = tf32r(x[(size_t)srcm * 32 + lane]);
            }
            // stage ea + ppf, lane m handles edge m
            if (lane < 16) {
                float* q = AB + lane * 68;
                const float4* ep = (const float4*)(ea + (size_t)eid * 8);
                float4 e0 = ep[0], e1 = ep[1];
                q[39] = tf32r(e0.x); q[40] = tf32r(e0.y);
                q[41] = tf32r(e0.z); q[42] = tf32r(e0.w);
                q[43] = tf32r(e1.x); q[44] = tf32r(e1.y);
                q[45] = tf32r(e1.z); q[46] = tf32r(e1.w);
                q[47] = 0.0f;
                float pjx = pos[src * 3 + 0], pjy = pos[src * 3 + 1], pjz = pos[src * 3 + 2];
                float px = pjx - pix, py = pjy - piy, pz = pjz - piz;
                float njx = normal[src * 3 + 0], njy = normal[src * 3 + 1], njz = normal[src * 3 + 2];
                q[32] = tf32r(sqrtf(px * px + py * py + pz * pz) * 0.125f);
                float s, c;
                sc_angle(nix, niy, niz, px, py, pz, s, c);
                q[33] = tf32r(s); q[34] = tf32r(c);
                sc_angle(njx, njy, njz, px, py, pz, s, c);
                q[35] = tf32r(s); q[36] = tf32r(c);
                sc_angle(nix, niy, niz, njx, njy, njz, s, c);
                q[37] = tf32r(s); q[38] = tf32r(c);
            }
            __syncwarp();

            // ---- GEMM1: [16x48] x [48x64], weights via LDS.128 fragments ----
            float c1[8][4];
            #pragma unroll
            for (int nt = 0; nt < 8; nt++) {
                float bl = sm[OFF_B1 + 8 * nt + 2 * t];
                float bh = sm[OFF_B1 + 8 * nt + 2 * t + 1];
                c1[nt][0] = bl; c1[nt][1] = bh; c1[nt][2] = bl; c1[nt][3] = bh;
            }
            #pragma unroll
            for (int ks = 0; ks < 6; ks++) {
                unsigned a0 = __float_as_uint(AB[g * 68 + 8 * ks + t]);
                unsigned a1v = __float_as_uint(AB[(g + 8) * 68 + 8 * ks + t]);
                unsigned a2 = __float_as_uint(AB[g * 68 + 8 * ks + t + 4]);
                unsigned a3 = __float_as_uint(AB[(g + 8) * 68 + 8 * ks + t + 4]);
                const float4* wp = (const float4*)(sm + OFF_W1F + (ks * 32 + lane) * 20);
                {
                    float4 w0 = wp[0], w2v = wp[2];  // b0/b1 for nt 0..3
                    mma8(c1[0], a0, a1v, a2, a3, __float_as_uint(w0.x), __float_as_uint(w2v.x));
                    mma8(c1[1], a0, a1v, a2, a3, __float_as_uint(w0.y), __float_as_uint(w2v.y));
                    mma8(c1[2], a0, a1v, a2, a3, __float_as_uint(w0.z), __float_as_uint(w2v.z));
                    mma8(c1[3], a0, a1v, a2, a3, __float_as_uint(w0.w), __float_as_uint(w2v.w));
                }
                {
                    float4 w1v = wp[1], w3v = wp[3];  // b0/b1 for nt 4..7
                    mma8(c1[4], a0, a1v, a2, a3, __float_as_uint(w1v.x), __float_as_uint(w3v.x));
                    mma8(c1[5], a0, a1v, a2, a3, __float_as_uint(w1v.y), __float_as_uint(w3v.y));
                    mma8(c1[6], a0, a1v, a2, a3, __float_as_uint(w1v.z), __float_as_uint(w3v.z));
                    mma8(c1[7], a0, a1v, a2, a3, __float_as_uint(w1v.w), __float_as_uint(w3v.w));
                }
            }
            // ---- ReLU + LN(64) in fragments ----
            float s0 = 0.0f, q0 = 0.0f, s1 = 0.0f, q1 = 0.0f;
            #pragma unroll
            for (int nt = 0; nt < 8; nt++) {
                float r0 = fmaxf(c1[nt][0], 0.0f), r1 = fmaxf(c1[nt][1], 0.0f);
                float r2 = fmaxf(c1[nt][2], 0.0f), r3 = fmaxf(c1[nt][3], 0.0f);
                c1[nt][0] = r0; c1[nt][1] = r1; c1[nt][2] = r2; c1[nt][3] = r3;
                s0 += r0 + r1; q0 += r0 * r0 + r1 * r1;
                s1 += r2 + r3; q1 += r2 * r2 + r3 * r3;
            }
            s0 += __shfl_xor_sync(0xffffffffu, s0, 1); s0 += __shfl_xor_sync(0xffffffffu, s0, 2);
            q0 += __shfl_xor_sync(0xffffffffu, q0, 1); q0 += __shfl_xor_sync(0xffffffffu, q0, 2);
            s1 += __shfl_xor_sync(0xffffffffu, s1, 1); s1 += __shfl_xor_sync(0xffffffffu, s1, 2);
            q1 += __shfl_xor_sync(0xffffffffu, q1, 1); q1 += __shfl_xor_sync(0xffffffffu, q1, 2);
            float mu0 = s0 * (1.0f / 64.0f);
            float rs0 = rsqrtf(q0 * (1.0f / 64.0f) - mu0 * mu0 + EPS_LN);
            float mu1 = s1 * (1.0f / 64.0f);
            float rs1 = rsqrtf(q1 * (1.0f / 64.0f) - mu1 * mu1 + EPS_LN);
            __syncwarp();   // all GEMM1 A-reads done before A2 overwrites AB
            #pragma unroll
            for (int nt = 0; nt < 8; nt++) {
                int f0 = 8 * nt + 2 * t, f1 = f0 + 1;
                float gl0 = sm[OFF_G1 + f0], bl0 = sm[OFF_BE1 + f0];
                float gl1 = sm[OFF_G1 + f1], bl1 = sm[OFF_BE1 + f1];
                AB[g * 68 + f0]       = tf32r((c1[nt][0] - mu0) * rs0 * gl0 + bl0);
                AB[g * 68 + f1]       = tf32r((c1[nt][1] - mu0) * rs0 * gl1 + bl1);
                AB[(g + 8) * 68 + f0] = tf32r((c1[nt][2] - mu1) * rs1 * gl0 + bl0);
                AB[(g + 8) * 68 + f1] = tf32r((c1[nt][3] - mu1) * rs1 * gl1 + bl1);
            }
            __syncwarp();

            // ---- GEMM2: [16x64] x [64x128], weights via LDS.128 fragments ----
            float c2[16][4];
            #pragma unroll
            for (int nt = 0; nt < 16; nt++) {
                float bl = sm[OFF_B2 + 8 * nt + 2 * t];
                float bh = sm[OFF_B2 + 8 * nt + 2 * t + 1];
                c2[nt][0] = bl; c2[nt][1] = bh; c2[nt][2] = bl; c2[nt][3] = bh;
            }
            #pragma unroll
            for (int ks = 0; ks < 8; ks++) {
                unsigned a0 = __float_as_uint(AB[g * 68 + 8 * ks + t]);
                unsigned a1v = __float_as_uint(AB[(g + 8) * 68 + 8 * ks + t]);
                unsigned a2 = __float_as_uint(AB[g * 68 + 8 * ks + t + 4]);
                unsigned a3 = __float_as_uint(AB[(g + 8) * 68 + 8 * ks + t + 4]);
                const float4* fap = (const float4*)(sm + OFF_W2FA + (ks * 32 + lane) * 20);
                const float4* fbp = (const float4*)(sm + OFF_W2FB + (ks * 32 + lane) * 20);
                #pragma unroll
                for (int qd = 0; qd < 4; qd++) {
                    float4 fa = fap[qd], fb = fbp[qd];
                    mma8(c2[4 * qd + 0], a0, a1v, a2, a3, __float_as_uint(fa.x), __float_as_uint(fb.x));
                    mma8(c2[4 * qd + 1], a0, a1v, a2, a3, __float_as_uint(fa.y), __float_as_uint(fb.y));
                    mma8(c2[4 * qd + 2], a0, a1v, a2, a3, __float_as_uint(fa.z), __float_as_uint(fb.z));
                    mma8(c2[4 * qd + 3], a0, a1v, a2, a3, __float_as_uint(fa.w), __float_as_uint(fb.w));
                }
            }
            // ---- ReLU + LN(128) + cross-edge max ----
            s0 = 0.0f; q0 = 0.0f; s1 = 0.0f; q1 = 0.0f;
            #pragma unroll
            for (int nt = 0; nt < 16; nt++) {
                float r0 = fmaxf(c2[nt][0], 0.0f), r1 = fmaxf(c2[nt][1], 0.0f);
                float r2 = fmaxf(c2[nt][2], 0.0f), r3 = fmaxf(c2[nt][3], 0.0f);
                c2[nt][0] = r0; c2[nt][1] = r1; c2[nt][2] = r2; c2[nt][3] = r3;
                s0 += r0 + r1; q0 += r0 * r0 + r1 * r1;
                s1 += r2 + r3; q1 += r2 * r2 + r3 * r3;
            }
            s0 += __shfl_xor_sync(0xffffffffu, s0, 1); s0 += __shfl_xor_sync(0xffffffffu, s0, 2);
            q0 += __shfl_xor_sync(0xffffffffu, q0, 1); q0 += __shfl_xor_sync(0xffffffffu, q0, 2);
            s1 += __shfl_xor_sync(0xffffffffu, s1, 1); s1 += __shfl_xor_sync(0xffffffffu, s1, 2);
            q1 += __shfl_xor_sync(0xffffffffu, q1, 1); q1 += __shfl_xor_sync(0xffffffffu, q1, 2);
            mu0 = s0 * (1.0f / 128.0f);
            rs0 = rsqrtf(q0 * (1.0f / 128.0f) - mu0 * mu0 + EPS_LN);
            mu1 = s1 * (1.0f / 128.0f);
            rs1 = rsqrtf(q1 * (1.0f / 128.0f) - mu1 * mu1 + EPS_LN);
            #pragma unroll
            for (int nt = 0; nt < 16; nt++) {
                int f0 = 8 * nt + 2 * t, f1 = f0 + 1;
                float g20 = sm[OFF_G2 + f0], b20 = sm[OFF_BE2 + f0];
                float g21 = sm[OFF_G2 + f1], b21 = sm[OFF_BE2 + f1];
                float v0 = fmaxf((c2[nt][0] - mu0) * rs0 * g20 + b20,
                                 (c2[nt][2] - mu1) * rs1 * g20 + b20);
                float v1 = fmaxf((c2[nt][1] - mu0) * rs0 * g21 + b21,
                                 (c2[nt][3] - mu1) * rs1 * g21 + b21);
                v0 = fmaxf(v0, __shfl_xor_sync(0xffffffffu, v0, 4));
                v0 = fmaxf(v0, __shfl_xor_sync(0xffffffffu, v0, 8));
                v0 = fmaxf(v0, __shfl_xor_sync(0xffffffffu, v0, 16));
                v1 = fmaxf(v1, __shfl_xor_sync(0xffffffffu, v1, 4));
                v1 = fmaxf(v1, __shfl_xor_sync(0xffffffffu, v1, 8));
                v1 = fmaxf(v1, __shfl_xor_sync(0xffffffffu, v1, 16));
                if (g == (nt >> 1)) {
                    int b = nt & 1;
                    mx4[2 * b]     = fmaxf(mx4[2 * b], v0);
                    mx4[2 * b + 1] = fmaxf(mx4[2 * b + 1], v1);
                }
            }
            __syncwarp();
        }

        // lane (g,t) writes features 8*(2g+b) + 2t + p for b,p in {0,1}
        #pragma unroll
        for (int b = 0; b < 2; b++) {
            int nt = 2 * g + b;
            g_aggf[(size_t)node * 128 + 8 * nt + 2 * t] =
                (deg > 0) ? mx4[2 * b] : 0.0f;
            g_aggf[(size_t)node * 128 + 8 * nt + 2 * t + 1] =
                (deg > 0) ? mx4[2 * b + 1] : 0.0f;
        }
    }
}

// ---------------------------------------------------------------------------
// Kernel 6: node MLP 128->256 (ReLU+LN), fp32, one warp x 4 nodes
// ---------------------------------------------------------------------------
__global__ __launch_bounds__(512)
void node_kernel(const float* __restrict__ Wg, const float* __restrict__ bg,
                 const float* __restrict__ gg, const float* __restrict__ beg,
                 float* __restrict__ out, int nNodes) {
    extern __shared__ float sm[];
    float* sWgT = sm;            // [256 rows][132 floats]
    float* sbg  = sm + 33792;
    float* sgg  = sm + 34048;
    float* sbeg = sm + 34304;
    float* sH   = sm + 34560;    // 16 warps * 4 nodes * 128

    int tid = threadIdx.x;
    for (int t = tid; t < 128 * 256; t += 512) {
        int i = t >> 8, k = t & 255;
        sWgT[k * 132 + i] = Wg[t];
    }
    for (int t = tid; t < 256; t += 512) { sbg[t] = bg[t]; sgg[t] = gg[t]; sbeg[t] = beg[t]; }
    __syncthreads();

    int lane = tid & 31, w = tid >> 5;
    int warpGlobal = blockIdx.x * 16 + w;
    int warpsTotal = gridDim.x * 16;
    float* myH = sH + w * 512;

    float bj[8], gj[8], bej[8];
    #pragma unroll
    for (int j = 0; j < 8; j++) {
        int k = lane + 32 * j;
        bj[j] = sbg[k]; gj[j] = sgg[k]; bej[j] = sbeg[k];
    }

    for (int base = warpGlobal * 4; base < nNodes; base += warpsTotal * 4) {
        #pragma unroll
        for (int m = 0; m < 4; m++) {
            int node = base + m;
            int nc = (node < nNodes) ? node : base;
            float4 f = ((const float4*)g_aggf)[(size_t)nc * 32 + lane];
            ((float4*)(myH + m * 128))[lane] = f;
        }
        __syncwarp();

        float acc[8][4];
        #pragma unroll
        for (int j = 0; j < 8; j++)
            #pragma unroll
            for (int m = 0; m < 4; m++) acc[j][m] = bj[j];

        #pragma unroll 4
        for (int i4 = 0; i4 < 32; i4++) {
            float4 wv[8];
            #pragma unroll
            for (int j = 0; j < 8; j++)
                wv[j] = *(const float4*)(sWgT + (lane + 32 * j) * 132 + i4 * 4);
            #pragma unroll
            for (int m = 0; m < 4; m++) {
                float4 xm = ((const float4*)(myH + m * 128))[i4];
                #pragma unroll
                for (int j = 0; j < 8; j++) {
                    acc[j][m] += xm.x * wv[j].x; acc[j][m] += xm.y * wv[j].y;
                    acc[j][m] += xm.z * wv[j].z; acc[j][m] += xm.w * wv[j].w;
                }
            }
        }

        float sum[4], sq[4];
        #pragma unroll
        for (int m = 0; m < 4; m++) {
            sum[m] = 0.0f; sq[m] = 0.0f;
            #pragma unroll
            for (int j = 0; j < 8; j++) {
                float v = fmaxf(acc[j][m], 0.0f);
                acc[j][m] = v;
                sum[m] += v;
                sq[m] += v * v;
            }
        }
        #pragma unroll
        for (int off = 16; off > 0; off >>= 1) {
            #pragma unroll
            for (int m = 0; m < 4; m++) {
                sum[m] += __shfl_xor_sync(0xffffffffu, sum[m], off);
                sq[m]  += __shfl_xor_sync(0xffffffffu, sq[m], off);
            }
        }
        #pragma unroll
        for (int m = 0; m < 4; m++) {
            int node = base + m;
            if (node < nNodes) {
                float mu = sum[m] * (1.0f / 256.0f);
                float var = sq[m] * (1.0f / 256.0f) - mu * mu;
                float rs = rsqrtf(var + EPS_LN);
                #pragma unroll
                for (int j = 0; j < 8; j++)
                    out[(size_t)node * 256 + lane + 32 * j] =
                        (acc[j][m] - mu) * rs * gj[j] + bej[j];
            }
        }
        __syncwarp();
    }
}

// ---------------------------------------------------------------------------
extern "C" void kernel_launch(void* const* d_in, const int* in_sizes, int n_in,
                              void* d_out, int out_size) {
    const float* x      = (const float*)d_in[0];
    const float* pos    = (const float*)d_in[1];
    const float* normal = (const float*)d_in[2];
    const float* ea     = (const float*)d_in[3];
    const void*  ei     = d_in[4];
    const float* W1  = (const float*)d_in[5];
    const float* b1  = (const float*)d_in[6];
    const float* g1  = (const float*)d_in[7];
    const float* be1 = (const float*)d_in[8];
    const float* W2  = (const float*)d_in[9];
    const float* b2  = (const float*)d_in[10];
    const float* g2  = (const float*)d_in[11];
    const float* be2 = (const float*)d_in[12];
    const float* Wg  = (const float*)d_in[13];
    const float* bg  = (const float*)d_in[14];
    const float* gg  = (const float*)d_in[15];
    const float* beg = (const float*)d_in[16];
    float* out = (float*)d_out;

    int E = in_sizes[4] / 2;
    int N = in_sizes[1] / 3;
    int nb = (N + 1023) / 1024;

    static const size_t cmpSmem = SMEM_FLOATS * sizeof(float);  // 93440 B
    static const size_t nodeSmem = 42752 * sizeof(float);       // 171008 B
    cudaFuncSetAttribute(compute_kernel, cudaFuncAttributeMaxDynamicSharedMemorySize,
                         (int)cmpSmem);
    cudaFuncSetAttribute(node_kernel, cudaFuncAttributeMaxDynamicSharedMemorySize,
                         (int)nodeSmem);

    init_kernel<<<64, 256>>>((const int*)ei, N);
    hist_kernel<<<512, 256>>>(ei, E);
    scanA_kernel<<<nb, 1024>>>(N);
    scanB_kernel<<<1, 64>>>(nb);
    scanC_kernel<<<nb, 1024>>>(N);
    fill_kernel<<<512, 256>>>(ei, E);
    compute_kernel<<<296, 256, cmpSmem>>>(x, pos, normal, ea, ei,
                                          W1, b1, g1, be1, W2, b2, g2, be2, E, N);
    node_kernel<<<148, 512, nodeSmem>>>(Wg, bg, gg, beg, out, N);
}

// round 15
// speedup vs baseline: 9.2724x; 1.2498x over previous
#include <cuda_runtime.h>
#include <cuda_fp16.h>
#include <cstdint>

#define EPS_LN 1e-5f
#define MAX_N 50048
#define MAX_E 1600064

__device__ float g_aggf[(size_t)50000 * 128];
__device__ int g_deg[MAX_N];
__device__ int g_cur[MAX_N];
__device__ int g_off[MAX_N + 1];
__device__ int g_csr[MAX_E];
__device__ int g_bsum[64];
__device__ int g_is64;

// ---------------------------------------------------------------------------
// fp16 mma helper (m16n8k16, fp32 accumulate). C layout == m16n8k8.
// ---------------------------------------------------------------------------
__device__ __forceinline__ void mma16(float* c,
                                      unsigned a0, unsigned a1, unsigned a2, unsigned a3,
                                      unsigned b0, unsigned b1) {
    asm volatile(
        "mma.sync.aligned.m16n8k16.row.col.f32.f16.f16.f32 "
        "{%0,%1,%2,%3}, {%4,%5,%6,%7}, {%8,%9}, {%0,%1,%2,%3};"
        : "+f"(c[0]), "+f"(c[1]), "+f"(c[2]), "+f"(c[3])
        : "r"(a0), "r"(a1), "r"(a2), "r"(a3), "r"(b0), "r"(b1));
}
__device__ __forceinline__ unsigned h2u(__half2 h) {
    return *(unsigned*)&h;
}

__device__ __forceinline__ void sc_angle(float ax, float ay, float az,
                                         float bx, float by, float bz,
                                         float& s, float& c) {
    float cx = ay * bz - az * by;
    float cy = az * bx - ax * bz;
    float cz = ax * by - ay * bx;
    float cn2 = cx * cx + cy * cy + cz * cz;
    float d = ax * bx + ay * by + az * bz;
    float den = cn2 + d * d;
    if (den > 0.0f) {
        float r = rsqrtf(den);
        s = sqrtf(cn2) * r;
        c = d * r;
    } else {
        s = 0.0f;
        c = 1.0f;
    }
}

// ---------------------------------------------------------------------------
// Kernel 1: zero degree counters + detect edge_index dtype
// ---------------------------------------------------------------------------
__global__ void init_kernel(const int* __restrict__ ei32, int nNodes) {
    int tid = blockIdx.x * blockDim.x + threadIdx.x;
    int stride = gridDim.x * blockDim.x;
    for (int i = tid; i < nNodes; i += stride) g_deg[i] = 0;
    if (blockIdx.x == 0 && threadIdx.x == 0) {
        int all0 = 1;
        for (int i = 0; i < 256; i++) all0 &= (ei32[2 * i + 1] == 0);
        g_is64 = all0;
    }
}

// ---------------------------------------------------------------------------
// Kernel 2: histogram of dst
// ---------------------------------------------------------------------------
__global__ void hist_kernel(const void* __restrict__ eiPtr, int E) {
    const bool is64 = (g_is64 != 0);
    const long long* ei64 = (const long long*)eiPtr;
    const int* ei32 = (const int*)eiPtr;
    int tid = blockIdx.x * blockDim.x + threadIdx.x;
    int stride = gridDim.x * blockDim.x;
    for (int e = tid; e < E; e += stride) {
        int dst = is64 ? (int)ei64[(long long)E + e] : ei32[(long long)E + e];
        atomicAdd(&g_deg[dst], 1);
    }
}

// ---------------------------------------------------------------------------
// Kernels 3a/3b/3c: parallel 3-phase exclusive scan of g_deg -> g_off, g_cur
// ---------------------------------------------------------------------------
__global__ void scanA_kernel(int nNodes) {
    int idx = blockIdx.x * 1024 + threadIdx.x;
    int lane = threadIdx.x & 31, wid = threadIdx.x >> 5;
    int v = (idx < nNodes) ? g_deg[idx] : 0;
    #pragma unroll
    for (int o = 16; o > 0; o >>= 1) v += __shfl_xor_sync(0xffffffffu, v, o);
    __shared__ int ws[32];
    if (lane == 0) ws[wid] = v;
    __syncthreads();
    if (threadIdx.x < 32) {
        int s = ws[threadIdx.x];
        #pragma unroll
        for (int o = 16; o > 0; o >>= 1) s += __shfl_xor_sync(0xffffffffu, s, o);
        if (threadIdx.x == 0) g_bsum[blockIdx.x] = s;
    }
}

__global__ void scanB_kernel(int nb) {
    __shared__ int sv[64];
    int t = threadIdx.x;
    sv[t] = (t < nb) ? g_bsum[t] : 0;
    __syncthreads();
    if (t == 0) {
        int run = 0;
        for (int i = 0; i < nb; i++) { int v = sv[i]; sv[i] = run; run += v; }
    }
    __syncthreads();
    if (t < nb) g_bsum[t] = sv[t];
}

__global__ void scanC_kernel(int nNodes) {
    int idx = blockIdx.x * 1024 + threadIdx.x;
    int lane = threadIdx.x & 31, wid = threadIdx.x >> 5;
    int v = (idx < nNodes) ? g_deg[idx] : 0;
    int s = v;
    #pragma unroll
    for (int o = 1; o < 32; o <<= 1) {
        int u = __shfl_up_sync(0xffffffffu, s, o);
        if (lane >= o) s += u;
    }
    __shared__ int ws[32];
    if (lane == 31) ws[wid] = s;
    __syncthreads();
    if (wid == 0) {
        int u = ws[lane];
        int ss = u;
        #pragma unroll
        for (int o = 1; o < 32; o <<= 1) {
            int p = __shfl_up_sync(0xffffffffu, ss, o);
            if (lane >= o) ss += p;
        }
        ws[lane] = ss - u;  // exclusive
    }
    __syncthreads();
    int off = g_bsum[blockIdx.x] + ws[wid] + s - v;
    if (idx < nNodes) {
        g_off[idx] = off;
        g_cur[idx] = off;
        if (idx == nNodes - 1) g_off[nNodes] = off + v;
    }
}

// ---------------------------------------------------------------------------
// Kernel 4: fill CSR
// ---------------------------------------------------------------------------
__global__ void fill_kernel(const void* __restrict__ eiPtr, int E) {
    const bool is64 = (g_is64 != 0);
    const long long* ei64 = (const long long*)eiPtr;
    const int* ei32 = (const int*)eiPtr;
    int tid = blockIdx.x * blockDim.x + threadIdx.x;
    int stride = gridDim.x * blockDim.x;
    for (int e = tid; e < E; e += stride) {
        int dst = is64 ? (int)ei64[(long long)E + e] : ei32[(long long)E + e];
        int p = atomicAdd(&g_cur[dst], 1);
        g_csr[p] = e;
    }
}

// ---------------------------------------------------------------------------
// Kernel 5: fp16 m16n8k16 mma fused edge MLP + segment max.
// 256-thread CTA (8 warps share staged weights), warp per node, 16 edges/batch.
// Activations staged as half (stride 70 halves = 35 banks: conflict-free
// A-fragment reads). Weights in fragment order (stride-20 word chunks,
// LDS.128). fp32 accumulate; C layout identical to the tf32 version.
// ---------------------------------------------------------------------------
// smem word (b32) offsets
#define OFF_W1F  0            // 3*32*20  = 1920
#define OFF_W2FA 1920         // 4*32*20  = 2560
#define OFF_W2FB 4480         // 4*32*20  = 2560
#define OFF_B1   7040
#define OFF_G1   7104
#define OFF_BE1  7168
#define OFF_B2   7232
#define OFF_G2   7360
#define OFF_BE2  7488
#define OFF_AB   7616         // 8 warps * 16 rows * 70 halves = 4480 words
#define SMEM_FLOATS 12096     // 48384 bytes

__global__ __launch_bounds__(256, 2)
void compute_kernel(const float* __restrict__ x,
                    const float* __restrict__ pos,
                    const float* __restrict__ normal,
                    const float* __restrict__ ea,
                    const void* __restrict__ eiPtr,
                    const float* __restrict__ W1, const float* __restrict__ b1,
                    const float* __restrict__ g1, const float* __restrict__ be1,
                    const float* __restrict__ W2, const float* __restrict__ b2,
                    const float* __restrict__ g2, const float* __restrict__ be2,
                    int E, int nNodes) {
    extern __shared__ float sm[];
    unsigned* smu = (unsigned*)sm;
    int tid = threadIdx.x;

    // ---- W1 fragments (fp16 pairs along k). chunk (ks,lane): 16 words:
    // j 0..7 -> b0 nt=j (k = 16ks+2t, +1); j 8..15 -> b1 nt=j-8 (k +8)
    for (int i = tid; i < 3 * 32 * 16; i += 256) {
        int ks = i >> 9, r = i & 511, ln = r >> 4, j = r & 15;
        int gg = ln >> 2, tt = ln & 3;
        int k0 = 16 * ks + 2 * tt + ((j & 8) ? 8 : 0);
        int n = ((j & 7) << 3) + gg;
        float lo = (k0 < 47) ? W1[k0 * 64 + n] : 0.0f;
        float hi = (k0 + 1 < 47) ? W1[(k0 + 1) * 64 + n] : 0.0f;
        smu[OFF_W1F + (ks * 32 + ln) * 20 + j] = h2u(__floats2half2_rn(lo, hi));
    }
    // ---- W2 fragments: FA = b0 (k=16ks+2t), FB = b1 (k+8); j = nt 0..15
    for (int i = tid; i < 4 * 32 * 16; i += 256) {
        int ks = i >> 9, r = i & 511, ln = r >> 4, j = r & 15;
        int gg = ln >> 2, tt = ln & 3;
        int n = (j << 3) + gg;
        int kA = 16 * ks + 2 * tt, kB = kA + 8;
        smu[OFF_W2FA + (ks * 32 + ln) * 20 + j] =
            h2u(__floats2half2_rn(W2[kA * 128 + n], W2[(kA + 1) * 128 + n]));
        smu[OFF_W2FB + (ks * 32 + ln) * 20 + j] =
            h2u(__floats2half2_rn(W2[kB * 128 + n], W2[(kB + 1) * 128 + n]));
    }
    for (int i = tid; i < 64; i += 256) {
        sm[OFF_B1 + i] = b1[i]; sm[OFF_G1 + i] = g1[i]; sm[OFF_BE1 + i] = be1[i];
    }
    for (int i = tid; i < 128; i += 256) {
        sm[OFF_B2 + i] = b2[i]; sm[OFF_G2 + i] = g2[i]; sm[OFF_BE2 + i] = be2[i];
    }
    __syncthreads();

    const int lane = tid & 31;
    const int w = tid >> 5;
    const int g = lane >> 2;      // row group 0..7
    const int t = lane & 3;       // thread in group 0..3
    const int warpGlobal = (blockIdx.x << 3) + w;
    const int warpsTotal = gridDim.x << 3;
    const bool is64 = (g_is64 != 0);
    const long long* ei64 = (const long long*)eiPtr;
    const int* ei32 = (const int*)eiPtr;

    __half* ABh = (__half*)(sm + OFF_AB) + w * 1120;   // [16 rows][70 halves]
    __half2* ABh2 = (__half2*)ABh;                     // [16][35]

    const float NEG_INF = -__int_as_float(0x7f800000);
    const int rowSel = lane >> 4;   // 0/1 for x staging
    const int cp = lane & 15;       // col pair for x staging

    for (int node = warpGlobal; node < nNodes; node += warpsTotal) {
        int rowStart = g_off[node];
        int deg = g_off[node + 1] - rowStart;

        float mx4[4];
        #pragma unroll
        for (int i = 0; i < 4; i++) mx4[i] = NEG_INF;

        float pix = pos[node * 3 + 0], piy = pos[node * 3 + 1], piz = pos[node * 3 + 2];
        float nix = normal[node * 3 + 0], niy = normal[node * 3 + 1], niz = normal[node * 3 + 2];

        for (int it = 0; it < deg; it += 16) {
            int eid = 0, src = 0;
            if (lane < 16) {
                int idx = it + lane;
                int cl = (idx < deg) ? idx : (deg - 1);
                eid = g_csr[rowStart + cl];
                src = is64 ? (int)ei64[eid] : ei32[eid];
            }
            // stage x rows as half2: lanes cover 2 rows x 16 col-pairs
            #pragma unroll
            for (int it2 = 0; it2 < 8; it2++) {
                int m = 2 * it2 + rowSel;
                int srcm = __shfl_sync(0xffffffffu, src, m);
                float2 xv = *(const float2*)(x + (size_t)srcm * 32 + 2 * cp);
                ABh2[m * 35 + cp] = __floats2half2_rn(xv.x, xv.y);
            }
            // stage ppf + ea (cols 32..47 = pairs 16..23), lane m handles edge m
            if (lane < 16) {
                const float4* ep = (const float4*)(ea + (size_t)eid * 8);
                float4 e0 = ep[0], e1 = ep[1];
                float pjx = pos[src * 3 + 0], pjy = pos[src * 3 + 1], pjz = pos[src * 3 + 2];
                float px = pjx - pix, py = pjy - piy, pz = pjz - piz;
                float njx = normal[src * 3 + 0], njy = normal[src * 3 + 1], njz = normal[src * 3 + 2];
                float d8 = sqrtf(px * px + py * py + pz * pz) * 0.125f;
                float s1, c1a, s2, c2a, s3, c3a;
                sc_angle(nix, niy, niz, px, py, pz, s1, c1a);
                sc_angle(njx, njy, njz, px, py, pz, s2, c2a);
                sc_angle(nix, niy, niz, njx, njy, njz, s3, c3a);
                __half2* q = ABh2 + lane * 35 + 16;
                q[0] = __floats2half2_rn(d8, s1);
                q[1] = __floats2half2_rn(c1a, s2);
                q[2] = __floats2half2_rn(c2a, s3);
                q[3] = __floats2half2_rn(c3a, e0.x);
                q[4] = __floats2half2_rn(e0.y, e0.z);
                q[5] = __floats2half2_rn(e0.w, e1.x);
                q[6] = __floats2half2_rn(e1.y, e1.z);
                q[7] = __floats2half2_rn(e1.w, 0.0f);
            }
            __syncwarp();

            // ---- GEMM1: [16x48] x [48x64] fp16, 3 k-steps ----
            float c1[8][4];
            #pragma unroll
            for (int nt = 0; nt < 8; nt++) {
                float bl = sm[OFF_B1 + 8 * nt + 2 * t];
                float bh = sm[OFF_B1 + 8 * nt + 2 * t + 1];
                c1[nt][0] = bl; c1[nt][1] = bh; c1[nt][2] = bl; c1[nt][3] = bh;
            }
            #pragma unroll
            for (int ks = 0; ks < 3; ks++) {
                const __half* ar = ABh + 16 * ks + 2 * t;
                unsigned a0 = *(const unsigned*)(ar + g * 70);
                unsigned a1v = *(const unsigned*)(ar + (g + 8) * 70);
                unsigned a2 = *(const unsigned*)(ar + g * 70 + 8);
                unsigned a3 = *(const unsigned*)(ar + (g + 8) * 70 + 8);
                const float4* wp = (const float4*)(sm + OFF_W1F + (ks * 32 + lane) * 20);
                float4 w0 = wp[0], w2v = wp[2];   // b0/b1 nt 0..3
                mma16(c1[0], a0, a1v, a2, a3, __float_as_uint(w0.x), __float_as_uint(w2v.x));
                mma16(c1[1], a0, a1v, a2, a3, __float_as_uint(w0.y), __float_as_uint(w2v.y));
                mma16(c1[2], a0, a1v, a2, a3, __float_as_uint(w0.z), __float_as_uint(w2v.z));
                mma16(c1[3], a0, a1v, a2, a3, __float_as_uint(w0.w), __float_as_uint(w2v.w));
                float4 w1v = wp[1], w3v = wp[3];  // b0/b1 nt 4..7
                mma16(c1[4], a0, a1v, a2, a3, __float_as_uint(w1v.x), __float_as_uint(w3v.x));
                mma16(c1[5], a0, a1v, a2, a3, __float_as_uint(w1v.y), __float_as_uint(w3v.y));
                mma16(c1[6], a0, a1v, a2, a3, __float_as_uint(w1v.z), __float_as_uint(w3v.z));
                mma16(c1[7], a0, a1v, a2, a3, __float_as_uint(w1v.w), __float_as_uint(w3v.w));
            }
            // ---- ReLU + LN(64) in fragments ----
            float s0 = 0.0f, q0 = 0.0f, s1 = 0.0f, q1 = 0.0f;
            #pragma unroll
            for (int nt = 0; nt < 8; nt++) {
                float r0 = fmaxf(c1[nt][0], 0.0f), r1 = fmaxf(c1[nt][1], 0.0f);
                float r2 = fmaxf(c1[nt][2], 0.0f), r3 = fmaxf(c1[nt][3], 0.0f);
                c1[nt][0] = r0; c1[nt][1] = r1; c1[nt][2] = r2; c1[nt][3] = r3;
                s0 += r0 + r1; q0 += r0 * r0 + r1 * r1;
                s1 += r2 + r3; q1 += r2 * r2 + r3 * r3;
            }
            s0 += __shfl_xor_sync(0xffffffffu, s0, 1); s0 += __shfl_xor_sync(0xffffffffu, s0, 2);
            q0 += __shfl_xor_sync(0xffffffffu, q0, 1); q0 += __shfl_xor_sync(0xffffffffu, q0, 2);
            s1 += __shfl_xor_sync(0xffffffffu, s1, 1); s1 += __shfl_xor_sync(0xffffffffu, s1, 2);
            q1 += __shfl_xor_sync(0xffffffffu, q1, 1); q1 += __shfl_xor_sync(0xffffffffu, q1, 2);
            float mu0 = s0 * (1.0f / 64.0f);
            float rs0 = rsqrtf(q0 * (1.0f / 64.0f) - mu0 * mu0 + EPS_LN);
            float mu1 = s1 * (1.0f / 64.0f);
            float rs1 = rsqrtf(q1 * (1.0f / 64.0f) - mu1 * mu1 + EPS_LN);
            __syncwarp();   // all GEMM1 A-reads done before h overwrites AB
            #pragma unroll
            for (int nt = 0; nt < 8; nt++) {
                int f0 = 8 * nt + 2 * t, f1 = f0 + 1;
                float gl0 = sm[OFF_G1 + f0], bl0 = sm[OFF_BE1 + f0];
                float gl1 = sm[OFF_G1 + f1], bl1 = sm[OFF_BE1 + f1];
                *(__half2*)(ABh + g * 70 + f0) = __floats2half2_rn(
                    (c1[nt][0] - mu0) * rs0 * gl0 + bl0,
                    (c1[nt][1] - mu0) * rs0 * gl1 + bl1);
                *(__half2*)(ABh + (g + 8) * 70 + f0) = __floats2half2_rn(
                    (c1[nt][2] - mu1) * rs1 * gl0 + bl0,
                    (c1[nt][3] - mu1) * rs1 * gl1 + bl1);
            }
            __syncwarp();

            // ---- GEMM2: [16x64] x [64x128] fp16, 4 k-steps ----
            float c2[16][4];
            #pragma unroll
            for (int nt = 0; nt < 16; nt++) {
                float bl = sm[OFF_B2 + 8 * nt + 2 * t];
                float bh = sm[OFF_B2 + 8 * nt + 2 * t + 1];
                c2[nt][0] = bl; c2[nt][1] = bh; c2[nt][2] = bl; c2[nt][3] = bh;
            }
            #pragma unroll
            for (int ks = 0; ks < 4; ks++) {
                const __half* ar = ABh + 16 * ks + 2 * t;
                unsigned a0 = *(const unsigned*)(ar + g * 70);
                unsigned a1v = *(const unsigned*)(ar + (g + 8) * 70);
                unsigned a2 = *(const unsigned*)(ar + g * 70 + 8);
                unsigned a3 = *(const unsigned*)(ar + (g + 8) * 70 + 8);
                const float4* fap = (const float4*)(sm + OFF_W2FA + (ks * 32 + lane) * 20);
                const float4* fbp = (const float4*)(sm + OFF_W2FB + (ks * 32 + lane) * 20);
                #pragma unroll
                for (int qd = 0; qd < 4; qd++) {
                    float4 fa = fap[qd], fb = fbp[qd];
                    mma16(c2[4 * qd + 0], a0, a1v, a2, a3, __float_as_uint(fa.x), __float_as_uint(fb.x));
                    mma16(c2[4 * qd + 1], a0, a1v, a2, a3, __float_as_uint(fa.y), __float_as_uint(fb.y));
                    mma16(c2[4 * qd + 2], a0, a1v, a2, a3, __float_as_uint(fa.z), __float_as_uint(fb.z));
                    mma16(c2[4 * qd + 3], a0, a1v, a2, a3, __float_as_uint(fa.w), __float_as_uint(fb.w));
                }
            }
            // ---- ReLU + LN(128) + cross-edge max ----
            s0 = 0.0f; q0 = 0.0f; s1 = 0.0f; q1 = 0.0f;
            #pragma unroll
            for (int nt = 0; nt < 16; nt++) {
                float r0 = fmaxf(c2[nt][0], 0.0f), r1 = fmaxf(c2[nt][1], 0.0f);
                float r2 = fmaxf(c2[nt][2], 0.0f), r3 = fmaxf(c2[nt][3], 0.0f);
                c2[nt][0] = r0; c2[nt][1] = r1; c2[nt][2] = r2; c2[nt][3] = r3;
                s0 += r0 + r1; q0 += r0 * r0 + r1 * r1;
                s1 += r2 + r3; q1 += r2 * r2 + r3 * r3;
            }
            s0 += __shfl_xor_sync(0xffffffffu, s0, 1); s0 += __shfl_xor_sync(0xffffffffu, s0, 2);
            q0 += __shfl_xor_sync(0xffffffffu, q0, 1); q0 += __shfl_xor_sync(0xffffffffu, q0, 2);
            s1 += __shfl_xor_sync(0xffffffffu, s1, 1); s1 += __shfl_xor_sync(0xffffffffu, s1, 2);
            q1 += __shfl_xor_sync(0xffffffffu, q1, 1); q1 += __shfl_xor_sync(0xffffffffu, q1, 2);
            mu0 = s0 * (1.0f / 128.0f);
            rs0 = rsqrtf(q0 * (1.0f / 128.0f) - mu0 * mu0 + EPS_LN);
            mu1 = s1 * (1.0f / 128.0f);
            rs1 = rsqrtf(q1 * (1.0f / 128.0f) - mu1 * mu1 + EPS_LN);
            #pragma unroll
            for (int nt = 0; nt < 16; nt++) {
                int f0 = 8 * nt + 2 * t, f1 = f0 + 1;
                float g20 = sm[OFF_G2 + f0], b20 = sm[OFF_BE2 + f0];
                float g21 = sm[OFF_G2 + f1], b21 = sm[OFF_BE2 + f1];
                float v0 = fmaxf((c2[nt][0] - mu0) * rs0 * g20 + b20,
                                 (c2[nt][2] - mu1) * rs1 * g20 + b20);
                float v1 = fmaxf((c2[nt][1] - mu0) * rs0 * g21 + b21,
                                 (c2[nt][3] - mu1) * rs1 * g21 + b21);
                v0 = fmaxf(v0, __shfl_xor_sync(0xffffffffu, v0, 4));
                v0 = fmaxf(v0, __shfl_xor_sync(0xffffffffu, v0, 8));
                v0 = fmaxf(v0, __shfl_xor_sync(0xffffffffu, v0, 16));
                v1 = fmaxf(v1, __shfl_xor_sync(0xffffffffu, v1, 4));
                v1 = fmaxf(v1, __shfl_xor_sync(0xffffffffu, v1, 8));
                v1 = fmaxf(v1, __shfl_xor_sync(0xffffffffu, v1, 16));
                if (g == (nt >> 1)) {
                    int b = nt & 1;
                    mx4[2 * b]     = fmaxf(mx4[2 * b], v0);
                    mx4[2 * b + 1] = fmaxf(mx4[2 * b + 1], v1);
                }
            }
            __syncwarp();
        }

        // lane (g,t) writes features 8*(2g+b) + 2t + p for b,p in {0,1}
        #pragma unroll
        for (int b = 0; b < 2; b++) {
            int nt = 2 * g + b;
            g_aggf[(size_t)node * 128 + 8 * nt + 2 * t] =
                (deg > 0) ? mx4[2 * b] : 0.0f;
            g_aggf[(size_t)node * 128 + 8 * nt + 2 * t + 1] =
                (deg > 0) ? mx4[2 * b + 1] : 0.0f;
        }
    }
}

// ---------------------------------------------------------------------------
// Kernel 6: node MLP 128->256 (ReLU+LN), fp32, one warp x 4 nodes
// ---------------------------------------------------------------------------
__global__ __launch_bounds__(512)
void node_kernel(const float* __restrict__ Wg, const float* __restrict__ bg,
                 const float* __restrict__ gg, const float* __restrict__ beg,
                 float* __restrict__ out, int nNodes) {
    extern __shared__ float sm[];
    float* sWgT = sm;            // [256 rows][132 floats]
    float* sbg  = sm + 33792;
    float* sgg  = sm + 34048;
    float* sbeg = sm + 34304;
    float* sH   = sm + 34560;    // 16 warps * 4 nodes * 128

    int tid = threadIdx.x;
    for (int t = tid; t < 128 * 256; t += 512) {
        int i = t >> 8, k = t & 255;
        sWgT[k * 132 + i] = Wg[t];
    }
    for (int t = tid; t < 256; t += 512) { sbg[t] = bg[t]; sgg[t] = gg[t]; sbeg[t] = beg[t]; }
    __syncthreads();

    int lane = tid & 31, w = tid >> 5;
    int warpGlobal = blockIdx.x * 16 + w;
    int warpsTotal = gridDim.x * 16;
    float* myH = sH + w * 512;

    float bj[8], gj[8], bej[8];
    #pragma unroll
    for (int j = 0; j < 8; j++) {
        int k = lane + 32 * j;
        bj[j] = sbg[k]; gj[j] = sgg[k]; bej[j] = sbeg[k];
    }

    for (int base = warpGlobal * 4; base < nNodes; base += warpsTotal * 4) {
        #pragma unroll
        for (int m = 0; m < 4; m++) {
            int node = base + m;
            int nc = (node < nNodes) ? node : base;
            float4 f = ((const float4*)g_aggf)[(size_t)nc * 32 + lane];
            ((float4*)(myH + m * 128))[lane] = f;
        }
        __syncwarp();

        float acc[8][4];
        #pragma unroll
        for (int j = 0; j < 8; j++)
            #pragma unroll
            for (int m = 0; m < 4; m++) acc[j][m] = bj[j];

        #pragma unroll 4
        for (int i4 = 0; i4 < 32; i4++) {
            float4 wv[8];
            #pragma unroll
            for (int j = 0; j < 8; j++)
                wv[j] = *(const float4*)(sWgT + (lane + 32 * j) * 132 + i4 * 4);
            #pragma unroll
            for (int m = 0; m < 4; m++) {
                float4 xm = ((const float4*)(myH + m * 128))[i4];
                #pragma unroll
                for (int j = 0; j < 8; j++) {
                    acc[j][m] += xm.x * wv[j].x; acc[j][m] += xm.y * wv[j].y;
                    acc[j][m] += xm.z * wv[j].z; acc[j][m] += xm.w * wv[j].w;
                }
            }
        }

        float sum[4], sq[4];
        #pragma unroll
        for (int m = 0; m < 4; m++) {
            sum[m] = 0.0f; sq[m] = 0.0f;
            #pragma unroll
            for (int j = 0; j < 8; j++) {
                float v = fmaxf(acc[j][m], 0.0f);
                acc[j][m] = v;
                sum[m] += v;
                sq[m] += v * v;
            }
        }
        #pragma unroll
        for (int off = 16; off > 0; off >>= 1) {
            #pragma unroll
            for (int m = 0; m < 4; m++) {
                sum[m] += __shfl_xor_sync(0xffffffffu, sum[m], off);
                sq[m]  += __shfl_xor_sync(0xffffffffu, sq[m], off);
            }
        }
        #pragma unroll
        for (int m = 0; m < 4; m++) {
            int node = base + m;
            if (node < nNodes) {
                float mu = sum[m] * (1.0f / 256.0f);
                float var = sq[m] * (1.0f / 256.0f) - mu * mu;
                float rs = rsqrtf(var + EPS_LN);
                #pragma unroll
                for (int j = 0; j < 8; j++)
                    out[(size_t)node * 256 + lane + 32 * j] =
                        (acc[j][m] - mu) * rs * gj[j] + bej[j];
            }
        }
        __syncwarp();
    }
}

// ---------------------------------------------------------------------------
extern "C" void kernel_launch(void* const* d_in, const int* in_sizes, int n_in,
                              void* d_out, int out_size) {
    const float* x      = (const float*)d_in[0];
    const float* pos    = (const float*)d_in[1];
    const float* normal = (const float*)d_in[2];
    const float* ea     = (const float*)d_in[3];
    const void*  ei     = d_in[4];
    const float* W1  = (const float*)d_in[5];
    const float* b1  = (const float*)d_in[6];
    const float* g1  = (const float*)d_in[7];
    const float* be1 = (const float*)d_in[8];
    const float* W2  = (const float*)d_in[9];
    const float* b2  = (const float*)d_in[10];
    const float* g2  = (const float*)d_in[11];
    const float* be2 = (const float*)d_in[12];
    const float* Wg  = (const float*)d_in[13];
    const float* bg  = (const float*)d_in[14];
    const float* gg  = (const float*)d_in[15];
    const float* beg = (const float*)d_in[16];
    float* out = (float*)d_out;

    int E = in_sizes[4] / 2;
    int N = in_sizes[1] / 3;
    int nb = (N + 1023) / 1024;

    static const size_t cmpSmem = SMEM_FLOATS * sizeof(float);  // 48384 B
    static const size_t nodeSmem = 42752 * sizeof(float);       // 171008 B
    cudaFuncSetAttribute(compute_kernel, cudaFuncAttributeMaxDynamicSharedMemorySize,
                         (int)cmpSmem);
    cudaFuncSetAttribute(node_kernel, cudaFuncAttributeMaxDynamicSharedMemorySize,
                         (int)nodeSmem);

    init_kernel<<<64, 256>>>((const int*)ei, N);
    hist_kernel<<<512, 256>>>(ei, E);
    scanA_kernel<<<nb, 1024>>>(N);
    scanB_kernel<<<1, 64>>>(nb);
    scanC_kernel<<<nb, 1024>>>(N);
    fill_kernel<<<512, 256>>>(ei, E);
    compute_kernel<<<296, 256, cmpSmem>>>(x, pos, normal, ea, ei,
                                          W1, b1, g1, be1, W2, b2, g2, be2, E, N);
    node_kernel<<<148, 512, nodeSmem>>>(Wg, bg, gg, beg, out, N);
}

// round 16
// speedup vs baseline: 9.4126x; 1.0151x over previous
#include <cuda_runtime.h>
#include <cuda_fp16.h>
#include <cstdint>

#define EPS_LN 1e-5f
#define MAX_N 50048
#define MAX_E 1600064

__device__ float g_aggf[(size_t)50000 * 128];
__device__ int g_deg[MAX_N];
__device__ int g_cur[MAX_N];
__device__ int g_off[MAX_N + 1];
__device__ int g_csr[MAX_E];
__device__ int g_bsum[64];
__device__ int g_is64;

// ---------------------------------------------------------------------------
// fp16 mma helper (m16n8k16, fp32 accumulate)
// ---------------------------------------------------------------------------
__device__ __forceinline__ void mma16(float* c,
                                      unsigned a0, unsigned a1, unsigned a2, unsigned a3,
                                      unsigned b0, unsigned b1) {
    asm volatile(
        "mma.sync.aligned.m16n8k16.row.col.f32.f16.f16.f32 "
        "{%0,%1,%2,%3}, {%4,%5,%6,%7}, {%8,%9}, {%0,%1,%2,%3};"
        : "+f"(c[0]), "+f"(c[1]), "+f"(c[2]), "+f"(c[3])
        : "r"(a0), "r"(a1), "r"(a2), "r"(a3), "r"(b0), "r"(b1));
}
__device__ __forceinline__ unsigned h2u(__half2 h) {
    return *(unsigned*)&h;
}

__device__ __forceinline__ void sc_angle(float ax, float ay, float az,
                                         float bx, float by, float bz,
                                         float& s, float& c) {
    float cx = ay * bz - az * by;
    float cy = az * bx - ax * bz;
    float cz = ax * by - ay * bx;
    float cn2 = cx * cx + cy * cy + cz * cz;
    float d = ax * bx + ay * by + az * bz;
    float den = cn2 + d * d;
    if (den > 0.0f) {
        float r = rsqrtf(den);
        s = sqrtf(cn2) * r;
        c = d * r;
    } else {
        s = 0.0f;
        c = 1.0f;
    }
}

// ---------------------------------------------------------------------------
// Kernel 1: zero degree counters + detect edge_index dtype
// ---------------------------------------------------------------------------
__global__ void init_kernel(const int* __restrict__ ei32, int nNodes) {
    int tid = blockIdx.x * blockDim.x + threadIdx.x;
    int stride = gridDim.x * blockDim.x;
    for (int i = tid; i < nNodes; i += stride) g_deg[i] = 0;
    if (blockIdx.x == 0 && threadIdx.x == 0) {
        int all0 = 1;
        for (int i = 0; i < 256; i++) all0 &= (ei32[2 * i + 1] == 0);
        g_is64 = all0;
    }
}

// ---------------------------------------------------------------------------
// Kernel 2: histogram of dst
// ---------------------------------------------------------------------------
__global__ void hist_kernel(const void* __restrict__ eiPtr, int E) {
    const bool is64 = (g_is64 != 0);
    const long long* ei64 = (const long long*)eiPtr;
    const int* ei32 = (const int*)eiPtr;
    int tid = blockIdx.x * blockDim.x + threadIdx.x;
    int stride = gridDim.x * blockDim.x;
    for (int e = tid; e < E; e += stride) {
        int dst = is64 ? (int)ei64[(long long)E + e] : ei32[(long long)E + e];
        atomicAdd(&g_deg[dst], 1);
    }
}

// ---------------------------------------------------------------------------
// Kernels 3a/3b/3c: parallel 3-phase exclusive scan of g_deg -> g_off, g_cur
// ---------------------------------------------------------------------------
__global__ void scanA_kernel(int nNodes) {
    int idx = blockIdx.x * 1024 + threadIdx.x;
    int lane = threadIdx.x & 31, wid = threadIdx.x >> 5;
    int v = (idx < nNodes) ? g_deg[idx] : 0;
    #pragma unroll
    for (int o = 16; o > 0; o >>= 1) v += __shfl_xor_sync(0xffffffffu, v, o);
    __shared__ int ws[32];
    if (lane == 0) ws[wid] = v;
    __syncthreads();
    if (threadIdx.x < 32) {
        int s = ws[threadIdx.x];
        #pragma unroll
        for (int o = 16; o > 0; o >>= 1) s += __shfl_xor_sync(0xffffffffu, s, o);
        if (threadIdx.x == 0) g_bsum[blockIdx.x] = s;
    }
}

__global__ void scanB_kernel(int nb) {
    __shared__ int sv[64];
    int t = threadIdx.x;
    sv[t] = (t < nb) ? g_bsum[t] : 0;
    __syncthreads();
    if (t == 0) {
        int run = 0;
        for (int i = 0; i < nb; i++) { int v = sv[i]; sv[i] = run; run += v; }
    }
    __syncthreads();
    if (t < nb) g_bsum[t] = sv[t];
}

__global__ void scanC_kernel(int nNodes) {
    int idx = blockIdx.x * 1024 + threadIdx.x;
    int lane = threadIdx.x & 31, wid = threadIdx.x >> 5;
    int v = (idx < nNodes) ? g_deg[idx] : 0;
    int s = v;
    #pragma unroll
    for (int o = 1; o < 32; o <<= 1) {
        int u = __shfl_up_sync(0xffffffffu, s, o);
        if (lane >= o) s += u;
    }
    __shared__ int ws[32];
    if (lane == 31) ws[wid] = s;
    __syncthreads();
    if (wid == 0) {
        int u = ws[lane];
        int ss = u;
        #pragma unroll
        for (int o = 1; o < 32; o <<= 1) {
            int p = __shfl_up_sync(0xffffffffu, ss, o);
            if (lane >= o) ss += p;
        }
        ws[lane] = ss - u;  // exclusive
    }
    __syncthreads();
    int off = g_bsum[blockIdx.x] + ws[wid] + s - v;
    if (idx < nNodes) {
        g_off[idx] = off;
        g_cur[idx] = off;
        if (idx == nNodes - 1) g_off[nNodes] = off + v;
    }
}

// ---------------------------------------------------------------------------
// Kernel 4: fill CSR
// ---------------------------------------------------------------------------
__global__ void fill_kernel(const void* __restrict__ eiPtr, int E) {
    const bool is64 = (g_is64 != 0);
    const long long* ei64 = (const long long*)eiPtr;
    const int* ei32 = (const int*)eiPtr;
    int tid = blockIdx.x * blockDim.x + threadIdx.x;
    int stride = gridDim.x * blockDim.x;
    for (int e = tid; e < E; e += stride) {
        int dst = is64 ? (int)ei64[(long long)E + e] : ei32[(long long)E + e];
        int p = atomicAdd(&g_cur[dst], 1);
        g_csr[p] = e;
    }
}

// ---------------------------------------------------------------------------
// Kernel 5: fp16 m16n8k16 mma fused edge MLP + segment max.
// 256-thread CTA, warp per node, 16 edges/batch.
// GEMM1 C-fragments are reused directly as GEMM2 A-fragments (h stays in
// registers; no smem round-trip). Next batch's gather (csr/src/x/ea/geom)
// is software-pipelined into registers behind the mma work.
// ---------------------------------------------------------------------------
// smem word (b32) offsets
#define OFF_W1F  0            // 3*32*20  = 1920
#define OFF_W2FA 1920         // 4*32*20  = 2560
#define OFF_W2FB 4480         // 4*32*20  = 2560
#define OFF_B1   7040
#define OFF_G1   7104
#define OFF_BE1  7168
#define OFF_B2   7232
#define OFF_G2   7360
#define OFF_BE2  7488
#define OFF_AB   7616         // 8 warps * 16 rows * 28 words (56 halves)
#define SMEM_FLOATS 11200     // 44800 bytes

__global__ __launch_bounds__(256, 2)
void compute_kernel(const float* __restrict__ x,
                    const float* __restrict__ pos,
                    const float* __restrict__ normal,
                    const float* __restrict__ ea,
                    const void* __restrict__ eiPtr,
                    const float* __restrict__ W1, const float* __restrict__ b1,
                    const float* __restrict__ g1, const float* __restrict__ be1,
                    const float* __restrict__ W2, const float* __restrict__ b2,
                    const float* __restrict__ g2, const float* __restrict__ be2,
                    int E, int nNodes) {
    extern __shared__ float sm[];
    unsigned* smu = (unsigned*)sm;
    int tid = threadIdx.x;

    // ---- W1 fragments (fp16 pairs along k). chunk (ks,lane): 16 words.
    for (int i = tid; i < 3 * 32 * 16; i += 256) {
        int ks = i >> 9, r = i & 511, ln = r >> 4, j = r & 15;
        int gg = ln >> 2, tt = ln & 3;
        int k0 = 16 * ks + 2 * tt + ((j & 8) ? 8 : 0);
        int n = ((j & 7) << 3) + gg;
        float lo = (k0 < 47) ? W1[k0 * 64 + n] : 0.0f;
        float hi = (k0 + 1 < 47) ? W1[(k0 + 1) * 64 + n] : 0.0f;
        smu[OFF_W1F + (ks * 32 + ln) * 20 + j] = h2u(__floats2half2_rn(lo, hi));
    }
    // ---- W2 fragments
    for (int i = tid; i < 4 * 32 * 16; i += 256) {
        int ks = i >> 9, r = i & 511, ln = r >> 4, j = r & 15;
        int gg = ln >> 2, tt = ln & 3;
        int n = (j << 3) + gg;
        int kA = 16 * ks + 2 * tt, kB = kA + 8;
        smu[OFF_W2FA + (ks * 32 + ln) * 20 + j] =
            h2u(__floats2half2_rn(W2[kA * 128 + n], W2[(kA + 1) * 128 + n]));
        smu[OFF_W2FB + (ks * 32 + ln) * 20 + j] =
            h2u(__floats2half2_rn(W2[kB * 128 + n], W2[(kB + 1) * 128 + n]));
    }
    for (int i = tid; i < 64; i += 256) {
        sm[OFF_B1 + i] = b1[i]; sm[OFF_G1 + i] = g1[i]; sm[OFF_BE1 + i] = be1[i];
    }
    for (int i = tid; i < 128; i += 256) {
        sm[OFF_B2 + i] = b2[i]; sm[OFF_G2 + i] = g2[i]; sm[OFF_BE2 + i] = be2[i];
    }
    __syncthreads();

    const int lane = tid & 31;
    const int w = tid >> 5;
    const int g = lane >> 2;
    const int t = lane & 3;
    const int warpGlobal = (blockIdx.x << 3) + w;
    const int warpsTotal = gridDim.x << 3;
    const bool is64 = (g_is64 != 0);
    const long long* ei64 = (const long long*)eiPtr;
    const int* ei32 = (const int*)eiPtr;

    __half* ABh = (__half*)(sm + OFF_AB) + w * (16 * 56);   // [16 rows][56 halves]
    __half2* ABh2 = (__half2*)ABh;                           // [16][28]

    const float NEG_INF = -__int_as_float(0x7f800000);
    const int rowSel = lane >> 4;
    const int cp = lane & 15;

    for (int node = warpGlobal; node < nNodes; node += warpsTotal) {
        int rowStart = g_off[node];
        int deg = g_off[node + 1] - rowStart;

        float mx4[4];
        #pragma unroll
        for (int i = 0; i < 4; i++) mx4[i] = NEG_INF;

        float pix = pos[node * 3 + 0], piy = pos[node * 3 + 1], piz = pos[node * 3 + 2];
        float nix = normal[node * 3 + 0], niy = normal[node * 3 + 1], niz = normal[node * 3 + 2];

        // ---- stage batch 0 (exposed) ----
        if (deg > 0) {
            int eid = 0, src = 0;
            if (lane < 16) {
                int idx = lane;
                int cl = (idx < deg) ? idx : (deg - 1);
                eid = g_csr[rowStart + cl];
                src = is64 ? (int)ei64[eid] : ei32[eid];
            }
            #pragma unroll
            for (int it2 = 0; it2 < 8; it2++) {
                int m = 2 * it2 + rowSel;
                int srcm = __shfl_sync(0xffffffffu, src, m);
                float2 xv = *(const float2*)(x + (size_t)srcm * 32 + 2 * cp);
                ABh2[m * 28 + cp] = __floats2half2_rn(xv.x, xv.y);
            }
            if (lane < 16) {
                const float4* ep = (const float4*)(ea + (size_t)eid * 8);
                float4 e0 = ep[0], e1 = ep[1];
                float pjx = pos[src * 3 + 0], pjy = pos[src * 3 + 1], pjz = pos[src * 3 + 2];
                float px = pjx - pix, py = pjy - piy, pz = pjz - piz;
                float njx = normal[src * 3 + 0], njy = normal[src * 3 + 1], njz = normal[src * 3 + 2];
                float d8 = sqrtf(px * px + py * py + pz * pz) * 0.125f;
                float s1a, c1a, s2a, c2a, s3a, c3a;
                sc_angle(nix, niy, niz, px, py, pz, s1a, c1a);
                sc_angle(njx, njy, njz, px, py, pz, s2a, c2a);
                sc_angle(nix, niy, niz, njx, njy, njz, s3a, c3a);
                __half2* q = ABh2 + lane * 28 + 16;
                q[0] = __floats2half2_rn(d8, s1a);
                q[1] = __floats2half2_rn(c1a, s2a);
                q[2] = __floats2half2_rn(c2a, s3a);
                q[3] = __floats2half2_rn(c3a, e0.x);
                q[4] = __floats2half2_rn(e0.y, e0.z);
                q[5] = __floats2half2_rn(e0.w, e1.x);
                q[6] = __floats2half2_rn(e1.y, e1.z);
                q[7] = __floats2half2_rn(e1.w, 0.0f);
            }
            __syncwarp();
        }

        for (int it = 0; it < deg; it += 16) {
            bool hasNext = (it + 16) < deg;
            // ---- prefetch next batch csr/src (2-dep chain, hidden by GEMM1)
            int eid_n = 0, src_n = 0;
            if (hasNext && lane < 16) {
                int idx = it + 16 + lane;
                int cl = (idx < deg) ? idx : (deg - 1);
                eid_n = g_csr[rowStart + cl];
                src_n = is64 ? (int)ei64[eid_n] : ei32[eid_n];
            }

            // ---- GEMM1: [16x48] x [48x64] fp16, 3 k-steps ----
            float c1[8][4];
            #pragma unroll
            for (int nt = 0; nt < 8; nt++) {
                float bl = sm[OFF_B1 + 8 * nt + 2 * t];
                float bh = sm[OFF_B1 + 8 * nt + 2 * t + 1];
                c1[nt][0] = bl; c1[nt][1] = bh; c1[nt][2] = bl; c1[nt][3] = bh;
            }
            #pragma unroll
            for (int ks = 0; ks < 3; ks++) {
                const __half* ar = ABh + 16 * ks + 2 * t;
                unsigned a0 = *(const unsigned*)(ar + g * 56);
                unsigned a1v = *(const unsigned*)(ar + (g + 8) * 56);
                unsigned a2 = *(const unsigned*)(ar + g * 56 + 8);
                unsigned a3 = *(const unsigned*)(ar + (g + 8) * 56 + 8);
                const float4* wp = (const float4*)(sm + OFF_W1F + (ks * 32 + lane) * 20);
                float4 w0 = wp[0], w2v = wp[2];
                mma16(c1[0], a0, a1v, a2, a3, __float_as_uint(w0.x), __float_as_uint(w2v.x));
                mma16(c1[1], a0, a1v, a2, a3, __float_as_uint(w0.y), __float_as_uint(w2v.y));
                mma16(c1[2], a0, a1v, a2, a3, __float_as_uint(w0.z), __float_as_uint(w2v.z));
                mma16(c1[3], a0, a1v, a2, a3, __float_as_uint(w0.w), __float_as_uint(w2v.w));
                float4 w1v = wp[1], w3v = wp[3];
                mma16(c1[4], a0, a1v, a2, a3, __float_as_uint(w1v.x), __float_as_uint(w3v.x));
                mma16(c1[5], a0, a1v, a2, a3, __float_as_uint(w1v.y), __float_as_uint(w3v.y));
                mma16(c1[6], a0, a1v, a2, a3, __float_as_uint(w1v.z), __float_as_uint(w3v.z));
                mma16(c1[7], a0, a1v, a2, a3, __float_as_uint(w1v.w), __float_as_uint(w3v.w));
            }
            // ---- ReLU + LN(64) in fragments ----
            float s0 = 0.0f, q0 = 0.0f, s1 = 0.0f, q1 = 0.0f;
            #pragma unroll
            for (int nt = 0; nt < 8; nt++) {
                float r0 = fmaxf(c1[nt][0], 0.0f), r1 = fmaxf(c1[nt][1], 0.0f);
                float r2 = fmaxf(c1[nt][2], 0.0f), r3 = fmaxf(c1[nt][3], 0.0f);
                c1[nt][0] = r0; c1[nt][1] = r1; c1[nt][2] = r2; c1[nt][3] = r3;
                s0 += r0 + r1; q0 += r0 * r0 + r1 * r1;
                s1 += r2 + r3; q1 += r2 * r2 + r3 * r3;
            }
            s0 += __shfl_xor_sync(0xffffffffu, s0, 1); s0 += __shfl_xor_sync(0xffffffffu, s0, 2);
            q0 += __shfl_xor_sync(0xffffffffu, q0, 1); q0 += __shfl_xor_sync(0xffffffffu, q0, 2);
            s1 += __shfl_xor_sync(0xffffffffu, s1, 1); s1 += __shfl_xor_sync(0xffffffffu, s1, 2);
            q1 += __shfl_xor_sync(0xffffffffu, q1, 1); q1 += __shfl_xor_sync(0xffffffffu, q1, 2);
            float mu0 = s0 * (1.0f / 64.0f);
            float rs0 = rsqrtf(q0 * (1.0f / 64.0f) - mu0 * mu0 + EPS_LN);
            float mu1 = s1 * (1.0f / 64.0f);
            float rs1 = rsqrtf(q1 * (1.0f / 64.0f) - mu1 * mu1 + EPS_LN);
            // pack normalized h directly into GEMM2 A-fragments (no smem!)
            unsigned hw[4][4];
            #pragma unroll
            for (int ks = 0; ks < 4; ks++) {
                int ntA = 2 * ks, ntB = 2 * ks + 1;
                int fA0 = 8 * ntA + 2 * t, fA1 = fA0 + 1;
                int fB0 = 8 * ntB + 2 * t, fB1 = fB0 + 1;
                float gA0 = sm[OFF_G1 + fA0], bA0 = sm[OFF_BE1 + fA0];
                float gA1 = sm[OFF_G1 + fA1], bA1 = sm[OFF_BE1 + fA1];
                float gB0 = sm[OFF_G1 + fB0], bB0 = sm[OFF_BE1 + fB0];
                float gB1 = sm[OFF_G1 + fB1], bB1 = sm[OFF_BE1 + fB1];
                hw[ks][0] = h2u(__floats2half2_rn(
                    (c1[ntA][0] - mu0) * rs0 * gA0 + bA0,
                    (c1[ntA][1] - mu0) * rs0 * gA1 + bA1));
                hw[ks][1] = h2u(__floats2half2_rn(
                    (c1[ntA][2] - mu1) * rs1 * gA0 + bA0,
                    (c1[ntA][3] - mu1) * rs1 * gA1 + bA1));
                hw[ks][2] = h2u(__floats2half2_rn(
                    (c1[ntB][0] - mu0) * rs0 * gB0 + bB0,
                    (c1[ntB][1] - mu0) * rs0 * gB1 + bB1));
                hw[ks][3] = h2u(__floats2half2_rn(
                    (c1[ntB][2] - mu1) * rs1 * gB0 + bB0,
                    (c1[ntB][3] - mu1) * rs1 * gB1 + bB1));
            }

            // ---- prefetch next batch x / ea / geometry into registers ----
            float2 xn[8];
            float4 ean0, ean1;
            float pnx = 0, pny = 0, pnz = 0, nnx = 0, nny = 0, nnz = 0;
            if (hasNext) {
                #pragma unroll
                for (int it2 = 0; it2 < 8; it2++) {
                    int m = 2 * it2 + rowSel;
                    int srcm = __shfl_sync(0xffffffffu, src_n, m);
                    xn[it2] = *(const float2*)(x + (size_t)srcm * 32 + 2 * cp);
                }
                if (lane < 16) {
                    const float4* ep = (const float4*)(ea + (size_t)eid_n * 8);
                    ean0 = ep[0]; ean1 = ep[1];
                    pnx = pos[src_n * 3 + 0]; pny = pos[src_n * 3 + 1]; pnz = pos[src_n * 3 + 2];
                    nnx = normal[src_n * 3 + 0]; nny = normal[src_n * 3 + 1]; nnz = normal[src_n * 3 + 2];
                }
            }

            // ---- GEMM2: [16x64] x [64x128] fp16, A from hw regs ----
            float c2[16][4];
            #pragma unroll
            for (int nt = 0; nt < 16; nt++) {
                float bl = sm[OFF_B2 + 8 * nt + 2 * t];
                float bh = sm[OFF_B2 + 8 * nt + 2 * t + 1];
                c2[nt][0] = bl; c2[nt][1] = bh; c2[nt][2] = bl; c2[nt][3] = bh;
            }
            #pragma unroll
            for (int ks = 0; ks < 4; ks++) {
                unsigned a0 = hw[ks][0], a1v = hw[ks][1];
                unsigned a2 = hw[ks][2], a3 = hw[ks][3];
                const float4* fap = (const float4*)(sm + OFF_W2FA + (ks * 32 + lane) * 20);
                const float4* fbp = (const float4*)(sm + OFF_W2FB + (ks * 32 + lane) * 20);
                #pragma unroll
                for (int qd = 0; qd < 4; qd++) {
                    float4 fa = fap[qd], fb = fbp[qd];
                    mma16(c2[4 * qd + 0], a0, a1v, a2, a3, __float_as_uint(fa.x), __float_as_uint(fb.x));
                    mma16(c2[4 * qd + 1], a0, a1v, a2, a3, __float_as_uint(fa.y), __float_as_uint(fb.y));
                    mma16(c2[4 * qd + 2], a0, a1v, a2, a3, __float_as_uint(fa.z), __float_as_uint(fb.z));
                    mma16(c2[4 * qd + 3], a0, a1v, a2, a3, __float_as_uint(fa.w), __float_as_uint(fb.w));
                }
            }
            // ---- ReLU + LN(128) + cross-edge max ----
            s0 = 0.0f; q0 = 0.0f; s1 = 0.0f; q1 = 0.0f;
            #pragma unroll
            for (int nt = 0; nt < 16; nt++) {
                float r0 = fmaxf(c2[nt][0], 0.0f), r1 = fmaxf(c2[nt][1], 0.0f);
                float r2 = fmaxf(c2[nt][2], 0.0f), r3 = fmaxf(c2[nt][3], 0.0f);
                c2[nt][0] = r0; c2[nt][1] = r1; c2[nt][2] = r2; c2[nt][3] = r3;
                s0 += r0 + r1; q0 += r0 * r0 + r1 * r1;
                s1 += r2 + r3; q1 += r2 * r2 + r3 * r3;
            }
            s0 += __shfl_xor_sync(0xffffffffu, s0, 1); s0 += __shfl_xor_sync(0xffffffffu, s0, 2);
            q0 += __shfl_xor_sync(0xffffffffu, q0, 1); q0 += __shfl_xor_sync(0xffffffffu, q0, 2);
            s1 += __shfl_xor_sync(0xffffffffu, s1, 1); s1 += __shfl_xor_sync(0xffffffffu, s1, 2);
            q1 += __shfl_xor_sync(0xffffffffu, q1, 1); q1 += __shfl_xor_sync(0xffffffffu, q1, 2);
            mu0 = s0 * (1.0f / 128.0f);
            rs0 = rsqrtf(q0 * (1.0f / 128.0f) - mu0 * mu0 + EPS_LN);
            mu1 = s1 * (1.0f / 128.0f);
            rs1 = rsqrtf(q1 * (1.0f / 128.0f) - mu1 * mu1 + EPS_LN);
            #pragma unroll
            for (int nt = 0; nt < 16; nt++) {
                int f0 = 8 * nt + 2 * t, f1 = f0 + 1;
                float g20 = sm[OFF_G2 + f0], b20 = sm[OFF_BE2 + f0];
                float g21 = sm[OFF_G2 + f1], b21 = sm[OFF_BE2 + f1];
                float v0 = fmaxf((c2[nt][0] - mu0) * rs0 * g20 + b20,
                                 (c2[nt][2] - mu1) * rs1 * g20 + b20);
                float v1 = fmaxf((c2[nt][1] - mu0) * rs0 * g21 + b21,
                                 (c2[nt][3] - mu1) * rs1 * g21 + b21);
                v0 = fmaxf(v0, __shfl_xor_sync(0xffffffffu, v0, 4));
                v0 = fmaxf(v0, __shfl_xor_sync(0xffffffffu, v0, 8));
                v0 = fmaxf(v0, __shfl_xor_sync(0xffffffffu, v0, 16));
                v1 = fmaxf(v1, __shfl_xor_sync(0xffffffffu, v1, 4));
                v1 = fmaxf(v1, __shfl_xor_sync(0xffffffffu, v1, 8));
                v1 = fmaxf(v1, __shfl_xor_sync(0xffffffffu, v1, 16));
                if (g == (nt >> 1)) {
                    int b = nt & 1;
                    mx4[2 * b]     = fmaxf(mx4[2 * b], v0);
                    mx4[2 * b + 1] = fmaxf(mx4[2 * b + 1], v1);
                }
            }
            __syncwarp();   // AB reads (GEMM1) done in all lanes before restage

            // ---- stage next batch from prefetched registers ----
            if (hasNext) {
                #pragma unroll
                for (int it2 = 0; it2 < 8; it2++) {
                    int m = 2 * it2 + rowSel;
                    ABh2[m * 28 + cp] = __floats2half2_rn(xn[it2].x, xn[it2].y);
                }
                if (lane < 16) {
                    float px = pnx - pix, py = pny - piy, pz = pnz - piz;
                    float d8 = sqrtf(px * px + py * py + pz * pz) * 0.125f;
                    float s1a, c1a, s2a, c2a, s3a, c3a;
                    sc_angle(nix, niy, niz, px, py, pz, s1a, c1a);
                    sc_angle(nnx, nny, nnz, px, py, pz, s2a, c2a);
                    sc_angle(nix, niy, niz, nnx, nny, nnz, s3a, c3a);
                    __half2* q = ABh2 + lane * 28 + 16;
                    q[0] = __floats2half2_rn(d8, s1a);
                    q[1] = __floats2half2_rn(c1a, s2a);
                    q[2] = __floats2half2_rn(c2a, s3a);
                    q[3] = __floats2half2_rn(c3a, ean0.x);
                    q[4] = __floats2half2_rn(ean0.y, ean0.z);
                    q[5] = __floats2half2_rn(ean0.w, ean1.x);
                    q[6] = __floats2half2_rn(ean1.y, ean1.z);
                    q[7] = __floats2half2_rn(ean1.w, 0.0f);
                }
            }
            __syncwarp();
        }

        // lane (g,t) writes features 8*(2g+b) + 2t + p for b,p in {0,1}
        #pragma unroll
        for (int b = 0; b < 2; b++) {
            int nt = 2 * g + b;
            g_aggf[(size_t)node * 128 + 8 * nt + 2 * t] =
                (deg > 0) ? mx4[2 * b] : 0.0f;
            g_aggf[(size_t)node * 128 + 8 * nt + 2 * t + 1] =
                (deg > 0) ? mx4[2 * b + 1] : 0.0f;
        }
    }
}

// ---------------------------------------------------------------------------
// Kernel 6: node MLP 128->256 (ReLU+LN), fp32, one warp x 4 nodes
// ---------------------------------------------------------------------------
__global__ __launch_bounds__(512)
void node_kernel(const float* __restrict__ Wg, const float* __restrict__ bg,
                 const float* __restrict__ gg, const float* __restrict__ beg,
                 float* __restrict__ out, int nNodes) {
    extern __shared__ float sm[];
    float* sWgT = sm;            // [256 rows][132 floats]
    float* sbg  = sm + 33792;
    float* sgg  = sm + 34048;
    float* sbeg = sm + 34304;
    float* sH   = sm + 34560;    // 16 warps * 4 nodes * 128

    int tid = threadIdx.x;
    for (int t = tid; t < 128 * 256; t += 512) {
        int i = t >> 8, k = t & 255;
        sWgT[k * 132 + i] = Wg[t];
    }
    for (int t = tid; t < 256; t += 512) { sbg[t] = bg[t]; sgg[t] = gg[t]; sbeg[t] = beg[t]; }
    __syncthreads();

    int lane = tid & 31, w = tid >> 5;
    int warpGlobal = blockIdx.x * 16 + w;
    int warpsTotal = gridDim.x * 16;
    float* myH = sH + w * 512;

    float bj[8], gj[8], bej[8];
    #pragma unroll
    for (int j = 0; j < 8; j++) {
        int k = lane + 32 * j;
        bj[j] = sbg[k]; gj[j] = sgg[k]; bej[j] = sbeg[k];
    }

    for (int base = warpGlobal * 4; base < nNodes; base += warpsTotal * 4) {
        #pragma unroll
        for (int m = 0; m < 4; m++) {
            int node = base + m;
            int nc = (node < nNodes) ? node : base;
            float4 f = ((const float4*)g_aggf)[(size_t)nc * 32 + lane];
            ((float4*)(myH + m * 128))[lane] = f;
        }
        __syncwarp();

        float acc[8][4];
        #pragma unroll
        for (int j = 0; j < 8; j++)
            #pragma unroll
            for (int m = 0; m < 4; m++) acc[j][m] = bj[j];

        #pragma unroll 4
        for (int i4 = 0; i4 < 32; i4++) {
            float4 wv[8];
            #pragma unroll
            for (int j = 0; j < 8; j++)
                wv[j] = *(const float4*)(sWgT + (lane + 32 * j) * 132 + i4 * 4);
            #pragma unroll
            for (int m = 0; m < 4; m++) {
                float4 xm = ((const float4*)(myH + m * 128))[i4];
                #pragma unroll
                for (int j = 0; j < 8; j++) {
                    acc[j][m] += xm.x * wv[j].x; acc[j][m] += xm.y * wv[j].y;
                    acc[j][m] += xm.z * wv[j].z; acc[j][m] += xm.w * wv[j].w;
                }
            }
        }

        float sum[4], sq[4];
        #pragma unroll
        for (int m = 0; m < 4; m++) {
            sum[m] = 0.0f; sq[m] = 0.0f;
            #pragma unroll
            for (int j = 0; j < 8; j++) {
                float v = fmaxf(acc[j][m], 0.0f);
                acc[j][m] = v;
                sum[m] += v;
                sq[m] += v * v;
            }
        }
        #pragma unroll
        for (int off = 16; off > 0; off >>= 1) {
            #pragma unroll
            for (int m = 0; m < 4; m++) {
                sum[m] += __shfl_xor_sync(0xffffffffu, sum[m], off);
                sq[m]  += __shfl_xor_sync(0xffffffffu, sq[m], off);
            }
        }
        #pragma unroll
        for (int m = 0; m < 4; m++) {
            int node = base + m;
            if (node < nNodes) {
                float mu = sum[m] * (1.0f / 256.0f);
                float var = sq[m] * (1.0f / 256.0f) - mu * mu;
                float rs = rsqrtf(var + EPS_LN);
                #pragma unroll
                for (int j = 0; j < 8; j++)
                    out[(size_t)node * 256 + lane + 32 * j] =
                        (acc[j][m] - mu) * rs * gj[j] + bej[j];
            }
        }
        __syncwarp();
    }
}

// ---------------------------------------------------------------------------
extern "C" void kernel_launch(void* const* d_in, const int* in_sizes, int n_in,
                              void* d_out, int out_size) {
    const float* x      = (const float*)d_in[0];
    const float* pos    = (const float*)d_in[1];
    const float* normal = (const float*)d_in[2];
    const float* ea     = (const float*)d_in[3];
    const void*  ei     = d_in[4];
    const float* W1  = (const float*)d_in[5];
    const float* b1  = (const float*)d_in[6];
    const float* g1  = (const float*)d_in[7];
    const float* be1 = (const float*)d_in[8];
    const float* W2  = (const float*)d_in[9];
    const float* b2  = (const float*)d_in[10];
    const float* g2  = (const float*)d_in[11];
    const float* be2 = (const float*)d_in[12];
    const float* Wg  = (const float*)d_in[13];
    const float* bg  = (const float*)d_in[14];
    const float* gg  = (const float*)d_in[15];
    const float* beg = (const float*)d_in[16];
    float* out = (float*)d_out;

    int E = in_sizes[4] / 2;
    int N = in_sizes[1] / 3;
    int nb = (N + 1023) / 1024;

    static const size_t cmpSmem = SMEM_FLOATS * sizeof(float);  // 44800 B
    static const size_t nodeSmem = 42752 * sizeof(float);       // 171008 B
    cudaFuncSetAttribute(compute_kernel, cudaFuncAttributeMaxDynamicSharedMemorySize,
                         (int)cmpSmem);
    cudaFuncSetAttribute(node_kernel, cudaFuncAttributeMaxDynamicSharedMemorySize,
                         (int)nodeSmem);

    init_kernel<<<64, 256>>>((const int*)ei, N);
    hist_kernel<<<512, 256>>>(ei, E);
    scanA_kernel<<<nb, 1024>>>(N);
    scanB_kernel<<<1, 64>>>(nb);
    scanC_kernel<<<nb, 1024>>>(N);
    fill_kernel<<<512, 256>>>(ei, E);
    compute_kernel<<<296, 256, cmpSmem>>>(x, pos, normal, ea, ei,
                                          W1, b1, g1, be1, W2, b2, g2, be2, E, N);
    node_kernel<<<148, 512, nodeSmem>>>(Wg, bg, gg, beg, out, N);
}

// round 17
// speedup vs baseline: 10.8252x; 1.1501x over previous
#include <cuda_runtime.h>
#include <cuda_fp16.h>
#include <cstdint>

#define EPS_LN 1e-5f
#define MAX_N 50048
#define MAX_E 1600064

__device__ float g_aggf[(size_t)50000 * 128];
__device__ int g_deg[MAX_N];
__device__ int g_cur[MAX_N];
__device__ int g_off[MAX_N + 1];
__device__ int g_csr[MAX_E];
__device__ int g_bsum[64];
__device__ int g_is64;

// ---------------------------------------------------------------------------
// fp16 mma helper (m16n8k16, fp32 accumulate)
// ---------------------------------------------------------------------------
__device__ __forceinline__ void mma16(float* c,
                                      unsigned a0, unsigned a1, unsigned a2, unsigned a3,
                                      unsigned b0, unsigned b1) {
    asm volatile(
        "mma.sync.aligned.m16n8k16.row.col.f32.f16.f16.f32 "
        "{%0,%1,%2,%3}, {%4,%5,%6,%7}, {%8,%9}, {%0,%1,%2,%3};"
        : "+f"(c[0]), "+f"(c[1]), "+f"(c[2]), "+f"(c[3])
        : "r"(a0), "r"(a1), "r"(a2), "r"(a3), "r"(b0), "r"(b1));
}
__device__ __forceinline__ unsigned h2u(__half2 h) {
    return *(unsigned*)&h;
}

__device__ __forceinline__ void sc_angle(float ax, float ay, float az,
                                         float bx, float by, float bz,
                                         float& s, float& c) {
    float cx = ay * bz - az * by;
    float cy = az * bx - ax * bz;
    float cz = ax * by - ay * bx;
    float cn2 = cx * cx + cy * cy + cz * cz;
    float d = ax * bx + ay * by + az * bz;
    float den = cn2 + d * d;
    if (den > 0.0f) {
        float r = rsqrtf(den);
        s = sqrtf(cn2) * r;
        c = d * r;
    } else {
        s = 0.0f;
        c = 1.0f;
    }
}

// ---------------------------------------------------------------------------
// Kernel 1: zero degree counters + detect edge_index dtype
// ---------------------------------------------------------------------------
__global__ void init_kernel(const int* __restrict__ ei32, int nNodes) {
    int tid = blockIdx.x * blockDim.x + threadIdx.x;
    int stride = gridDim.x * blockDim.x;
    for (int i = tid; i < nNodes; i += stride) g_deg[i] = 0;
    if (blockIdx.x == 0 && threadIdx.x == 0) {
        int all0 = 1;
        for (int i = 0; i < 256; i++) all0 &= (ei32[2 * i + 1] == 0);
        g_is64 = all0;
    }
}

// ---------------------------------------------------------------------------
// Kernel 2: histogram of dst
// ---------------------------------------------------------------------------
__global__ void hist_kernel(const void* __restrict__ eiPtr, int E) {
    const bool is64 = (g_is64 != 0);
    const long long* ei64 = (const long long*)eiPtr;
    const int* ei32 = (const int*)eiPtr;
    int tid = blockIdx.x * blockDim.x + threadIdx.x;
    int stride = gridDim.x * blockDim.x;
    for (int e = tid; e < E; e += stride) {
        int dst = is64 ? (int)ei64[(long long)E + e] : ei32[(long long)E + e];
        atomicAdd(&g_deg[dst], 1);
    }
}

// ---------------------------------------------------------------------------
// Kernels 3a/3b/3c: parallel 3-phase exclusive scan of g_deg -> g_off, g_cur
// ---------------------------------------------------------------------------
__global__ void scanA_kernel(int nNodes) {
    int idx = blockIdx.x * 1024 + threadIdx.x;
    int lane = threadIdx.x & 31, wid = threadIdx.x >> 5;
    int v = (idx < nNodes) ? g_deg[idx] : 0;
    #pragma unroll
    for (int o = 16; o > 0; o >>= 1) v += __shfl_xor_sync(0xffffffffu, v, o);
    __shared__ int ws[32];
    if (lane == 0) ws[wid] = v;
    __syncthreads();
    if (threadIdx.x < 32) {
        int s = ws[threadIdx.x];
        #pragma unroll
        for (int o = 16; o > 0; o >>= 1) s += __shfl_xor_sync(0xffffffffu, s, o);
        if (threadIdx.x == 0) g_bsum[blockIdx.x] = s;
    }
}

__global__ void scanB_kernel(int nb) {
    __shared__ int sv[64];
    int t = threadIdx.x;
    sv[t] = (t < nb) ? g_bsum[t] : 0;
    __syncthreads();
    if (t == 0) {
        int run = 0;
        for (int i = 0; i < nb; i++) { int v = sv[i]; sv[i] = run; run += v; }
    }
    __syncthreads();
    if (t < nb) g_bsum[t] = sv[t];
}

__global__ void scanC_kernel(int nNodes) {
    int idx = blockIdx.x * 1024 + threadIdx.x;
    int lane = threadIdx.x & 31, wid = threadIdx.x >> 5;
    int v = (idx < nNodes) ? g_deg[idx] : 0;
    int s = v;
    #pragma unroll
    for (int o = 1; o < 32; o <<= 1) {
        int u = __shfl_up_sync(0xffffffffu, s, o);
        if (lane >= o) s += u;
    }
    __shared__ int ws[32];
    if (lane == 31) ws[wid] = s;
    __syncthreads();
    if (wid == 0) {
        int u = ws[lane];
        int ss = u;
        #pragma unroll
        for (int o = 1; o < 32; o <<= 1) {
            int p = __shfl_up_sync(0xffffffffu, ss, o);
            if (lane >= o) ss += p;
        }
        ws[lane] = ss - u;  // exclusive
    }
    __syncthreads();
    int off = g_bsum[blockIdx.x] + ws[wid] + s - v;
    if (idx < nNodes) {
        g_off[idx] = off;
        g_cur[idx] = off;
        if (idx == nNodes - 1) g_off[nNodes] = off + v;
    }
}

// ---------------------------------------------------------------------------
// Kernel 4: fill CSR
// ---------------------------------------------------------------------------
__global__ void fill_kernel(const void* __restrict__ eiPtr, int E) {
    const bool is64 = (g_is64 != 0);
    const long long* ei64 = (const long long*)eiPtr;
    const int* ei32 = (const int*)eiPtr;
    int tid = blockIdx.x * blockDim.x + threadIdx.x;
    int stride = gridDim.x * blockDim.x;
    for (int e = tid; e < E; e += stride) {
        int dst = is64 ? (int)ei64[(long long)E + e] : ei32[(long long)E + e];
        int p = atomicAdd(&g_cur[dst], 1);
        g_csr[p] = e;
    }
}

// ---------------------------------------------------------------------------
// Kernel 5: fp16 m16n8k16 mma fused edge MLP + segment max.
// 256-thread CTA, warp per node, 16 edges/batch. h stays in registers
// (GEMM1 C-fragments == GEMM2 A-fragments). Cross-edge max kept in 32
// per-lane running maxima; the shfl butterfly runs ONCE per node.
// ---------------------------------------------------------------------------
// smem word (b32) offsets
#define OFF_W1F  0            // 3*32*20  = 1920
#define OFF_W2FA 1920         // 4*32*20  = 2560
#define OFF_W2FB 4480         // 4*32*20  = 2560
#define OFF_B1   7040
#define OFF_G1   7104
#define OFF_BE1  7168
#define OFF_B2   7232
#define OFF_G2   7360
#define OFF_BE2  7488
#define OFF_AB   7616         // 8 warps * 16 rows * 28 words (56 halves)
#define SMEM_FLOATS 11200     // 44800 bytes

__global__ __launch_bounds__(256, 2)
void compute_kernel(const float* __restrict__ x,
                    const float* __restrict__ pos,
                    const float* __restrict__ normal,
                    const float* __restrict__ ea,
                    const void* __restrict__ eiPtr,
                    const float* __restrict__ W1, const float* __restrict__ b1,
                    const float* __restrict__ g1, const float* __restrict__ be1,
                    const float* __restrict__ W2, const float* __restrict__ b2,
                    const float* __restrict__ g2, const float* __restrict__ be2,
                    int E, int nNodes) {
    extern __shared__ float sm[];
    unsigned* smu = (unsigned*)sm;
    int tid = threadIdx.x;

    // ---- W1 fragments (fp16 pairs along k). chunk (ks,lane): 16 words.
    for (int i = tid; i < 3 * 32 * 16; i += 256) {
        int ks = i >> 9, r = i & 511, ln = r >> 4, j = r & 15;
        int gg = ln >> 2, tt = ln & 3;
        int k0 = 16 * ks + 2 * tt + ((j & 8) ? 8 : 0);
        int n = ((j & 7) << 3) + gg;
        float lo = (k0 < 47) ? W1[k0 * 64 + n] : 0.0f;
        float hi = (k0 + 1 < 47) ? W1[(k0 + 1) * 64 + n] : 0.0f;
        smu[OFF_W1F + (ks * 32 + ln) * 20 + j] = h2u(__floats2half2_rn(lo, hi));
    }
    // ---- W2 fragments
    for (int i = tid; i < 4 * 32 * 16; i += 256) {
        int ks = i >> 9, r = i & 511, ln = r >> 4, j = r & 15;
        int gg = ln >> 2, tt = ln & 3;
        int n = (j << 3) + gg;
        int kA = 16 * ks + 2 * tt, kB = kA + 8;
        smu[OFF_W2FA + (ks * 32 + ln) * 20 + j] =
            h2u(__floats2half2_rn(W2[kA * 128 + n], W2[(kA + 1) * 128 + n]));
        smu[OFF_W2FB + (ks * 32 + ln) * 20 + j] =
            h2u(__floats2half2_rn(W2[kB * 128 + n], W2[(kB + 1) * 128 + n]));
    }
    for (int i = tid; i < 64; i += 256) {
        sm[OFF_B1 + i] = b1[i]; sm[OFF_G1 + i] = g1[i]; sm[OFF_BE1 + i] = be1[i];
    }
    for (int i = tid; i < 128; i += 256) {
        sm[OFF_B2 + i] = b2[i]; sm[OFF_G2 + i] = g2[i]; sm[OFF_BE2 + i] = be2[i];
    }
    __syncthreads();

    const int lane = tid & 31;
    const int w = tid >> 5;
    const int g = lane >> 2;
    const int t = lane & 3;
    const int warpGlobal = (blockIdx.x << 3) + w;
    const int warpsTotal = gridDim.x << 3;
    const bool is64 = (g_is64 != 0);
    const long long* ei64 = (const long long*)eiPtr;
    const int* ei32 = (const int*)eiPtr;

    __half* ABh = (__half*)(sm + OFF_AB) + w * (16 * 56);   // [16 rows][56 halves]
    __half2* ABh2 = (__half2*)ABh;                           // [16][28]

    const float NEG_INF = -__int_as_float(0x7f800000);
    const int rowSel = lane >> 4;
    const int cp = lane & 15;

    for (int node = warpGlobal; node < nNodes; node += warpsTotal) {
        int rowStart = g_off[node];
        int deg = g_off[node + 1] - rowStart;

        // per-lane running maxima for all 32 owned features (compile-time idx)
        float mx[32];
        #pragma unroll
        for (int i = 0; i < 32; i++) mx[i] = NEG_INF;

        float pix = pos[node * 3 + 0], piy = pos[node * 3 + 1], piz = pos[node * 3 + 2];
        float nix = normal[node * 3 + 0], niy = normal[node * 3 + 1], niz = normal[node * 3 + 2];

        for (int it = 0; it < deg; it += 16) {
            // ---- stage this batch ----
            int eid = 0, src = 0;
            if (lane < 16) {
                int idx = it + lane;
                int cl = (idx < deg) ? idx : (deg - 1);
                eid = g_csr[rowStart + cl];
                src = is64 ? (int)ei64[eid] : ei32[eid];
            }
            #pragma unroll
            for (int it2 = 0; it2 < 8; it2++) {
                int m = 2 * it2 + rowSel;
                int srcm = __shfl_sync(0xffffffffu, src, m);
                float2 xv = *(const float2*)(x + (size_t)srcm * 32 + 2 * cp);
                ABh2[m * 28 + cp] = __floats2half2_rn(xv.x, xv.y);
            }
            if (lane < 16) {
                const float4* ep = (const float4*)(ea + (size_t)eid * 8);
                float4 e0 = ep[0], e1 = ep[1];
                float pjx = pos[src * 3 + 0], pjy = pos[src * 3 + 1], pjz = pos[src * 3 + 2];
                float px = pjx - pix, py = pjy - piy, pz = pjz - piz;
                float njx = normal[src * 3 + 0], njy = normal[src * 3 + 1], njz = normal[src * 3 + 2];
                float d8 = sqrtf(px * px + py * py + pz * pz) * 0.125f;
                float s1a, c1a, s2a, c2a, s3a, c3a;
                sc_angle(nix, niy, niz, px, py, pz, s1a, c1a);
                sc_angle(njx, njy, njz, px, py, pz, s2a, c2a);
                sc_angle(nix, niy, niz, njx, njy, njz, s3a, c3a);
                __half2* q = ABh2 + lane * 28 + 16;
                q[0] = __floats2half2_rn(d8, s1a);
                q[1] = __floats2half2_rn(c1a, s2a);
                q[2] = __floats2half2_rn(c2a, s3a);
                q[3] = __floats2half2_rn(c3a, e0.x);
                q[4] = __floats2half2_rn(e0.y, e0.z);
                q[5] = __floats2half2_rn(e0.w, e1.x);
                q[6] = __floats2half2_rn(e1.y, e1.z);
                q[7] = __floats2half2_rn(e1.w, 0.0f);
            }
            __syncwarp();

            // ---- GEMM1: [16x48] x [48x64] fp16, 3 k-steps ----
            float c1[8][4];
            #pragma unroll
            for (int nt = 0; nt < 8; nt++) {
                float bl = sm[OFF_B1 + 8 * nt + 2 * t];
                float bh = sm[OFF_B1 + 8 * nt + 2 * t + 1];
                c1[nt][0] = bl; c1[nt][1] = bh; c1[nt][2] = bl; c1[nt][3] = bh;
            }
            #pragma unroll
            for (int ks = 0; ks < 3; ks++) {
                const __half* ar = ABh + 16 * ks + 2 * t;
                unsigned a0 = *(const unsigned*)(ar + g * 56);
                unsigned a1v = *(const unsigned*)(ar + (g + 8) * 56);
                unsigned a2 = *(const unsigned*)(ar + g * 56 + 8);
                unsigned a3 = *(const unsigned*)(ar + (g + 8) * 56 + 8);
                const float4* wp = (const float4*)(sm + OFF_W1F + (ks * 32 + lane) * 20);
                float4 w0 = wp[0], w2v = wp[2];
                mma16(c1[0], a0, a1v, a2, a3, __float_as_uint(w0.x), __float_as_uint(w2v.x));
                mma16(c1[1], a0, a1v, a2, a3, __float_as_uint(w0.y), __float_as_uint(w2v.y));
                mma16(c1[2], a0, a1v, a2, a3, __float_as_uint(w0.z), __float_as_uint(w2v.z));
                mma16(c1[3], a0, a1v, a2, a3, __float_as_uint(w0.w), __float_as_uint(w2v.w));
                float4 w1v = wp[1], w3v = wp[3];
                mma16(c1[4], a0, a1v, a2, a3, __float_as_uint(w1v.x), __float_as_uint(w3v.x));
                mma16(c1[5], a0, a1v, a2, a3, __float_as_uint(w1v.y), __float_as_uint(w3v.y));
                mma16(c1[6], a0, a1v, a2, a3, __float_as_uint(w1v.z), __float_as_uint(w3v.z));
                mma16(c1[7], a0, a1v, a2, a3, __float_as_uint(w1v.w), __float_as_uint(w3v.w));
            }
            // ---- ReLU + LN(64) in fragments ----
            float s0 = 0.0f, q0 = 0.0f, s1 = 0.0f, q1 = 0.0f;
            #pragma unroll
            for (int nt = 0; nt < 8; nt++) {
                float r0 = fmaxf(c1[nt][0], 0.0f), r1 = fmaxf(c1[nt][1], 0.0f);
                float r2 = fmaxf(c1[nt][2], 0.0f), r3 = fmaxf(c1[nt][3], 0.0f);
                c1[nt][0] = r0; c1[nt][1] = r1; c1[nt][2] = r2; c1[nt][3] = r3;
                s0 += r0 + r1; q0 += r0 * r0 + r1 * r1;
                s1 += r2 + r3; q1 += r2 * r2 + r3 * r3;
            }
            s0 += __shfl_xor_sync(0xffffffffu, s0, 1); s0 += __shfl_xor_sync(0xffffffffu, s0, 2);
            q0 += __shfl_xor_sync(0xffffffffu, q0, 1); q0 += __shfl_xor_sync(0xffffffffu, q0, 2);
            s1 += __shfl_xor_sync(0xffffffffu, s1, 1); s1 += __shfl_xor_sync(0xffffffffu, s1, 2);
            q1 += __shfl_xor_sync(0xffffffffu, q1, 1); q1 += __shfl_xor_sync(0xffffffffu, q1, 2);
            float mu0 = s0 * (1.0f / 64.0f);
            float rs0 = rsqrtf(q0 * (1.0f / 64.0f) - mu0 * mu0 + EPS_LN);
            float mu1 = s1 * (1.0f / 64.0f);
            float rs1 = rsqrtf(q1 * (1.0f / 64.0f) - mu1 * mu1 + EPS_LN);
            // pack normalized h directly into GEMM2 A-fragments
            unsigned hw[4][4];
            #pragma unroll
            for (int ks = 0; ks < 4; ks++) {
                int ntA = 2 * ks, ntB = 2 * ks + 1;
                int fA0 = 8 * ntA + 2 * t, fA1 = fA0 + 1;
                int fB0 = 8 * ntB + 2 * t, fB1 = fB0 + 1;
                float gA0 = sm[OFF_G1 + fA0], bA0 = sm[OFF_BE1 + fA0];
                float gA1 = sm[OFF_G1 + fA1], bA1 = sm[OFF_BE1 + fA1];
                float gB0 = sm[OFF_G1 + fB0], bB0 = sm[OFF_BE1 + fB0];
                float gB1 = sm[OFF_G1 + fB1], bB1 = sm[OFF_BE1 + fB1];
                hw[ks][0] = h2u(__floats2half2_rn(
                    (c1[ntA][0] - mu0) * rs0 * gA0 + bA0,
                    (c1[ntA][1] - mu0) * rs0 * gA1 + bA1));
                hw[ks][1] = h2u(__floats2half2_rn(
                    (c1[ntA][2] - mu1) * rs1 * gA0 + bA0,
                    (c1[ntA][3] - mu1) * rs1 * gA1 + bA1));
                hw[ks][2] = h2u(__floats2half2_rn(
                    (c1[ntB][0] - mu0) * rs0 * gB0 + bB0,
                    (c1[ntB][1] - mu0) * rs0 * gB1 + bB1));
                hw[ks][3] = h2u(__floats2half2_rn(
                    (c1[ntB][2] - mu1) * rs1 * gB0 + bB0,
                    (c1[ntB][3] - mu1) * rs1 * gB1 + bB1));
            }

            // ---- GEMM2: [16x64] x [64x128] fp16, A from hw regs ----
            float c2[16][4];
            #pragma unroll
            for (int nt = 0; nt < 16; nt++) {
                float bl = sm[OFF_B2 + 8 * nt + 2 * t];
                float bh = sm[OFF_B2 + 8 * nt + 2 * t + 1];
                c2[nt][0] = bl; c2[nt][1] = bh; c2[nt][2] = bl; c2[nt][3] = bh;
            }
            #pragma unroll
            for (int ks = 0; ks < 4; ks++) {
                unsigned a0 = hw[ks][0], a1v = hw[ks][1];
                unsigned a2 = hw[ks][2], a3 = hw[ks][3];
                const float4* fap = (const float4*)(sm + OFF_W2FA + (ks * 32 + lane) * 20);
                const float4* fbp = (const float4*)(sm + OFF_W2FB + (ks * 32 + lane) * 20);
                #pragma unroll
                for (int qd = 0; qd < 4; qd++) {
                    float4 fa = fap[qd], fb = fbp[qd];
                    mma16(c2[4 * qd + 0], a0, a1v, a2, a3, __float_as_uint(fa.x), __float_as_uint(fb.x));
                    mma16(c2[4 * qd + 1], a0, a1v, a2, a3, __float_as_uint(fa.y), __float_as_uint(fb.y));
                    mma16(c2[4 * qd + 2], a0, a1v, a2, a3, __float_as_uint(fa.z), __float_as_uint(fb.z));
                    mma16(c2[4 * qd + 3], a0, a1v, a2, a3, __float_as_uint(fa.w), __float_as_uint(fb.w));
                }
            }
            // ---- ReLU + LN(128) + per-lane running max (no butterfly) ----
            s0 = 0.0f; q0 = 0.0f; s1 = 0.0f; q1 = 0.0f;
            #pragma unroll
            for (int nt = 0; nt < 16; nt++) {
                float r0 = fmaxf(c2[nt][0], 0.0f), r1 = fmaxf(c2[nt][1], 0.0f);
                float r2 = fmaxf(c2[nt][2], 0.0f), r3 = fmaxf(c2[nt][3], 0.0f);
                c2[nt][0] = r0; c2[nt][1] = r1; c2[nt][2] = r2; c2[nt][3] = r3;
                s0 += r0 + r1; q0 += r0 * r0 + r1 * r1;
                s1 += r2 + r3; q1 += r2 * r2 + r3 * r3;
            }
            s0 += __shfl_xor_sync(0xffffffffu, s0, 1); s0 += __shfl_xor_sync(0xffffffffu, s0, 2);
            q0 += __shfl_xor_sync(0xffffffffu, q0, 1); q0 += __shfl_xor_sync(0xffffffffu, q0, 2);
            s1 += __shfl_xor_sync(0xffffffffu, s1, 1); s1 += __shfl_xor_sync(0xffffffffu, s1, 2);
            q1 += __shfl_xor_sync(0xffffffffu, q1, 1); q1 += __shfl_xor_sync(0xffffffffu, q1, 2);
            mu0 = s0 * (1.0f / 128.0f);
            rs0 = rsqrtf(q0 * (1.0f / 128.0f) - mu0 * mu0 + EPS_LN);
            mu1 = s1 * (1.0f / 128.0f);
            rs1 = rsqrtf(q1 * (1.0f / 128.0f) - mu1 * mu1 + EPS_LN);
            #pragma unroll
            for (int nt = 0; nt < 16; nt++) {
                int f0 = 8 * nt + 2 * t, f1 = f0 + 1;
                float g20 = sm[OFF_G2 + f0], b20 = sm[OFF_BE2 + f0];
                float g21 = sm[OFF_G2 + f1], b21 = sm[OFF_BE2 + f1];
                float v0 = fmaxf((c2[nt][0] - mu0) * rs0 * g20 + b20,
                                 (c2[nt][2] - mu1) * rs1 * g20 + b20);
                float v1 = fmaxf((c2[nt][1] - mu0) * rs0 * g21 + b21,
                                 (c2[nt][3] - mu1) * rs1 * g21 + b21);
                mx[2 * nt]     = fmaxf(mx[2 * nt], v0);
                mx[2 * nt + 1] = fmaxf(mx[2 * nt + 1], v1);
            }
            __syncwarp();   // GEMM1 A-reads done in all lanes before restage
        }

        // ---- once-per-node butterfly across g, then write ----
        #pragma unroll
        for (int i = 0; i < 32; i++) {
            float v = mx[i];
            v = fmaxf(v, __shfl_xor_sync(0xffffffffu, v, 4));
            v = fmaxf(v, __shfl_xor_sync(0xffffffffu, v, 8));
            v = fmaxf(v, __shfl_xor_sync(0xffffffffu, v, 16));
            mx[i] = v;
        }
        #pragma unroll
        for (int nt = 0; nt < 16; nt++) {
            if (g == (nt >> 1)) {
                g_aggf[(size_t)node * 128 + 8 * nt + 2 * t] =
                    (deg > 0) ? mx[2 * nt] : 0.0f;
                g_aggf[(size_t)node * 128 + 8 * nt + 2 * t + 1] =
                    (deg > 0) ? mx[2 * nt + 1] : 0.0f;
            }
        }
    }
}

// ---------------------------------------------------------------------------
// Kernel 6: fp16 mma node MLP 128->256 (ReLU+LN).
// 256-thread CTA, 8 warps, warp per 16 nodes. N split into two 128-halves;
// half-0 raw ReLU'd C stashed to lane-private smem (f32), LN(256) after both.
// ---------------------------------------------------------------------------
#define NOFF_WGFA 0            // 8*32*36 = 9216
#define NOFF_WGFB 9216         // 9216
#define NOFF_BG   18432
#define NOFF_GG   18688
#define NOFF_BEG  18944
#define NOFF_A    19200        // 8 warps * 1088 words ([16 rows][136 halves])
#define NOFF_ST   27904        // 8 warps * 2048 words ([64 slots][32 lanes])
#define NSMEM_FLOATS 44288     // 177152 bytes

__global__ __launch_bounds__(256)
void node_kernel(const float* __restrict__ Wg, const float* __restrict__ bg,
                 const float* __restrict__ gg, const float* __restrict__ beg,
                 float* __restrict__ out, int nNodes) {
    extern __shared__ float sm[];
    unsigned* smu = (unsigned*)sm;
    int tid = threadIdx.x;

    // ---- Wg fragments: ks 0..7, lane, j = nt 0..31 ----
    for (int i = tid; i < 8 * 32 * 32; i += 256) {
        int ks = i >> 10, r = i & 1023, ln = r >> 5, j = r & 31;
        int gg2 = ln >> 2, tt = ln & 3;
        int n = (j << 3) + gg2;
        int kA = 16 * ks + 2 * tt, kB = kA + 8;
        smu[NOFF_WGFA + (ks * 32 + ln) * 36 + j] =
            h2u(__floats2half2_rn(Wg[kA * 256 + n], Wg[(kA + 1) * 256 + n]));
        smu[NOFF_WGFB + (ks * 32 + ln) * 36 + j] =
            h2u(__floats2half2_rn(Wg[kB * 256 + n], Wg[(kB + 1) * 256 + n]));
    }
    for (int i = tid; i < 256; i += 256) {
        sm[NOFF_BG + i] = bg[i]; sm[NOFF_GG + i] = gg[i]; sm[NOFF_BEG + i] = beg[i];
    }
    __syncthreads();

    const int lane = tid & 31;
    const int w = tid >> 5;
    const int g = lane >> 2;
    const int t = lane & 3;
    const int warpGlobal = (blockIdx.x << 3) + w;
    const int warpsTotal = gridDim.x << 3;

    __half* Ah = (__half*)(sm + NOFF_A) + w * 2176;   // [16 rows][136 halves]
    float* st = sm + NOFF_ST + w * 2048;              // [64 slots][32 lanes]

    for (int base = warpGlobal * 16; base < nNodes; base += warpsTotal * 16) {
        // ---- stage A: one agg row (512B) per iteration, fully coalesced ----
        #pragma unroll 4
        for (int rr = 0; rr < 16; rr++) {
            int nd = base + rr;
            if (nd >= nNodes) nd = nNodes - 1;
            float4 v = ((const float4*)(g_aggf + (size_t)nd * 128))[lane];
            *(__half2*)(Ah + rr * 136 + 4 * lane) = __floats2half2_rn(v.x, v.y);
            *(__half2*)(Ah + rr * 136 + 4 * lane + 2) = __floats2half2_rn(v.z, v.w);
        }
        __syncwarp();

        float sum0 = 0.0f, sq0 = 0.0f, sum1 = 0.0f, sq1 = 0.0f;

        // ================= half nh = 0 (features 0..127) =================
        {
            float c[16][4];
            #pragma unroll
            for (int nt = 0; nt < 16; nt++) {
                int f = 8 * nt + 2 * t;
                c[nt][0] = sm[NOFF_BG + f]; c[nt][1] = sm[NOFF_BG + f + 1];
                c[nt][2] = c[nt][0]; c[nt][3] = c[nt][1];
            }
            #pragma unroll
            for (int ks = 0; ks < 8; ks++) {
                const __half* ar = Ah + 16 * ks + 2 * t;
                unsigned a0 = *(const unsigned*)(ar + g * 136);
                unsigned a1v = *(const unsigned*)(ar + (g + 8) * 136);
                unsigned a2 = *(const unsigned*)(ar + g * 136 + 8);
                unsigned a3 = *(const unsigned*)(ar + (g + 8) * 136 + 8);
                const float4* fap = (const float4*)(smu + NOFF_WGFA + (ks * 32 + lane) * 36);
                const float4* fbp = (const float4*)(smu + NOFF_WGFB + (ks * 32 + lane) * 36);
                #pragma unroll
                for (int qd = 0; qd < 4; qd++) {
                    float4 fa = fap[qd], fb = fbp[qd];
                    mma16(c[4 * qd + 0], a0, a1v, a2, a3, __float_as_uint(fa.x), __float_as_uint(fb.x));
                    mma16(c[4 * qd + 1], a0, a1v, a2, a3, __float_as_uint(fa.y), __float_as_uint(fb.y));
                    mma16(c[4 * qd + 2], a0, a1v, a2, a3, __float_as_uint(fa.z), __float_as_uint(fb.z));
                    mma16(c[4 * qd + 3], a0, a1v, a2, a3, __float_as_uint(fa.w), __float_as_uint(fb.w));
                }
            }
            // relu + partial sums + stash raw (lane-private, conflict-free)
            #pragma unroll
            for (int nt = 0; nt < 16; nt++) {
                float r0 = fmaxf(c[nt][0], 0.0f), r1 = fmaxf(c[nt][1], 0.0f);
                float r2 = fmaxf(c[nt][2], 0.0f), r3 = fmaxf(c[nt][3], 0.0f);
                sum0 += r0 + r1; sq0 += r0 * r0 + r1 * r1;
                sum1 += r2 + r3; sq1 += r2 * r2 + r3 * r3;
                st[(nt * 4 + 0) * 32 + lane] = r0;
                st[(nt * 4 + 1) * 32 + lane] = r1;
                st[(nt * 4 + 2) * 32 + lane] = r2;
                st[(nt * 4 + 3) * 32 + lane] = r3;
            }
        }

        // ================= half nh = 1 (features 128..255) =================
        float c[16][4];
        #pragma unroll
        for (int nt = 0; nt < 16; nt++) {
            int f = 128 + 8 * nt + 2 * t;
            c[nt][0] = sm[NOFF_BG + f]; c[nt][1] = sm[NOFF_BG + f + 1];
            c[nt][2] = c[nt][0]; c[nt][3] = c[nt][1];
        }
        #pragma unroll
        for (int ks = 0; ks < 8; ks++) {
            const __half* ar = Ah + 16 * ks + 2 * t;
            unsigned a0 = *(const unsigned*)(ar + g * 136);
            unsigned a1v = *(const unsigned*)(ar + (g + 8) * 136);
            unsigned a2 = *(const unsigned*)(ar + g * 136 + 8);
            unsigned a3 = *(const unsigned*)(ar + (g + 8) * 136 + 8);
            const float4* fap = (const float4*)(smu + NOFF_WGFA + (ks * 32 + lane) * 36 + 16);
            const float4* fbp = (const float4*)(smu + NOFF_WGFB + (ks * 32 + lane) * 36 + 16);
            #pragma unroll
            for (int qd = 0; qd < 4; qd++) {
                float4 fa = fap[qd], fb = fbp[qd];
                mma16(c[4 * qd + 0], a0, a1v, a2, a3, __float_as_uint(fa.x), __float_as_uint(fb.x));
                mma16(c[4 * qd + 1], a0, a1v, a2, a3, __float_as_uint(fa.y), __float_as_uint(fb.y));
                mma16(c[4 * qd + 2], a0, a1v, a2, a3, __float_as_uint(fa.z), __float_as_uint(fb.z));
                mma16(c[4 * qd + 3], a0, a1v, a2, a3, __float_as_uint(fa.w), __float_as_uint(fb.w));
            }
        }
        #pragma unroll
        for (int nt = 0; nt < 16; nt++) {
            float r0 = fmaxf(c[nt][0], 0.0f), r1 = fmaxf(c[nt][1], 0.0f);
            float r2 = fmaxf(c[nt][2], 0.0f), r3 = fmaxf(c[nt][3], 0.0f);
            c[nt][0] = r0; c[nt][1] = r1; c[nt][2] = r2; c[nt][3] = r3;
            sum0 += r0 + r1; sq0 += r0 * r0 + r1 * r1;
            sum1 += r2 + r3; sq1 += r2 * r2 + r3 * r3;
        }

        // ---- LN(256) stats (quad reduction) ----
        sum0 += __shfl_xor_sync(0xffffffffu, sum0, 1); sum0 += __shfl_xor_sync(0xffffffffu, sum0, 2);
        sq0  += __shfl_xor_sync(0xffffffffu, sq0, 1);  sq0  += __shfl_xor_sync(0xffffffffu, sq0, 2);
        sum1 += __shfl_xor_sync(0xffffffffu, sum1, 1); sum1 += __shfl_xor_sync(0xffffffffu, sum1, 2);
        sq1  += __shfl_xor_sync(0xffffffffu, sq1, 1);  sq1  += __shfl_xor_sync(0xffffffffu, sq1, 2);
        float mu0 = sum0 * (1.0f / 256.0f);
        float rs0 = rsqrtf(sq0 * (1.0f / 256.0f) - mu0 * mu0 + EPS_LN);
        float mu1 = sum1 * (1.0f / 256.0f);
        float rs1 = rsqrtf(sq1 * (1.0f / 256.0f) - mu1 * mu1 + EPS_LN);

        int nodeG = base + g, nodeG8 = base + g + 8;
        bool okG = nodeG < nNodes, okG8 = nodeG8 < nNodes;

        // ---- write half 1 (from regs) ----
        #pragma unroll
        for (int nt = 0; nt < 16; nt++) {
            int f = 128 + 8 * nt + 2 * t;
            float ga0 = sm[NOFF_GG + f], ba0 = sm[NOFF_BEG + f];
            float ga1 = sm[NOFF_GG + f + 1], ba1 = sm[NOFF_BEG + f + 1];
            if (okG) {
                float2 o;
                o.x = (c[nt][0] - mu0) * rs0 * ga0 + ba0;
                o.y = (c[nt][1] - mu0) * rs0 * ga1 + ba1;
                *(float2*)(out + (size_t)nodeG * 256 + f) = o;
            }
            if (okG8) {
                float2 o;
                o.x = (c[nt][2] - mu1) * rs1 * ga0 + ba0;
                o.y = (c[nt][3] - mu1) * rs1 * ga1 + ba1;
                *(float2*)(out + (size_t)nodeG8 * 256 + f) = o;
            }
        }
        // ---- write half 0 (from stash) ----
        #pragma unroll
        for (int nt = 0; nt < 16; nt++) {
            int f = 8 * nt + 2 * t;
            float r0 = st[(nt * 4 + 0) * 32 + lane];
            float r1 = st[(nt * 4 + 1) * 32 + lane];
            float r2 = st[(nt * 4 + 2) * 32 + lane];
            float r3 = st[(nt * 4 + 3) * 32 + lane];
            float ga0 = sm[NOFF_GG + f], ba0 = sm[NOFF_BEG + f];
            float ga1 = sm[NOFF_GG + f + 1], ba1 = sm[NOFF_BEG + f + 1];
            if (okG) {
                float2 o;
                o.x = (r0 - mu0) * rs0 * ga0 + ba0;
                o.y = (r1 - mu0) * rs0 * ga1 + ba1;
                *(float2*)(out + (size_t)nodeG * 256 + f) = o;
            }
            if (okG8) {
                float2 o;
                o.x = (r2 - mu1) * rs1 * ga0 + ba0;
                o.y = (r3 - mu1) * rs1 * ga1 + ba1;
                *(float2*)(out + (size_t)nodeG8 * 256 + f) = o;
            }
        }
        __syncwarp();   // A reads done before next restage
    }
}

// ---------------------------------------------------------------------------
extern "C" void kernel_launch(void* const* d_in, const int* in_sizes, int n_in,
                              void* d_out, int out_size) {
    const float* x      = (const float*)d_in[0];
    const float* pos    = (const float*)d_in[1];
    const float* normal = (const float*)d_in[2];
    const float* ea     = (const float*)d_in[3];
    const void*  ei     = d_in[4];
    const float* W1  = (const float*)d_in[5];
    const float* b1  = (const float*)d_in[6];
    const float* g1  = (const float*)d_in[7];
    const float* be1 = (const float*)d_in[8];
    const float* W2  = (const float*)d_in[9];
    const float* b2  = (const float*)d_in[10];
    const float* g2  = (const float*)d_in[11];
    const float* be2 = (const float*)d_in[12];
    const float* Wg  = (const float*)d_in[13];
    const float* bg  = (const float*)d_in[14];
    const float* gg  = (const float*)d_in[15];
    const float* beg = (const float*)d_in[16];
    float* out = (float*)d_out;

    int E = in_sizes[4] / 2;
    int N = in_sizes[1] / 3;
    int nb = (N + 1023) / 1024;

    static const size_t cmpSmem = SMEM_FLOATS * sizeof(float);    // 44800 B
    static const size_t nodeSmem = NSMEM_FLOATS * sizeof(float);  // 177152 B
    cudaFuncSetAttribute(compute_kernel, cudaFuncAttributeMaxDynamicSharedMemorySize,
                         (int)cmpSmem);
    cudaFuncSetAttribute(node_kernel, cudaFuncAttributeMaxDynamicSharedMemorySize,
                         (int)nodeSmem);

    init_kernel<<<64, 256>>>((const int*)ei, N);
    hist_kernel<<<512, 256>>>(ei, E);
    scanA_kernel<<<nb, 1024>>>(N);
    scanB_kernel<<<1, 64>>>(nb);
    scanC_kernel<<<nb, 1024>>>(N);
    fill_kernel<<<512, 256>>>(ei, E);
    compute_kernel<<<296, 256, cmpSmem>>>(x, pos, normal, ea, ei,
                                          W1, b1, g1, be1, W2, b2, g2, be2, E, N);
    node_kernel<<<148, 256, nodeSmem>>>(Wg, bg, gg, beg, out, N);
}